// round 1
// baseline (speedup 1.0000x reference)
#include <cuda_runtime.h>
#include <math.h>

#define S_LEN 2048
#define B_SZ  2
#define NTOK  4096
#define H_NUM 8
#define HDIM  64
#define NEGBIG -1e9f

// ---------------- scratch (device globals; no allocation) ----------------
__device__ float g_qkv  [NTOK*1536];
__device__ float g_attnL[NTOK*512];
__device__ float g_qc   [NTOK*512];
__device__ float g_attnC[NTOK*512];
__device__ float g_qt   [NTOK*512];
__device__ float g_attnT[NTOK*512];
__device__ float g_gatec[NTOK*512];
__device__ float g_gatet[NTOK*512];
__device__ float g_comp [384*512];
__device__ float g_kc   [384*512];
__device__ float g_vc   [384*512];
__device__ float g_sel  [128*512];
__device__ float g_kt   [128*512];
__device__ float g_vt   [128*512];
__device__ float g_imp  [NTOK];
__device__ int   g_tidx [128];

// ---------------- SGEMM: C(N,M) = A(N,K) @ B(K,M) + bias, epilogues ------
// EPI 0: store. EPI 1: sigmoid-store. EPI 2: C += gate * (acc + bias)
// Requires N % 128 == 0, M % 128 == 0, K % 8 == 0 (all shapes here comply).
template<int EPI>
__global__ __launch_bounds__(256) void sgemm128(
    const float* __restrict__ A, const float* __restrict__ B,
    const float* __restrict__ bias, float* __restrict__ C,
    const float* __restrict__ gate, int N, int M, int K)
{
    __shared__ float As[8][128];
    __shared__ float Bs[8][128];
    const int tid = threadIdx.x;
    const int row0 = blockIdx.y * 128, col0 = blockIdx.x * 128;
    const int arow = tid >> 1, acol = (tid & 1) * 4;
    const int brow = tid >> 5, bcol = (tid & 31) * 4;
    const int ty = tid >> 4, tx = tid & 15;

    float acc[8][8];
#pragma unroll
    for (int i = 0; i < 8; i++)
#pragma unroll
        for (int j = 0; j < 8; j++) acc[i][j] = 0.f;

    for (int k0 = 0; k0 < K; k0 += 8) {
        float4 av = *(const float4*)(A + (size_t)(row0 + arow) * K + k0 + acol);
        float4 bv = *(const float4*)(B + (size_t)(k0 + brow) * M + col0 + bcol);
        As[acol + 0][arow] = av.x;
        As[acol + 1][arow] = av.y;
        As[acol + 2][arow] = av.z;
        As[acol + 3][arow] = av.w;
        *(float4*)(&Bs[brow][bcol]) = bv;
        __syncthreads();
#pragma unroll
        for (int kk = 0; kk < 8; kk++) {
            float a[8], b[8];
#pragma unroll
            for (int i = 0; i < 8; i++) a[i] = As[kk][ty * 8 + i];
#pragma unroll
            for (int j = 0; j < 8; j++) b[j] = Bs[kk][tx * 8 + j];
#pragma unroll
            for (int i = 0; i < 8; i++)
#pragma unroll
                for (int j = 0; j < 8; j++) acc[i][j] += a[i] * b[j];
        }
        __syncthreads();
    }

#pragma unroll
    for (int i = 0; i < 8; i++) {
        int r = row0 + ty * 8 + i;
#pragma unroll
        for (int j = 0; j < 8; j++) {
            int c = col0 + tx * 8 + j;
            float v = acc[i][j] + bias[c];
            size_t off = (size_t)r * M + c;
            if (EPI == 0)      C[off] = v;
            else if (EPI == 1) C[off] = 1.f / (1.f + expf(-v));
            else               C[off] += gate[off] * v;
        }
    }
}

// ---------------- generic flash attention (64q x 64k tiles) --------------
// mode 0: local window (0 <= q-k < 512), keys = qkv buffer
// mode 1: compressed   (q >= (k+1)*8)
// mode 2: topk         (q >= tidx[b*64+k])
// Fully-masked rows yield uniform softmax (scores all -1e9), matching ref.
__global__ __launch_bounds__(256) void attn_kernel(
    const float* __restrict__ Qb, int q_stride,
    const float* __restrict__ Kb, int k_stride,
    const float* __restrict__ Vb, int v_stride,
    float* __restrict__ O,
    const int* __restrict__ tidx,
    int n_keys, int mode)
{
    extern __shared__ float sm[];
    float* Qs  = sm;                 // [64][65]
    float* KVs = sm + 64 * 65;       // [64][65]  (K then reused for V)
    float* Ss  = sm + 2 * 64 * 65;   // [64][65]  (probabilities)
    int*   pos = (int*)(sm + 3 * 64 * 65);  // [64]

    const int b = blockIdx.z, h = blockIdx.y, q0 = blockIdx.x * 64;
    const int tid = threadIdx.x;

    for (int idx = tid; idx < 64 * 64; idx += 256) {
        int i = idx >> 6, d = idx & 63;
        Qs[i * 65 + d] = Qb[(size_t)(b * S_LEN + q0 + i) * q_stride + h * HDIM + d] * 0.125f;
    }

    const int i_r = tid >> 2, jseg = tid & 3;
    const int q = q0 + i_r;
    float o[16];
#pragma unroll
    for (int c = 0; c < 16; c++) o[c] = 0.f;
    float m = -INFINITY, l = 0.f;

    int kt0 = 0, ktend = n_keys;
    if (mode == 0) { kt0 = (q0 > 511) ? ((q0 - 511) & ~63) : 0; ktend = q0 + 64; }

    for (int kt = kt0; kt < ktend; kt += 64) {
        __syncthreads();
        for (int idx = tid; idx < 64 * 64; idx += 256) {
            int j = idx >> 6, d = idx & 63;
            KVs[j * 65 + d] = Kb[(size_t)(b * n_keys + kt + j) * k_stride + h * HDIM + d];
        }
        if (tid < 64) {
            int j = kt + tid;
            pos[tid] = (mode == 0) ? j : (mode == 1 ? (j + 1) * 8 : tidx[b * 64 + j]);
        }
        __syncthreads();

        float s[16];
#pragma unroll
        for (int jj = 0; jj < 16; jj++) s[jj] = 0.f;
        for (int d = 0; d < 64; d++) {
            float qd = Qs[i_r * 65 + d];
#pragma unroll
            for (int jj = 0; jj < 16; jj++)
                s[jj] += qd * KVs[(jseg * 16 + jj) * 65 + d];
        }

        float mt = -INFINITY;
#pragma unroll
        for (int jj = 0; jj < 16; jj++) {
            int p = pos[jseg * 16 + jj];
            bool vis = (mode == 0) ? ((unsigned)(q - p) < 512u) : (q >= p);
            if (!vis) s[jj] = NEGBIG;
            mt = fmaxf(mt, s[jj]);
        }
        mt = fmaxf(mt, __shfl_xor_sync(0xffffffffu, mt, 1));
        mt = fmaxf(mt, __shfl_xor_sync(0xffffffffu, mt, 2));
        float m_new = fmaxf(m, mt);

        float lt = 0.f;
#pragma unroll
        for (int jj = 0; jj < 16; jj++) {
            float p = expf(s[jj] - m_new);
            lt += p;
            Ss[i_r * 65 + jseg * 16 + jj] = p;
        }
        lt += __shfl_xor_sync(0xffffffffu, lt, 1);
        lt += __shfl_xor_sync(0xffffffffu, lt, 2);
        float alpha = expf(m - m_new);
        l = l * alpha + lt;
        m = m_new;
#pragma unroll
        for (int c = 0; c < 16; c++) o[c] *= alpha;
        __syncthreads();

        for (int idx = tid; idx < 64 * 64; idx += 256) {
            int j = idx >> 6, d = idx & 63;
            KVs[j * 65 + d] = Vb[(size_t)(b * n_keys + kt + j) * v_stride + h * HDIM + d];
        }
        __syncthreads();

        for (int j = 0; j < 64; j++) {
            float p = Ss[i_r * 65 + j];
#pragma unroll
            for (int c = 0; c < 16; c++)
                o[c] += p * KVs[j * 65 + jseg * 16 + c];
        }
    }

    float inv = 1.f / l;
#pragma unroll
    for (int c = 0; c < 16; c++)
        O[(size_t)(b * S_LEN + q0 + i_r) * 512 + h * HDIM + jseg * 16 + c] = o[c] * inv;
}

// ---------------- small kernels -------------------------------------------
__global__ void pool_kernel(const float* __restrict__ x, float* __restrict__ comp)
{
    int p = blockIdx.x % 192, b = blockIdx.x / 192;
    int d = threadIdx.x; // 512 threads
    float s = 0.f;
#pragma unroll
    for (int r = 0; r < 8; r++)
        s += x[(size_t)(b * S_LEN + p * 8 + r) * 512 + d];
    comp[(size_t)(b * 192 + p) * 512 + d] = s * 0.125f;
}

__global__ void imp_kernel(const float* __restrict__ x, const float* __restrict__ W,
                           const float* __restrict__ bias, float* __restrict__ imp)
{
    int t = blockIdx.x * 8 + (threadIdx.x >> 5);
    int lane = threadIdx.x & 31;
    float s = 0.f;
    for (int i = lane; i < 512; i += 32)
        s += x[(size_t)t * 512 + i] * W[i];
#pragma unroll
    for (int off = 16; off; off >>= 1)
        s += __shfl_xor_sync(0xffffffffu, s, off);
    if (!lane) imp[t] = s + bias[0];
}

__global__ void topk_kernel(const float* __restrict__ imp, int* __restrict__ tidx)
{
    int b = blockIdx.x;
    __shared__ float v[2048];
    __shared__ float bestv[256];
    __shared__ int   besti[256];
    int tid = threadIdx.x;
    for (int i = tid; i < 2048; i += 256) v[i] = imp[b * 2048 + i];
    __syncthreads();
    for (int r = 0; r < 64; r++) {
        float bv = -INFINITY; int bi = 0x7fffffff;
        for (int i = tid; i < 2048; i += 256) {
            float xv = v[i];
            if (xv > bv) { bv = xv; bi = i; }
        }
        bestv[tid] = bv; besti[tid] = bi;
        __syncthreads();
        for (int s2 = 128; s2 > 0; s2 >>= 1) {
            if (tid < s2) {
                float xo = bestv[tid + s2]; int io = besti[tid + s2];
                if (xo > bestv[tid] || (xo == bestv[tid] && io < besti[tid])) {
                    bestv[tid] = xo; besti[tid] = io;
                }
            }
            __syncthreads();
        }
        if (tid == 0) { tidx[b * 64 + r] = besti[0]; v[besti[0]] = -INFINITY; }
        __syncthreads();
    }
}

__global__ void gather_kernel(const float* __restrict__ x, const int* __restrict__ tidx,
                              float* __restrict__ sel)
{
    int row = blockIdx.x;         // 0..127
    int b = row >> 6;
    int src = tidx[row];
    for (int d = threadIdx.x; d < 512; d += 256)
        sel[(size_t)row * 512 + d] = x[(size_t)(b * S_LEN + src) * 512 + d];
}

// ---------------- launch ---------------------------------------------------
extern "C" void kernel_launch(void* const* d_in, const int* in_sizes, int n_in,
                              void* d_out, int out_size)
{
    const float* x    = (const float*)d_in[0];
    const float* Wqkv = (const float*)d_in[1];  const float* bqkv = (const float*)d_in[2];
    const float* Wlo  = (const float*)d_in[3];  const float* blo  = (const float*)d_in[4];
    const float* Wcq  = (const float*)d_in[5];  const float* bcq  = (const float*)d_in[6];
    const float* Wck  = (const float*)d_in[7];  const float* bck  = (const float*)d_in[8];
    const float* Wcv  = (const float*)d_in[9];  const float* bcv  = (const float*)d_in[10];
    const float* Wco  = (const float*)d_in[11]; const float* bco  = (const float*)d_in[12];
    const float* Wgc  = (const float*)d_in[13]; const float* bgc  = (const float*)d_in[14];
    const float* Wimp = (const float*)d_in[15]; const float* bimp = (const float*)d_in[16];
    const float* Wtq  = (const float*)d_in[17]; const float* btq  = (const float*)d_in[18];
    const float* Wtk  = (const float*)d_in[19]; const float* btk  = (const float*)d_in[20];
    const float* Wtv  = (const float*)d_in[21]; const float* btv  = (const float*)d_in[22];
    const float* Wto  = (const float*)d_in[23]; const float* bto  = (const float*)d_in[24];
    const float* Wgt  = (const float*)d_in[25]; const float* bgt  = (const float*)d_in[26];
    float* out = (float*)d_out;

    float *qkv, *attnL, *qc, *attnC, *qt, *attnT, *gatec, *gatet;
    float *comp, *kc, *vc, *sel, *kt, *vt, *imp;
    int* tidx;
    cudaGetSymbolAddress((void**)&qkv,   g_qkv);
    cudaGetSymbolAddress((void**)&attnL, g_attnL);
    cudaGetSymbolAddress((void**)&qc,    g_qc);
    cudaGetSymbolAddress((void**)&attnC, g_attnC);
    cudaGetSymbolAddress((void**)&qt,    g_qt);
    cudaGetSymbolAddress((void**)&attnT, g_attnT);
    cudaGetSymbolAddress((void**)&gatec, g_gatec);
    cudaGetSymbolAddress((void**)&gatet, g_gatet);
    cudaGetSymbolAddress((void**)&comp,  g_comp);
    cudaGetSymbolAddress((void**)&kc,    g_kc);
    cudaGetSymbolAddress((void**)&vc,    g_vc);
    cudaGetSymbolAddress((void**)&sel,   g_sel);
    cudaGetSymbolAddress((void**)&kt,    g_kt);
    cudaGetSymbolAddress((void**)&vt,    g_vt);
    cudaGetSymbolAddress((void**)&imp,   g_imp);
    cudaGetSymbolAddress((void**)&tidx,  g_tidx);

    const int ATTN_SMEM = (3 * 64 * 65 + 64) * 4; // 50176 bytes
    cudaFuncSetAttribute(attn_kernel, cudaFuncAttributeMaxDynamicSharedMemorySize, ATTN_SMEM);

    // 1) big projections from x
    sgemm128<0><<<dim3(12, 32), 256>>>(x, Wqkv, bqkv, qkv,  nullptr, NTOK, 1536, 512);
    sgemm128<0><<<dim3(4, 32),  256>>>(x, Wcq,  bcq,  qc,   nullptr, NTOK, 512,  512);
    sgemm128<1><<<dim3(4, 32),  256>>>(x, Wgc,  bgc,  gatec,nullptr, NTOK, 512,  512);
    sgemm128<0><<<dim3(4, 32),  256>>>(x, Wtq,  btq,  qt,   nullptr, NTOK, 512,  512);
    sgemm128<1><<<dim3(4, 32),  256>>>(x, Wgt,  bgt,  gatet,nullptr, NTOK, 512,  512);

    // 2) compressed branch inputs
    pool_kernel<<<384, 512>>>(x, comp);
    sgemm128<0><<<dim3(4, 3), 256>>>(comp, Wck, bck, kc, nullptr, 384, 512, 512);
    sgemm128<0><<<dim3(4, 3), 256>>>(comp, Wcv, bcv, vc, nullptr, 384, 512, 512);

    // 3) top-k branch inputs
    imp_kernel<<<512, 256>>>(x, Wimp, bimp, imp);
    topk_kernel<<<2, 256>>>(imp, tidx);
    gather_kernel<<<128, 256>>>(x, tidx, sel);
    sgemm128<0><<<dim3(4, 1), 256>>>(sel, Wtk, btk, kt, nullptr, 128, 512, 512);
    sgemm128<0><<<dim3(4, 1), 256>>>(sel, Wtv, btv, vt, nullptr, 128, 512, 512);

    // 4) attentions
    attn_kernel<<<dim3(32, 8, 2), 256, ATTN_SMEM>>>(
        qkv, 1536, qkv + 512, 1536, qkv + 1024, 1536, attnL, nullptr, 2048, 0);
    attn_kernel<<<dim3(32, 8, 2), 256, ATTN_SMEM>>>(
        qc, 512, kc, 512, vc, 512, attnC, nullptr, 192, 1);
    attn_kernel<<<dim3(32, 8, 2), 256, ATTN_SMEM>>>(
        qt, 512, kt, 512, vt, 512, attnT, tidx, 64, 2);

    // 5) output projections (gated ones accumulate into d_out)
    sgemm128<0><<<dim3(4, 32), 256>>>(attnL, Wlo, blo, out, nullptr, NTOK, 512, 512);
    sgemm128<2><<<dim3(4, 32), 256>>>(attnC, Wco, bco, out, gatec,  NTOK, 512, 512);
    sgemm128<2><<<dim3(4, 32), 256>>>(attnT, Wto, bto, out, gatet,  NTOK, 512, 512);
}

// round 2
// speedup vs baseline: 1.9049x; 1.9049x over previous
#include <cuda_runtime.h>
#include <math.h>

#define S_LEN 2048
#define NTOK  4096
#define HDIM  64
#define NEGBIG -1e9f

// ---------------- f32x2 helpers (sm_103a packed fp32) ----------------------
__device__ __forceinline__ unsigned long long f32dup(float x) {
    unsigned long long r;
    asm("mov.b64 %0, {%1, %1};" : "=l"(r) : "f"(x));
    return r;
}
__device__ __forceinline__ unsigned long long fma2(unsigned long long a,
                                                   unsigned long long b,
                                                   unsigned long long c) {
    unsigned long long d;
    asm("fma.rn.f32x2 %0, %1, %2, %3;" : "=l"(d) : "l"(a), "l"(b), "l"(c));
    return d;
}
__device__ __forceinline__ unsigned long long mul2(unsigned long long a,
                                                   unsigned long long b) {
    unsigned long long d;
    asm("mul.rn.f32x2 %0, %1, %2;" : "=l"(d) : "l"(a), "l"(b));
    return d;
}
__device__ __forceinline__ float2 unpack2(unsigned long long v) {
    float2 r;
    asm("mov.b64 {%0, %1}, %2;" : "=f"(r.x), "=f"(r.y) : "l"(v));
    return r;
}

// ---------------- scratch (device globals; no allocation) ------------------
__device__ float g_qkv  [NTOK*1536];   // also reused as 3 output-GEMM buffers
__device__ float g_attnL[NTOK*512];
__device__ float g_qc   [NTOK*512];
__device__ float g_attnC[NTOK*512];
__device__ float g_qt   [NTOK*512];
__device__ float g_attnT[NTOK*512];
__device__ float g_gatec[NTOK*512];
__device__ float g_gatet[NTOK*512];
__device__ float g_comp [384*512];
__device__ float g_kc   [384*512];
__device__ float g_vc   [384*512];
__device__ float g_sel  [128*512];
__device__ float g_kt   [128*512];
__device__ float g_vt   [128*512];
__device__ float g_imp  [NTOK];
__device__ int   g_tidx [128];

// ---------------- batched SGEMM: C = A @ B + bias, per-segment epilogue ----
// epi 0: store   epi 1: sigmoid-store
struct Seg {
    const float* A; const float* B; const float* bias; float* C;
    int M; int tiles; int epi;
};
struct Batch { Seg s[5]; int n; };

__global__ __launch_bounds__(256) void sgemm_b(Batch bt, int K)
{
    __shared__ float As[8][128];
    __shared__ float Bs[8][128];

    int ct = blockIdx.x, si = 0;
    while (si < bt.n - 1 && ct >= bt.s[si].tiles) { ct -= bt.s[si].tiles; si++; }
    const float* A   = bt.s[si].A;
    const float* B   = bt.s[si].B;
    const float* bias= bt.s[si].bias;
    float*       C   = bt.s[si].C;
    const int    M   = bt.s[si].M;
    const int    epi = bt.s[si].epi;

    const int tid = threadIdx.x;
    const int row0 = blockIdx.y * 128, col0 = ct * 128;
    const int arow = tid >> 1, acol = (tid & 1) * 4;
    const int brow = tid >> 5, bcol = (tid & 31) * 4;
    const int ty = tid >> 4, tx = tid & 15;

    unsigned long long acc[8][4];
#pragma unroll
    for (int i = 0; i < 8; i++)
#pragma unroll
        for (int j = 0; j < 4; j++) acc[i][j] = 0ull;

    float4 av = *(const float4*)(A + (size_t)(row0 + arow) * K + acol);
    float4 bv = *(const float4*)(B + (size_t)brow * M + col0 + bcol);

    for (int k0 = 0; k0 < K; k0 += 8) {
        As[acol + 0][arow] = av.x;
        As[acol + 1][arow] = av.y;
        As[acol + 2][arow] = av.z;
        As[acol + 3][arow] = av.w;
        *(float4*)(&Bs[brow][bcol]) = bv;
        __syncthreads();
        if (k0 + 8 < K) {
            av = *(const float4*)(A + (size_t)(row0 + arow) * K + k0 + 8 + acol);
            bv = *(const float4*)(B + (size_t)(k0 + 8 + brow) * M + col0 + bcol);
        }
#pragma unroll
        for (int kk = 0; kk < 8; kk++) {
            float4 alo = *(const float4*)(&As[kk][ty * 8]);
            float4 ahi = *(const float4*)(&As[kk][ty * 8 + 4]);
            ulonglong2 b01 = *(const ulonglong2*)(&Bs[kk][tx * 8]);
            ulonglong2 b23 = *(const ulonglong2*)(&Bs[kk][tx * 8 + 4]);
            float a[8] = {alo.x, alo.y, alo.z, alo.w, ahi.x, ahi.y, ahi.z, ahi.w};
#pragma unroll
            for (int i = 0; i < 8; i++) {
                unsigned long long ad = f32dup(a[i]);
                acc[i][0] = fma2(ad, b01.x, acc[i][0]);
                acc[i][1] = fma2(ad, b01.y, acc[i][1]);
                acc[i][2] = fma2(ad, b23.x, acc[i][2]);
                acc[i][3] = fma2(ad, b23.y, acc[i][3]);
            }
        }
        __syncthreads();
    }

#pragma unroll
    for (int i = 0; i < 8; i++) {
        int r = row0 + ty * 8 + i;
        int c = col0 + tx * 8;
        float v[8];
#pragma unroll
        for (int j = 0; j < 4; j++) {
            float2 t = unpack2(acc[i][j]);
            v[2 * j] = t.x + bias[c + 2 * j];
            v[2 * j + 1] = t.y + bias[c + 2 * j + 1];
        }
        if (epi == 1) {
#pragma unroll
            for (int j = 0; j < 8; j++) v[j] = 1.f / (1.f + expf(-v[j]));
        }
        float4* dst = (float4*)(C + (size_t)r * M + c);
        dst[0] = make_float4(v[0], v[1], v[2], v[3]);
        dst[1] = make_float4(v[4], v[5], v[6], v[7]);
    }
}

// ---------------- batched flash attention (64q x 64k tiles) ----------------
// mode 0: local window (0 <= q-k < 512)   mode 1: compressed (q >= (k+1)*8)
// mode 2: topk (q >= tidx[k]).  Fully-masked rows -> uniform softmax (matches ref).
struct AttnParams {
    const float* Q[3]; const float* K[3]; const float* V[3]; float* O[3];
    int qs[3], ks[3], nk[3];
    const int* tidx;
};

__global__ __launch_bounds__(256) void attn_b(AttnParams P)
{
    extern __shared__ float sm[];
    float* Qs = sm;                   // [64][68]
    float* Ks = Qs + 64 * 68;         // [64][72]
    float* Vs = Ks + 64 * 72;         // [64][72]
    float* Ss = Vs + 64 * 72;         // [64][65]
    int*  pos = (int*)(Ss + 64 * 65); // [64]

    const int mode = blockIdx.z >> 1, b = blockIdx.z & 1;
    const int h = blockIdx.y, q0 = blockIdx.x * 64;
    const int tid = threadIdx.x;

    const float* Qb = P.Q[mode]; const float* Kb = P.K[mode]; const float* Vb = P.V[mode];
    float* O = P.O[mode];
    const int qs = P.qs[mode], ks = P.ks[mode], nk = P.nk[mode];

    for (int idx = tid; idx < 64 * 16; idx += 256) {
        int r = idx >> 4, d0 = (idx & 15) << 2;
        float4 q = *(const float4*)(Qb + (size_t)(b * S_LEN + q0 + r) * qs + h * HDIM + d0);
        q.x *= 0.125f; q.y *= 0.125f; q.z *= 0.125f; q.w *= 0.125f;
        *(float4*)(&Qs[r * 68 + d0]) = q;
    }

    const int i_r = tid >> 2, jseg = tid & 3;
    const int q = q0 + i_r;
    unsigned long long o2[8];
#pragma unroll
    for (int c = 0; c < 8; c++) o2[c] = 0ull;
    float m = -INFINITY, l = 0.f;

    int kt0 = 0, ktend = nk;
    if (mode == 0) { kt0 = (q0 > 511) ? ((q0 - 511) & ~63) : 0; ktend = q0 + 64; }

    for (int kt = kt0; kt < ktend; kt += 64) {
        __syncthreads();
        for (int idx = tid; idx < 64 * 16; idx += 256) {
            int r = idx >> 4, d0 = (idx & 15) << 2;
            size_t gb = (size_t)(b * nk + kt + r);
            *(float4*)(&Ks[r * 72 + d0]) = *(const float4*)(Kb + gb * ks + h * HDIM + d0);
            *(float4*)(&Vs[r * 72 + d0]) = *(const float4*)(Vb + gb * ks + h * HDIM + d0);
        }
        if (tid < 64) {
            int j = kt + tid;
            pos[tid] = (mode == 0) ? j : (mode == 1 ? (j + 1) * 8 : P.tidx[b * 64 + j]);
        }
        __syncthreads();

        // ---- QK^T : s[jj] for keys j_local = 4*jj + jseg ----
        unsigned long long s2[16];
#pragma unroll
        for (int jj = 0; jj < 16; jj++) s2[jj] = 0ull;
        for (int d0 = 0; d0 < 64; d0 += 4) {
            ulonglong2 qq = *(const ulonglong2*)(&Qs[i_r * 68 + d0]);
#pragma unroll
            for (int jj = 0; jj < 16; jj++) {
                ulonglong2 kk2 = *(const ulonglong2*)(&Ks[(4 * jj + jseg) * 72 + d0]);
                s2[jj] = fma2(qq.x, kk2.x, s2[jj]);
                s2[jj] = fma2(qq.y, kk2.y, s2[jj]);
            }
        }

        float s[16], mt = -INFINITY;
#pragma unroll
        for (int jj = 0; jj < 16; jj++) {
            float2 t = unpack2(s2[jj]);
            float sv = t.x + t.y;
            int p = pos[4 * jj + jseg];
            bool vis = (mode == 0) ? ((unsigned)(q - p) < 512u) : (q >= p);
            if (!vis) sv = NEGBIG;
            s[jj] = sv;
            mt = fmaxf(mt, sv);
        }
        mt = fmaxf(mt, __shfl_xor_sync(0xffffffffu, mt, 1));
        mt = fmaxf(mt, __shfl_xor_sync(0xffffffffu, mt, 2));
        float m_new = fmaxf(m, mt);

        float lt = 0.f;
#pragma unroll
        for (int jj = 0; jj < 16; jj++) {
            float p = expf(s[jj] - m_new);
            lt += p;
            Ss[i_r * 65 + 4 * jj + jseg] = p;
        }
        lt += __shfl_xor_sync(0xffffffffu, lt, 1);
        lt += __shfl_xor_sync(0xffffffffu, lt, 2);
        float alpha = expf(m - m_new);
        l = l * alpha + lt;
        m = m_new;
        unsigned long long a2 = f32dup(alpha);
#pragma unroll
        for (int c = 0; c < 8; c++) o2[c] = mul2(o2[c], a2);
        __syncwarp();

        // ---- P @ V : o covers d = jseg*16 .. jseg*16+15 ----
        for (int j = 0; j < 64; j++) {
            unsigned long long p2 = f32dup(Ss[i_r * 65 + j]);
            ulonglong2 v01 = *(const ulonglong2*)(&Vs[j * 72 + jseg * 16]);
            ulonglong2 v23 = *(const ulonglong2*)(&Vs[j * 72 + jseg * 16 + 8]);
            o2[0] = fma2(p2, v01.x, o2[0]);
            o2[1] = fma2(p2, v01.y, o2[1]);
            o2[2] = fma2(p2, v23.x, o2[2]);
            o2[3] = fma2(p2, v23.y, o2[3]);
            ulonglong2 v45 = *(const ulonglong2*)(&Vs[j * 72 + jseg * 16 + 4]);
            ulonglong2 v67 = *(const ulonglong2*)(&Vs[j * 72 + jseg * 16 + 12]);
            o2[4] = fma2(p2, v45.x, o2[4]);
            o2[5] = fma2(p2, v45.y, o2[5]);
            o2[6] = fma2(p2, v67.x, o2[6]);
            o2[7] = fma2(p2, v67.y, o2[7]);
        }
    }

    float inv = 1.f / l;
    float* dst = O + (size_t)(b * S_LEN + q0 + i_r) * 512 + h * HDIM + jseg * 16;
    float2 t0 = unpack2(o2[0]), t1 = unpack2(o2[1]), t4 = unpack2(o2[4]), t5 = unpack2(o2[5]);
    float2 t2 = unpack2(o2[2]), t3 = unpack2(o2[3]), t6 = unpack2(o2[6]), t7 = unpack2(o2[7]);
    ((float4*)dst)[0] = make_float4(t0.x * inv, t0.y * inv, t1.x * inv, t1.y * inv);
    ((float4*)dst)[1] = make_float4(t4.x * inv, t4.y * inv, t5.x * inv, t5.y * inv);
    ((float4*)dst)[2] = make_float4(t2.x * inv, t2.y * inv, t3.x * inv, t3.y * inv);
    ((float4*)dst)[3] = make_float4(t6.x * inv, t6.y * inv, t7.x * inv, t7.y * inv);
}

// ---------------- small kernels ---------------------------------------------
__global__ void pool_kernel(const float* __restrict__ x, float* __restrict__ comp)
{
    int p = blockIdx.x % 192, b = blockIdx.x / 192;
    int d = threadIdx.x;
    float s = 0.f;
#pragma unroll
    for (int r = 0; r < 8; r++)
        s += x[(size_t)(b * S_LEN + p * 8 + r) * 512 + d];
    comp[(size_t)(b * 192 + p) * 512 + d] = s * 0.125f;
}

__global__ void imp_kernel(const float* __restrict__ x, const float* __restrict__ W,
                           const float* __restrict__ bias, float* __restrict__ imp)
{
    int t = blockIdx.x * 8 + (threadIdx.x >> 5);
    int lane = threadIdx.x & 31;
    float s = 0.f;
    for (int i = lane; i < 512; i += 32)
        s += x[(size_t)t * 512 + i] * W[i];
#pragma unroll
    for (int off = 16; off; off >>= 1)
        s += __shfl_xor_sync(0xffffffffu, s, off);
    if (!lane) imp[t] = s + bias[0];
}

__global__ void topk_kernel(const float* __restrict__ imp, int* __restrict__ tidx)
{
    int b = blockIdx.x;
    __shared__ float v[2048];
    __shared__ float bestv[256];
    __shared__ int   besti[256];
    int tid = threadIdx.x;
    for (int i = tid; i < 2048; i += 256) v[i] = imp[b * 2048 + i];
    __syncthreads();
    for (int r = 0; r < 64; r++) {
        float bv = -INFINITY; int bi = 0x7fffffff;
        for (int i = tid; i < 2048; i += 256) {
            float xv = v[i];
            if (xv > bv) { bv = xv; bi = i; }
        }
        bestv[tid] = bv; besti[tid] = bi;
        __syncthreads();
        for (int s2 = 128; s2 > 0; s2 >>= 1) {
            if (tid < s2) {
                float xo = bestv[tid + s2]; int io = besti[tid + s2];
                if (xo > bestv[tid] || (xo == bestv[tid] && io < besti[tid])) {
                    bestv[tid] = xo; besti[tid] = io;
                }
            }
            __syncthreads();
        }
        if (tid == 0) { tidx[b * 64 + r] = besti[0]; v[besti[0]] = -INFINITY; }
        __syncthreads();
    }
}

__global__ void gather_kernel(const float* __restrict__ x, const int* __restrict__ tidx,
                              float* __restrict__ sel)
{
    int row = blockIdx.x;
    int b = row >> 6;
    int src = tidx[row];
    for (int d = threadIdx.x; d < 512; d += 256)
        sel[(size_t)row * 512 + d] = x[(size_t)(b * S_LEN + src) * 512 + d];
}

__global__ void combine_kernel(const float* __restrict__ b0, const float* __restrict__ bC,
                               const float* __restrict__ bT, const float* __restrict__ gc,
                               const float* __restrict__ gt, float* __restrict__ out)
{
    int i = (blockIdx.x * 256 + threadIdx.x) * 4;
    float4 v0 = *(const float4*)(b0 + i);
    float4 vC = *(const float4*)(bC + i);
    float4 vT = *(const float4*)(bT + i);
    float4 c = *(const float4*)(gc + i);
    float4 t = *(const float4*)(gt + i);
    v0.x += c.x * vC.x + t.x * vT.x;
    v0.y += c.y * vC.y + t.y * vT.y;
    v0.z += c.z * vC.z + t.z * vT.z;
    v0.w += c.w * vC.w + t.w * vT.w;
    *(float4*)(out + i) = v0;
}

// ---------------- launch -----------------------------------------------------
extern "C" void kernel_launch(void* const* d_in, const int* in_sizes, int n_in,
                              void* d_out, int out_size)
{
    const float* x    = (const float*)d_in[0];
    const float* Wqkv = (const float*)d_in[1];  const float* bqkv = (const float*)d_in[2];
    const float* Wlo  = (const float*)d_in[3];  const float* blo  = (const float*)d_in[4];
    const float* Wcq  = (const float*)d_in[5];  const float* bcq  = (const float*)d_in[6];
    const float* Wck  = (const float*)d_in[7];  const float* bck  = (const float*)d_in[8];
    const float* Wcv  = (const float*)d_in[9];  const float* bcv  = (const float*)d_in[10];
    const float* Wco  = (const float*)d_in[11]; const float* bco  = (const float*)d_in[12];
    const float* Wgc  = (const float*)d_in[13]; const float* bgc  = (const float*)d_in[14];
    const float* Wimp = (const float*)d_in[15]; const float* bimp = (const float*)d_in[16];
    const float* Wtq  = (const float*)d_in[17]; const float* btq  = (const float*)d_in[18];
    const float* Wtk  = (const float*)d_in[19]; const float* btk  = (const float*)d_in[20];
    const float* Wtv  = (const float*)d_in[21]; const float* btv  = (const float*)d_in[22];
    const float* Wto  = (const float*)d_in[23]; const float* bto  = (const float*)d_in[24];
    const float* Wgt  = (const float*)d_in[25]; const float* bgt  = (const float*)d_in[26];
    float* out = (float*)d_out;

    float *qkv, *attnL, *qc, *attnC, *qt, *attnT, *gatec, *gatet;
    float *comp, *kc, *vc, *sel, *kt, *vt, *imp;
    int* tidx;
    cudaGetSymbolAddress((void**)&qkv,   g_qkv);
    cudaGetSymbolAddress((void**)&attnL, g_attnL);
    cudaGetSymbolAddress((void**)&qc,    g_qc);
    cudaGetSymbolAddress((void**)&attnC, g_attnC);
    cudaGetSymbolAddress((void**)&qt,    g_qt);
    cudaGetSymbolAddress((void**)&attnT, g_attnT);
    cudaGetSymbolAddress((void**)&gatec, g_gatec);
    cudaGetSymbolAddress((void**)&gatet, g_gatet);
    cudaGetSymbolAddress((void**)&comp,  g_comp);
    cudaGetSymbolAddress((void**)&kc,    g_kc);
    cudaGetSymbolAddress((void**)&vc,    g_vc);
    cudaGetSymbolAddress((void**)&sel,   g_sel);
    cudaGetSymbolAddress((void**)&kt,    g_kt);
    cudaGetSymbolAddress((void**)&vt,    g_vt);
    cudaGetSymbolAddress((void**)&imp,   g_imp);
    cudaGetSymbolAddress((void**)&tidx,  g_tidx);

    const int ATTN_SMEM = (64 * 68 + 2 * 64 * 72 + 64 * 65) * 4 + 64 * 4; // 71168
    cudaFuncSetAttribute(attn_b, cudaFuncAttributeMaxDynamicSharedMemorySize, ATTN_SMEM);

    // 1) batched x-projections: qkv | comp_q | gate_comp | topk_q | gate_topk
    {
        Batch bt;
        bt.s[0] = {x, Wqkv, bqkv, qkv,   1536, 12, 0};
        bt.s[1] = {x, Wcq,  bcq,  qc,    512,  4,  0};
        bt.s[2] = {x, Wgc,  bgc,  gatec, 512,  4,  1};
        bt.s[3] = {x, Wtq,  btq,  qt,    512,  4,  0};
        bt.s[4] = {x, Wgt,  bgt,  gatet, 512,  4,  1};
        bt.n = 5;
        sgemm_b<<<dim3(28, 32), 256>>>(bt, 512);
    }

    // 2) compressed branch inputs
    pool_kernel<<<384, 512>>>(x, comp);
    {
        Batch bt;
        bt.s[0] = {comp, Wck, bck, kc, 512, 4, 0};
        bt.s[1] = {comp, Wcv, bcv, vc, 512, 4, 0};
        bt.n = 2;
        sgemm_b<<<dim3(8, 3), 256>>>(bt, 512);
    }

    // 3) top-k branch inputs
    imp_kernel<<<512, 256>>>(x, Wimp, bimp, imp);
    topk_kernel<<<2, 256>>>(imp, tidx);
    gather_kernel<<<128, 256>>>(x, tidx, sel);
    {
        Batch bt;
        bt.s[0] = {sel, Wtk, btk, kt, 512, 4, 0};
        bt.s[1] = {sel, Wtv, btv, vt, 512, 4, 0};
        bt.n = 2;
        sgemm_b<<<dim3(8, 1), 256>>>(bt, 512);
    }

    // 4) all three attentions in one launch
    {
        AttnParams P;
        P.Q[0] = qkv;        P.K[0] = qkv + 512; P.V[0] = qkv + 1024;
        P.O[0] = attnL;      P.qs[0] = 1536;     P.ks[0] = 1536; P.nk[0] = 2048;
        P.Q[1] = qc;         P.K[1] = kc;        P.V[1] = vc;
        P.O[1] = attnC;      P.qs[1] = 512;      P.ks[1] = 512;  P.nk[1] = 192;
        P.Q[2] = qt;         P.K[2] = kt;        P.V[2] = vt;
        P.O[2] = attnT;      P.qs[2] = 512;      P.ks[2] = 512;  P.nk[2] = 64;
        P.tidx = tidx;
        attn_b<<<dim3(32, 8, 6), 256, ATTN_SMEM>>>(P);
    }

    // 5) batched output projections into scratch (qkv buffer now free), then combine
    float* buf0 = qkv;
    float* bufC = qkv + (size_t)NTOK * 512;
    float* bufT = qkv + (size_t)NTOK * 1024;
    {
        Batch bt;
        bt.s[0] = {attnL, Wlo, blo, buf0, 512, 4, 0};
        bt.s[1] = {attnC, Wco, bco, bufC, 512, 4, 0};
        bt.s[2] = {attnT, Wto, bto, bufT, 512, 4, 0};
        bt.n = 3;
        sgemm_b<<<dim3(12, 32), 256>>>(bt, 512);
    }
    combine_kernel<<<NTOK * 512 / 1024, 256>>>(buf0, bufC, bufT, gatec, gatet, out);
}

// round 4
// speedup vs baseline: 2.2465x; 1.1793x over previous
#include <cuda_runtime.h>
#include <cuda_bf16.h>
#include <math.h>
#include <stdint.h>

#define S_LEN 2048
#define NTOK  4096
#define HDIM  64
#define NEGBIG -1e9f

// ===================== f32x2 helpers (attention) ============================
__device__ __forceinline__ unsigned long long f32dup(float x) {
    unsigned long long r;
    asm("mov.b64 %0, {%1, %1};" : "=l"(r) : "f"(x));
    return r;
}
__device__ __forceinline__ unsigned long long fma2(unsigned long long a,
                                                   unsigned long long b,
                                                   unsigned long long c) {
    unsigned long long d;
    asm("fma.rn.f32x2 %0, %1, %2, %3;" : "=l"(d) : "l"(a), "l"(b), "l"(c));
    return d;
}
__device__ __forceinline__ unsigned long long mul2(unsigned long long a,
                                                   unsigned long long b) {
    unsigned long long d;
    asm("mul.rn.f32x2 %0, %1, %2;" : "=l"(d) : "l"(a), "l"(b));
    return d;
}
__device__ __forceinline__ float2 unpack2(unsigned long long v) {
    float2 r;
    asm("mov.b64 {%0, %1}, %2;" : "=f"(r.x), "=f"(r.y) : "l"(v));
    return r;
}

// ===================== HMMA m16n8k16 bf16 ===================================
__device__ __forceinline__ void mma16816(float* c, const uint32_t* a,
                                         uint32_t b0, uint32_t b1) {
    asm volatile(
        "mma.sync.aligned.m16n8k16.row.col.f32.bf16.bf16.f32 "
        "{%0,%1,%2,%3}, {%4,%5,%6,%7}, {%8,%9}, {%0,%1,%2,%3};"
        : "+f"(c[0]), "+f"(c[1]), "+f"(c[2]), "+f"(c[3])
        : "r"(a[0]), "r"(a[1]), "r"(a[2]), "r"(a[3]), "r"(b0), "r"(b1));
}

// ===================== scratch ==============================================
__device__ __align__(16) float g_qkv  [NTOK*1536];   // + reused as 3 out-GEMM bufs
__device__ __align__(16) float g_attnL[NTOK*512];
__device__ __align__(16) float g_qc   [NTOK*512];
__device__ __align__(16) float g_attnC[NTOK*512];
__device__ __align__(16) float g_qt   [NTOK*512];
__device__ __align__(16) float g_attnT[NTOK*512];
__device__ __align__(16) float g_gatec[NTOK*512];
__device__ __align__(16) float g_gatet[NTOK*512];
__device__ __align__(16) float g_comp [384*512];
__device__ __align__(16) float g_sel  [128*512];
__device__ __align__(16) float g_kc   [384*512];
__device__ __align__(16) float g_vc   [384*512];
__device__ __align__(16) float g_kt   [128*512];
__device__ __align__(16) float g_vt   [128*512];
__device__ __align__(16) float g_imp  [NTOK];
__device__ int   g_tidx [128];

// bf16 split arenas
__device__ __align__(16) __nv_bfloat16 g_xh[NTOK*512],  g_xl[NTOK*512];
__device__ __align__(16) __nv_bfloat16 g_aLh[NTOK*512], g_aLl[NTOK*512];
__device__ __align__(16) __nv_bfloat16 g_aCh[NTOK*512], g_aCl[NTOK*512];
__device__ __align__(16) __nv_bfloat16 g_aTh[NTOK*512], g_aTl[NTOK*512];
__device__ __align__(16) __nv_bfloat16 g_ch[384*512],   g_cl[384*512];
__device__ __align__(16) __nv_bfloat16 g_sh[128*512],   g_sl[128*512];
__device__ __align__(16) __nv_bfloat16 g_wh[7168*512],  g_wl[7168*512]; // transposed weights

// ===================== converters ===========================================
struct CSeg { const float* src; __nv_bfloat16* hi; __nv_bfloat16* lo; int blk; };
struct CBatch { CSeg s[3]; int n; };

__global__ __launch_bounds__(256) void conv_split(CBatch bt)
{
    int b = blockIdx.x, si = 0;
    while (si < bt.n - 1 && b >= bt.s[si].blk) { b -= bt.s[si].blk; si++; }
    size_t e = (size_t)b * 1024 + threadIdx.x * 4;
    float4 v = *(const float4*)(bt.s[si].src + e);
    __nv_bfloat16 h0 = __float2bfloat16(v.x), h1 = __float2bfloat16(v.y);
    __nv_bfloat16 h2 = __float2bfloat16(v.z), h3 = __float2bfloat16(v.w);
    __nv_bfloat16 l0 = __float2bfloat16(v.x - __bfloat162float(h0));
    __nv_bfloat16 l1 = __float2bfloat16(v.y - __bfloat162float(h1));
    __nv_bfloat16 l2 = __float2bfloat16(v.z - __bfloat162float(h2));
    __nv_bfloat16 l3 = __float2bfloat16(v.w - __bfloat162float(h3));
    *(__nv_bfloat162*)(bt.s[si].hi + e)     = __halves2bfloat162(h0, h1);
    *(__nv_bfloat162*)(bt.s[si].hi + e + 2) = __halves2bfloat162(h2, h3);
    *(__nv_bfloat162*)(bt.s[si].lo + e)     = __halves2bfloat162(l0, l1);
    *(__nv_bfloat162*)(bt.s[si].lo + e + 2) = __halves2bfloat162(l2, l3);
}

struct WSeg { const float* W; __nv_bfloat16* hi; __nv_bfloat16* lo; int M; int blk; };
struct WBatch { WSeg s[12]; int n; };

__global__ __launch_bounds__(256) void conv_w(WBatch bt)
{
    int b = blockIdx.x, si = 0;
    while (si < bt.n - 1 && b >= bt.s[si].blk) { b -= bt.s[si].blk; si++; }
    int e = b * 256 + threadIdx.x;
    int n = e >> 9, k = e & 511;
    float w = bt.s[si].W[(size_t)k * bt.s[si].M + n];
    __nv_bfloat16 h = __float2bfloat16(w);
    bt.s[si].hi[(size_t)n * 512 + k] = h;
    bt.s[si].lo[(size_t)n * 512 + k] = __float2bfloat16(w - __bfloat162float(h));
}

// ===================== HMMA GEMM (bf16 3-split, fp32 acc) ===================
// C[rows x Mout] = A[rows x 512] @ W[512 x Mout] + bias
// A split arenas [rows][512]; B = transposed weight split [Mout][512] (= .col operand).
// 128x128 tile / CTA, 8 warps (4 row x 2 col), warp does 32x64 via m16n8k16.
struct MSeg {
    const __nv_bfloat16 *Ah, *Al, *Bh, *Bl;
    const float* bias; float* C;
    int tiles, epi, Mout;
};
struct MBatch { MSeg s[5]; int n; };

#define SSTR 40   // smem row stride in bf16 (20 banks -> conflict-free frags)

__global__ __launch_bounds__(256) void mma_gemm(MBatch bt)
{
    __shared__ __nv_bfloat16 sA[2][128 * SSTR];
    __shared__ __nv_bfloat16 sB[2][128 * SSTR];

    int ct = blockIdx.x, si = 0;
    while (si < bt.n - 1 && ct >= bt.s[si].tiles) { ct -= bt.s[si].tiles; si++; }
    const __nv_bfloat16* __restrict__ Ah = bt.s[si].Ah;
    const __nv_bfloat16* __restrict__ Al = bt.s[si].Al;
    const __nv_bfloat16* __restrict__ Bh = bt.s[si].Bh;
    const __nv_bfloat16* __restrict__ Bl = bt.s[si].Bl;
    const int row0 = blockIdx.y * 128, col0 = ct * 128;

    const int tid = threadIdx.x, wid = tid >> 5, lane = tid & 31;
    const int wr = wid & 3, wc = wid >> 2;
    const int lr = lane >> 2, lc = (lane & 3) * 2;

    float acc[2][8][4];
#pragma unroll
    for (int mt = 0; mt < 2; mt++)
#pragma unroll
        for (int nt = 0; nt < 8; nt++)
#pragma unroll
            for (int j = 0; j < 4; j++) acc[mt][nt][j] = 0.f;

    const int ldr = tid >> 2, ldc = (tid & 3) * 8;   // 256 threads: 64 rows x 4 col16

    for (int kc = 0; kc < 512; kc += 32) {
        __syncthreads();
#pragma unroll
        for (int half = 0; half < 2; half++) {
            int r = ldr + half * 64;
            *(uint4*)(sA[0] + r * SSTR + ldc) =
                *(const uint4*)(Ah + (size_t)(row0 + r) * 512 + kc + ldc);
            *(uint4*)(sA[1] + r * SSTR + ldc) =
                *(const uint4*)(Al + (size_t)(row0 + r) * 512 + kc + ldc);
            *(uint4*)(sB[0] + r * SSTR + ldc) =
                *(const uint4*)(Bh + (size_t)(col0 + r) * 512 + kc + ldc);
            *(uint4*)(sB[1] + r * SSTR + ldc) =
                *(const uint4*)(Bl + (size_t)(col0 + r) * 512 + kc + ldc);
        }
        __syncthreads();

#pragma unroll
        for (int ks = 0; ks < 2; ks++) {
            const int k0 = ks * 16;
            uint32_t af[2][2][4];   // [hi/lo][mt][reg]
#pragma unroll
            for (int h = 0; h < 2; h++)
#pragma unroll
                for (int mt = 0; mt < 2; mt++) {
                    const __nv_bfloat16* base = sA[h] + (wr * 32 + mt * 16 + lr) * SSTR + k0 + lc;
                    af[h][mt][0] = *(const uint32_t*)(base);
                    af[h][mt][1] = *(const uint32_t*)(base + 8 * SSTR);
                    af[h][mt][2] = *(const uint32_t*)(base + 8);
                    af[h][mt][3] = *(const uint32_t*)(base + 8 * SSTR + 8);
                }
#pragma unroll
            for (int nt = 0; nt < 8; nt++) {
                const __nv_bfloat16* bb = sB[0] + (wc * 64 + nt * 8 + lr) * SSTR + k0 + lc;
                const __nv_bfloat16* bl = sB[1] + (wc * 64 + nt * 8 + lr) * SSTR + k0 + lc;
                uint32_t bh0 = *(const uint32_t*)(bb);
                uint32_t bh1 = *(const uint32_t*)(bb + 8);
                uint32_t bl0 = *(const uint32_t*)(bl);
                uint32_t bl1 = *(const uint32_t*)(bl + 8);
#pragma unroll
                for (int mt = 0; mt < 2; mt++) {
                    mma16816(acc[mt][nt], af[0][mt], bh0, bh1);
                    mma16816(acc[mt][nt], af[0][mt], bl0, bl1);
                    mma16816(acc[mt][nt], af[1][mt], bh0, bh1);
                }
            }
        }
    }

    // ---- epilogue ----
    const float* __restrict__ bias = bt.s[si].bias;
    float* __restrict__ C = bt.s[si].C;
    const int Mout = bt.s[si].Mout, epi = bt.s[si].epi;
#pragma unroll
    for (int mt = 0; mt < 2; mt++) {
        int r = row0 + wr * 32 + mt * 16 + lr;
#pragma unroll
        for (int nt = 0; nt < 8; nt++) {
            int c = col0 + wc * 64 + nt * 8 + lc;
            float b0 = __ldg(bias + c), b1 = __ldg(bias + c + 1);
            float v0 = acc[mt][nt][0] + b0, v1 = acc[mt][nt][1] + b1;
            float v2 = acc[mt][nt][2] + b0, v3 = acc[mt][nt][3] + b1;
            if (epi) {
                v0 = 1.f / (1.f + expf(-v0));
                v1 = 1.f / (1.f + expf(-v1));
                v2 = 1.f / (1.f + expf(-v2));
                v3 = 1.f / (1.f + expf(-v3));
            }
            *(float2*)(C + (size_t)r * Mout + c)       = make_float2(v0, v1);
            *(float2*)(C + (size_t)(r + 8) * Mout + c) = make_float2(v2, v3);
        }
    }
}

// ===================== flash attention (R2, passing) ========================
struct AttnParams {
    const float* Q[3]; const float* K[3]; const float* V[3]; float* O[3];
    int qs[3], ks[3], nk[3];
    const int* tidx;
};

__global__ __launch_bounds__(256) void attn_b(AttnParams P)
{
    extern __shared__ char dynsm[];
    float* sm = (float*)dynsm;
    float* Qs = sm;
    float* Ks = Qs + 64 * 68;
    float* Vs = Ks + 64 * 72;
    float* Ss = Vs + 64 * 72;
    int*  pos = (int*)(Ss + 64 * 65);

    const int mode = blockIdx.z >> 1, b = blockIdx.z & 1;
    const int h = blockIdx.y, q0 = blockIdx.x * 64;
    const int tid = threadIdx.x;

    const float* Qb = P.Q[mode]; const float* Kb = P.K[mode]; const float* Vb = P.V[mode];
    float* O = P.O[mode];
    const int qs = P.qs[mode], ks = P.ks[mode], nk = P.nk[mode];

    for (int idx = tid; idx < 64 * 16; idx += 256) {
        int r = idx >> 4, d0 = (idx & 15) << 2;
        float4 q = *(const float4*)(Qb + (size_t)(b * S_LEN + q0 + r) * qs + h * HDIM + d0);
        q.x *= 0.125f; q.y *= 0.125f; q.z *= 0.125f; q.w *= 0.125f;
        *(float4*)(&Qs[r * 68 + d0]) = q;
    }

    const int i_r = tid >> 2, jseg = tid & 3;
    const int q = q0 + i_r;
    unsigned long long o2[8];
#pragma unroll
    for (int c = 0; c < 8; c++) o2[c] = 0ull;
    float m = -INFINITY, l = 0.f;

    int kt0 = 0, ktend = nk;
    if (mode == 0) { kt0 = (q0 > 511) ? ((q0 - 511) & ~63) : 0; ktend = q0 + 64; }

    for (int kt = kt0; kt < ktend; kt += 64) {
        __syncthreads();
        for (int idx = tid; idx < 64 * 16; idx += 256) {
            int r = idx >> 4, d0 = (idx & 15) << 2;
            size_t gb = (size_t)(b * nk + kt + r);
            *(float4*)(&Ks[r * 72 + d0]) = *(const float4*)(Kb + gb * ks + h * HDIM + d0);
            *(float4*)(&Vs[r * 72 + d0]) = *(const float4*)(Vb + gb * ks + h * HDIM + d0);
        }
        if (tid < 64) {
            int j = kt + tid;
            pos[tid] = (mode == 0) ? j : (mode == 1 ? (j + 1) * 8 : P.tidx[b * 64 + j]);
        }
        __syncthreads();

        unsigned long long s2[16];
#pragma unroll
        for (int jj = 0; jj < 16; jj++) s2[jj] = 0ull;
        for (int d0 = 0; d0 < 64; d0 += 4) {
            ulonglong2 qq = *(const ulonglong2*)(&Qs[i_r * 68 + d0]);
#pragma unroll
            for (int jj = 0; jj < 16; jj++) {
                ulonglong2 kk2 = *(const ulonglong2*)(&Ks[(4 * jj + jseg) * 72 + d0]);
                s2[jj] = fma2(qq.x, kk2.x, s2[jj]);
                s2[jj] = fma2(qq.y, kk2.y, s2[jj]);
            }
        }

        float s[16], mt = -INFINITY;
#pragma unroll
        for (int jj = 0; jj < 16; jj++) {
            float2 t = unpack2(s2[jj]);
            float sv = t.x + t.y;
            int p = pos[4 * jj + jseg];
            bool vis = (mode == 0) ? ((unsigned)(q - p) < 512u) : (q >= p);
            if (!vis) sv = NEGBIG;
            s[jj] = sv;
            mt = fmaxf(mt, sv);
        }
        mt = fmaxf(mt, __shfl_xor_sync(0xffffffffu, mt, 1));
        mt = fmaxf(mt, __shfl_xor_sync(0xffffffffu, mt, 2));
        float m_new = fmaxf(m, mt);

        float lt = 0.f;
#pragma unroll
        for (int jj = 0; jj < 16; jj++) {
            float p = expf(s[jj] - m_new);
            lt += p;
            Ss[i_r * 65 + 4 * jj + jseg] = p;
        }
        lt += __shfl_xor_sync(0xffffffffu, lt, 1);
        lt += __shfl_xor_sync(0xffffffffu, lt, 2);
        float alpha = expf(m - m_new);
        l = l * alpha + lt;
        m = m_new;
        unsigned long long a2 = f32dup(alpha);
#pragma unroll
        for (int c = 0; c < 8; c++) o2[c] = mul2(o2[c], a2);
        __syncwarp();

        for (int j = 0; j < 64; j++) {
            unsigned long long p2 = f32dup(Ss[i_r * 65 + j]);
            ulonglong2 v01 = *(const ulonglong2*)(&Vs[j * 72 + jseg * 16]);
            ulonglong2 v23 = *(const ulonglong2*)(&Vs[j * 72 + jseg * 16 + 8]);
            o2[0] = fma2(p2, v01.x, o2[0]);
            o2[1] = fma2(p2, v01.y, o2[1]);
            o2[2] = fma2(p2, v23.x, o2[2]);
            o2[3] = fma2(p2, v23.y, o2[3]);
            ulonglong2 v45 = *(const ulonglong2*)(&Vs[j * 72 + jseg * 16 + 4]);
            ulonglong2 v67 = *(const ulonglong2*)(&Vs[j * 72 + jseg * 16 + 12]);
            o2[4] = fma2(p2, v45.x, o2[4]);
            o2[5] = fma2(p2, v45.y, o2[5]);
            o2[6] = fma2(p2, v67.x, o2[6]);
            o2[7] = fma2(p2, v67.y, o2[7]);
        }
    }

    float inv = 1.f / l;
    float* dst = O + (size_t)(b * S_LEN + q0 + i_r) * 512 + h * HDIM + jseg * 16;
    float2 t0 = unpack2(o2[0]), t1 = unpack2(o2[1]), t4 = unpack2(o2[4]), t5 = unpack2(o2[5]);
    float2 t2 = unpack2(o2[2]), t3 = unpack2(o2[3]), t6 = unpack2(o2[6]), t7 = unpack2(o2[7]);
    ((float4*)dst)[0] = make_float4(t0.x * inv, t0.y * inv, t1.x * inv, t1.y * inv);
    ((float4*)dst)[1] = make_float4(t4.x * inv, t4.y * inv, t5.x * inv, t5.y * inv);
    ((float4*)dst)[2] = make_float4(t2.x * inv, t2.y * inv, t3.x * inv, t3.y * inv);
    ((float4*)dst)[3] = make_float4(t6.x * inv, t6.y * inv, t7.x * inv, t7.y * inv);
}

// ===================== small kernels ========================================
__global__ void pool_kernel(const float* __restrict__ x, float* __restrict__ comp)
{
    int p = blockIdx.x % 192, b = blockIdx.x / 192;
    int d = threadIdx.x;
    float s = 0.f;
#pragma unroll
    for (int r = 0; r < 8; r++)
        s += x[(size_t)(b * S_LEN + p * 8 + r) * 512 + d];
    comp[(size_t)(b * 192 + p) * 512 + d] = s * 0.125f;
}

__global__ void imp_kernel(const float* __restrict__ x, const float* __restrict__ W,
                           const float* __restrict__ bias, float* __restrict__ imp)
{
    int t = blockIdx.x * 8 + (threadIdx.x >> 5);
    int lane = threadIdx.x & 31;
    float s = 0.f;
    for (int i = lane; i < 512; i += 32)
        s += x[(size_t)t * 512 + i] * W[i];
#pragma unroll
    for (int off = 16; off; off >>= 1)
        s += __shfl_xor_sync(0xffffffffu, s, off);
    if (!lane) imp[t] = s + bias[0];
}

__global__ void topk_kernel(const float* __restrict__ imp, int* __restrict__ tidx)
{
    int b = blockIdx.x;
    __shared__ float v[2048];
    __shared__ float bestv[256];
    __shared__ int   besti[256];
    int tid = threadIdx.x;
    for (int i = tid; i < 2048; i += 256) v[i] = imp[b * 2048 + i];
    __syncthreads();
    for (int r = 0; r < 64; r++) {
        float bv = -INFINITY; int bi = 0x7fffffff;
        for (int i = tid; i < 2048; i += 256) {
            float xv = v[i];
            if (xv > bv) { bv = xv; bi = i; }
        }
        bestv[tid] = bv; besti[tid] = bi;
        __syncthreads();
        for (int s2 = 128; s2 > 0; s2 >>= 1) {
            if (tid < s2) {
                float xo = bestv[tid + s2]; int io = besti[tid + s2];
                if (xo > bestv[tid] || (xo == bestv[tid] && io < besti[tid])) {
                    bestv[tid] = xo; besti[tid] = io;
                }
            }
            __syncthreads();
        }
        if (tid == 0) { tidx[b * 64 + r] = besti[0]; v[besti[0]] = -INFINITY; }
        __syncthreads();
    }
}

__global__ void gather_kernel(const float* __restrict__ x, const int* __restrict__ tidx,
                              float* __restrict__ sel)
{
    int row = blockIdx.x;
    int b = row >> 6;
    int src = tidx[row];
    for (int d = threadIdx.x; d < 512; d += 256)
        sel[(size_t)row * 512 + d] = x[(size_t)(b * S_LEN + src) * 512 + d];
}

__global__ void combine_kernel(const float* __restrict__ b0, const float* __restrict__ bC,
                               const float* __restrict__ bT, const float* __restrict__ gc,
                               const float* __restrict__ gt, float* __restrict__ out)
{
    int i = (blockIdx.x * 256 + threadIdx.x) * 4;
    float4 v0 = *(const float4*)(b0 + i);
    float4 vC = *(const float4*)(bC + i);
    float4 vT = *(const float4*)(bT + i);
    float4 c = *(const float4*)(gc + i);
    float4 t = *(const float4*)(gt + i);
    v0.x += c.x * vC.x + t.x * vT.x;
    v0.y += c.y * vC.y + t.y * vT.y;
    v0.z += c.z * vC.z + t.z * vT.z;
    v0.w += c.w * vC.w + t.w * vT.w;
    *(float4*)(out + i) = v0;
}

// ===================== launch ===============================================
extern "C" void kernel_launch(void* const* d_in, const int* in_sizes, int n_in,
                              void* d_out, int out_size)
{
    const float* x    = (const float*)d_in[0];
    const float* Wqkv = (const float*)d_in[1];  const float* bqkv = (const float*)d_in[2];
    const float* Wlo  = (const float*)d_in[3];  const float* blo  = (const float*)d_in[4];
    const float* Wcq  = (const float*)d_in[5];  const float* bcq  = (const float*)d_in[6];
    const float* Wck  = (const float*)d_in[7];  const float* bck  = (const float*)d_in[8];
    const float* Wcv  = (const float*)d_in[9];  const float* bcv  = (const float*)d_in[10];
    const float* Wco  = (const float*)d_in[11]; const float* bco  = (const float*)d_in[12];
    const float* Wgc  = (const float*)d_in[13]; const float* bgc  = (const float*)d_in[14];
    const float* Wimp = (const float*)d_in[15]; const float* bimp = (const float*)d_in[16];
    const float* Wtq  = (const float*)d_in[17]; const float* btq  = (const float*)d_in[18];
    const float* Wtk  = (const float*)d_in[19]; const float* btk  = (const float*)d_in[20];
    const float* Wtv  = (const float*)d_in[21]; const float* btv  = (const float*)d_in[22];
    const float* Wto  = (const float*)d_in[23]; const float* bto  = (const float*)d_in[24];
    const float* Wgt  = (const float*)d_in[25]; const float* bgt  = (const float*)d_in[26];
    float* out = (float*)d_out;

    float *qkv, *attnL, *qc, *attnC, *qt, *attnT, *gatec, *gatet;
    float *comp, *sel, *kc, *vc, *kt, *vt, *imp;
    int* tidx;
    __nv_bfloat16 *xh, *xl, *aLh, *aLl, *aCh, *aCl, *aTh, *aTl, *ch, *cl, *sh, *sl, *wh, *wl;
    cudaGetSymbolAddress((void**)&qkv,   g_qkv);
    cudaGetSymbolAddress((void**)&attnL, g_attnL);
    cudaGetSymbolAddress((void**)&qc,    g_qc);
    cudaGetSymbolAddress((void**)&attnC, g_attnC);
    cudaGetSymbolAddress((void**)&qt,    g_qt);
    cudaGetSymbolAddress((void**)&attnT, g_attnT);
    cudaGetSymbolAddress((void**)&gatec, g_gatec);
    cudaGetSymbolAddress((void**)&gatet, g_gatet);
    cudaGetSymbolAddress((void**)&comp,  g_comp);
    cudaGetSymbolAddress((void**)&sel,   g_sel);
    cudaGetSymbolAddress((void**)&kc,    g_kc);
    cudaGetSymbolAddress((void**)&vc,    g_vc);
    cudaGetSymbolAddress((void**)&kt,    g_kt);
    cudaGetSymbolAddress((void**)&vt,    g_vt);
    cudaGetSymbolAddress((void**)&imp,   g_imp);
    cudaGetSymbolAddress((void**)&tidx,  g_tidx);
    cudaGetSymbolAddress((void**)&xh,  g_xh);  cudaGetSymbolAddress((void**)&xl,  g_xl);
    cudaGetSymbolAddress((void**)&aLh, g_aLh); cudaGetSymbolAddress((void**)&aLl, g_aLl);
    cudaGetSymbolAddress((void**)&aCh, g_aCh); cudaGetSymbolAddress((void**)&aCl, g_aCl);
    cudaGetSymbolAddress((void**)&aTh, g_aTh); cudaGetSymbolAddress((void**)&aTl, g_aTl);
    cudaGetSymbolAddress((void**)&ch,  g_ch);  cudaGetSymbolAddress((void**)&cl,  g_cl);
    cudaGetSymbolAddress((void**)&sh,  g_sh);  cudaGetSymbolAddress((void**)&sl,  g_sl);
    cudaGetSymbolAddress((void**)&wh,  g_wh);  cudaGetSymbolAddress((void**)&wl,  g_wl);

    const int ATTN_SMEM = (64 * 68 + 2 * 64 * 72 + 64 * 65) * 4 + 64 * 4;
    cudaFuncSetAttribute(attn_b, cudaFuncAttributeMaxDynamicSharedMemorySize, ATTN_SMEM);

    // weight arena row offsets (each row = 512 bf16)
    const int O_QKV = 0,    O_LO = 1536, O_CQ = 2048, O_CK = 2560, O_CV = 3072,
              O_CO = 3584,  O_GC = 4096, O_TQ = 4608, O_TK = 5120, O_TV = 5632,
              O_TO = 6144,  O_GT = 6656;
    #define WH(o) (wh + (size_t)(o) * 512)
    #define WL(o) (wl + (size_t)(o) * 512)

    // 0) convert weights (transpose) and x
    {
        WBatch wb;
        wb.s[0]  = {Wqkv, WH(O_QKV), WL(O_QKV), 1536, 3072};
        wb.s[1]  = {Wlo,  WH(O_LO),  WL(O_LO),  512, 1024};
        wb.s[2]  = {Wcq,  WH(O_CQ),  WL(O_CQ),  512, 1024};
        wb.s[3]  = {Wck,  WH(O_CK),  WL(O_CK),  512, 1024};
        wb.s[4]  = {Wcv,  WH(O_CV),  WL(O_CV),  512, 1024};
        wb.s[5]  = {Wco,  WH(O_CO),  WL(O_CO),  512, 1024};
        wb.s[6]  = {Wgc,  WH(O_GC),  WL(O_GC),  512, 1024};
        wb.s[7]  = {Wtq,  WH(O_TQ),  WL(O_TQ),  512, 1024};
        wb.s[8]  = {Wtk,  WH(O_TK),  WL(O_TK),  512, 1024};
        wb.s[9]  = {Wtv,  WH(O_TV),  WL(O_TV),  512, 1024};
        wb.s[10] = {Wto,  WH(O_TO),  WL(O_TO),  512, 1024};
        wb.s[11] = {Wgt,  WH(O_GT),  WL(O_GT),  512, 1024};
        wb.n = 12;
        conv_w<<<3072 + 11 * 1024, 256>>>(wb);
    }
    {
        CBatch cb; cb.s[0] = {x, xh, xl, 2048}; cb.n = 1;
        conv_split<<<2048, 256>>>(cb);
    }

    // 1) batched x-projections on HMMA tensor cores
    {
        MBatch mb;
        mb.s[0] = {xh, xl, WH(O_QKV), WL(O_QKV), bqkv, qkv,   12, 0, 1536};
        mb.s[1] = {xh, xl, WH(O_CQ),  WL(O_CQ),  bcq,  qc,    4,  0, 512};
        mb.s[2] = {xh, xl, WH(O_GC),  WL(O_GC),  bgc,  gatec, 4,  1, 512};
        mb.s[3] = {xh, xl, WH(O_TQ),  WL(O_TQ),  btq,  qt,    4,  0, 512};
        mb.s[4] = {xh, xl, WH(O_GT),  WL(O_GT),  bgt,  gatet, 4,  1, 512};
        mb.n = 5;
        mma_gemm<<<dim3(28, 32), 256>>>(mb);
    }

    // 2) compressed branch
    pool_kernel<<<384, 512>>>(x, comp);
    {
        CBatch cb; cb.s[0] = {comp, ch, cl, 192}; cb.n = 1;
        conv_split<<<192, 256>>>(cb);
    }
    {
        MBatch mb;
        mb.s[0] = {ch, cl, WH(O_CK), WL(O_CK), bck, kc, 4, 0, 512};
        mb.s[1] = {ch, cl, WH(O_CV), WL(O_CV), bcv, vc, 4, 0, 512};
        mb.n = 2;
        mma_gemm<<<dim3(8, 3), 256>>>(mb);
    }

    // 3) top-k branch
    imp_kernel<<<512, 256>>>(x, Wimp, bimp, imp);
    topk_kernel<<<2, 256>>>(imp, tidx);
    gather_kernel<<<128, 256>>>(x, tidx, sel);
    {
        CBatch cb; cb.s[0] = {sel, sh, sl, 64}; cb.n = 1;
        conv_split<<<64, 256>>>(cb);
    }
    {
        MBatch mb;
        mb.s[0] = {sh, sl, WH(O_TK), WL(O_TK), btk, kt, 4, 0, 512};
        mb.s[1] = {sh, sl, WH(O_TV), WL(O_TV), btv, vt, 4, 0, 512};
        mb.n = 2;
        mma_gemm<<<dim3(8, 1), 256>>>(mb);
    }

    // 4) all three attentions (fp32 FFMA2 path)
    {
        AttnParams P;
        P.Q[0] = qkv;   P.K[0] = qkv + 512; P.V[0] = qkv + 1024;
        P.O[0] = attnL; P.qs[0] = 1536;     P.ks[0] = 1536; P.nk[0] = 2048;
        P.Q[1] = qc;    P.K[1] = kc;        P.V[1] = vc;
        P.O[1] = attnC; P.qs[1] = 512;      P.ks[1] = 512;  P.nk[1] = 192;
        P.Q[2] = qt;    P.K[2] = kt;        P.V[2] = vt;
        P.O[2] = attnT; P.qs[2] = 512;      P.ks[2] = 512;  P.nk[2] = 64;
        P.tidx = tidx;
        attn_b<<<dim3(32, 8, 6), 256, ATTN_SMEM>>>(P);
    }

    // 5) convert attn outputs, output projections, combine
    {
        CBatch cb;
        cb.s[0] = {attnL, aLh, aLl, 2048};
        cb.s[1] = {attnC, aCh, aCl, 2048};
        cb.s[2] = {attnT, aTh, aTl, 2048};
        cb.n = 3;
        conv_split<<<3 * 2048, 256>>>(cb);
    }
    float* buf0 = qkv;
    float* bufC = qkv + (size_t)NTOK * 512;
    float* bufT = qkv + (size_t)NTOK * 1024;
    {
        MBatch mb;
        mb.s[0] = {aLh, aLl, WH(O_LO), WL(O_LO), blo, buf0, 4, 0, 512};
        mb.s[1] = {aCh, aCl, WH(O_CO), WL(O_CO), bco, bufC, 4, 0, 512};
        mb.s[2] = {aTh, aTl, WH(O_TO), WL(O_TO), bto, bufT, 4, 0, 512};
        mb.n = 3;
        mma_gemm<<<dim3(12, 32), 256>>>(mb);
    }
    combine_kernel<<<NTOK * 512 / 1024, 256>>>(buf0, bufC, bufT, gatec, gatet, out);
}

// round 5
// speedup vs baseline: 3.9605x; 1.7630x over previous
#include <cuda_runtime.h>
#include <cuda_bf16.h>
#include <math.h>
#include <stdint.h>

#define S_LEN 2048
#define NTOK  4096
#define HDIM  64
#define NEGBIG -1e9f

// ===================== HMMA m16n8k16 bf16 ===================================
__device__ __forceinline__ void mma16816(float* c, const uint32_t* a,
                                         uint32_t b0, uint32_t b1) {
    asm volatile(
        "mma.sync.aligned.m16n8k16.row.col.f32.bf16.bf16.f32 "
        "{%0,%1,%2,%3}, {%4,%5,%6,%7}, {%8,%9}, {%0,%1,%2,%3};"
        : "+f"(c[0]), "+f"(c[1]), "+f"(c[2]), "+f"(c[3])
        : "r"(a[0]), "r"(a[1]), "r"(a[2]), "r"(a[3]), "r"(b0), "r"(b1));
}
__device__ __forceinline__ void ldsm_x2_t(uint32_t& r0, uint32_t& r1, uint32_t addr) {
    asm volatile("ldmatrix.sync.aligned.m8n8.x2.trans.shared.b16 {%0,%1}, [%2];"
                 : "=r"(r0), "=r"(r1) : "r"(addr));
}
__device__ __forceinline__ uint32_t smem_u32(const void* p) {
    uint32_t a;
    asm("{ .reg .u64 t; cvta.to.shared.u64 t, %1; cvt.u32.u64 %0, t; }"
        : "=r"(a) : "l"(p));
    return a;
}

// ===================== scratch ==============================================
__device__ __align__(16) float g_qkv  [NTOK*1536];   // + reused as 3 out-GEMM bufs
__device__ __align__(16) float g_attnL[NTOK*512];
__device__ __align__(16) float g_qc   [NTOK*512];
__device__ __align__(16) float g_attnC[NTOK*512];
__device__ __align__(16) float g_qt   [NTOK*512];
__device__ __align__(16) float g_attnT[NTOK*512];
__device__ __align__(16) float g_gatec[NTOK*512];
__device__ __align__(16) float g_gatet[NTOK*512];
__device__ __align__(16) float g_comp [384*512];
__device__ __align__(16) float g_sel  [128*512];
__device__ __align__(16) float g_kc   [384*512];
__device__ __align__(16) float g_vc   [384*512];
__device__ __align__(16) float g_kt   [128*512];
__device__ __align__(16) float g_vt   [128*512];
__device__ __align__(16) float g_imp  [NTOK];
__device__ int   g_tidx [128];

// bf16 split arenas
__device__ __align__(16) __nv_bfloat16 g_xh[NTOK*512],  g_xl[NTOK*512];
__device__ __align__(16) __nv_bfloat16 g_aLh[NTOK*512], g_aLl[NTOK*512];
__device__ __align__(16) __nv_bfloat16 g_aCh[NTOK*512], g_aCl[NTOK*512];
__device__ __align__(16) __nv_bfloat16 g_aTh[NTOK*512], g_aTl[NTOK*512];
__device__ __align__(16) __nv_bfloat16 g_ch[384*512],   g_cl[384*512];
__device__ __align__(16) __nv_bfloat16 g_sh[128*512],   g_sl[128*512];
__device__ __align__(16) __nv_bfloat16 g_wh[7168*512],  g_wl[7168*512];

// ===================== converters ===========================================
struct CSeg { const float* src; __nv_bfloat16* hi; __nv_bfloat16* lo; int blk; };
struct CBatch { CSeg s[3]; int n; };

__global__ __launch_bounds__(256) void conv_split(CBatch bt)
{
    int b = blockIdx.x, si = 0;
    while (si < bt.n - 1 && b >= bt.s[si].blk) { b -= bt.s[si].blk; si++; }
    size_t e = (size_t)b * 1024 + threadIdx.x * 4;
    float4 v = *(const float4*)(bt.s[si].src + e);
    __nv_bfloat16 h0 = __float2bfloat16(v.x), h1 = __float2bfloat16(v.y);
    __nv_bfloat16 h2 = __float2bfloat16(v.z), h3 = __float2bfloat16(v.w);
    __nv_bfloat16 l0 = __float2bfloat16(v.x - __bfloat162float(h0));
    __nv_bfloat16 l1 = __float2bfloat16(v.y - __bfloat162float(h1));
    __nv_bfloat16 l2 = __float2bfloat16(v.z - __bfloat162float(h2));
    __nv_bfloat16 l3 = __float2bfloat16(v.w - __bfloat162float(h3));
    *(__nv_bfloat162*)(bt.s[si].hi + e)     = __halves2bfloat162(h0, h1);
    *(__nv_bfloat162*)(bt.s[si].hi + e + 2) = __halves2bfloat162(h2, h3);
    *(__nv_bfloat162*)(bt.s[si].lo + e)     = __halves2bfloat162(l0, l1);
    *(__nv_bfloat162*)(bt.s[si].lo + e + 2) = __halves2bfloat162(l2, l3);
}

// conv_w: coalesced transpose via 32x32 smem tile
struct WSeg { const float* W; __nv_bfloat16* hi; __nv_bfloat16* lo; int M; int blk; };
struct WBatch { WSeg s[12]; int n; };

__global__ __launch_bounds__(256) void conv_w(WBatch bt)
{
    __shared__ float ts[32][33];
    int b = blockIdx.x, si = 0;
    while (si < bt.n - 1 && b >= bt.s[si].blk) { b -= bt.s[si].blk; si++; }
    const float* __restrict__ W = bt.s[si].W;
    const int M = bt.s[si].M;
    const int ntn = M >> 5;
    const int tk = (b / ntn) * 32, tn = (b % ntn) * 32;
    const int tx = threadIdx.x & 31, ty = threadIdx.x >> 5;
#pragma unroll
    for (int i = 0; i < 4; i++)
        ts[ty + 8 * i][tx] = W[(size_t)(tk + ty + 8 * i) * M + tn + tx];
    __syncthreads();
#pragma unroll
    for (int i = 0; i < 4; i++) {
        int n = tn + ty + 8 * i, k = tk + tx;
        float w = ts[tx][ty + 8 * i];
        __nv_bfloat16 hh = __float2bfloat16(w);
        bt.s[si].hi[(size_t)n * 512 + k] = hh;
        bt.s[si].lo[(size_t)n * 512 + k] = __float2bfloat16(w - __bfloat162float(hh));
    }
}

// ===================== HMMA GEMM (unchanged, passing) =======================
struct MSeg {
    const __nv_bfloat16 *Ah, *Al, *Bh, *Bl;
    const float* bias; float* C;
    int tiles, epi, Mout;
};
struct MBatch { MSeg s[5]; int n; };

#define SSTR 40

__global__ __launch_bounds__(256) void mma_gemm(MBatch bt)
{
    __shared__ __nv_bfloat16 sA[2][128 * SSTR];
    __shared__ __nv_bfloat16 sB[2][128 * SSTR];

    int ct = blockIdx.x, si = 0;
    while (si < bt.n - 1 && ct >= bt.s[si].tiles) { ct -= bt.s[si].tiles; si++; }
    const __nv_bfloat16* __restrict__ Ah = bt.s[si].Ah;
    const __nv_bfloat16* __restrict__ Al = bt.s[si].Al;
    const __nv_bfloat16* __restrict__ Bh = bt.s[si].Bh;
    const __nv_bfloat16* __restrict__ Bl = bt.s[si].Bl;
    const int row0 = blockIdx.y * 128, col0 = ct * 128;

    const int tid = threadIdx.x, wid = tid >> 5, lane = tid & 31;
    const int wr = wid & 3, wc = wid >> 2;
    const int lr = lane >> 2, lc = (lane & 3) * 2;

    float acc[2][8][4];
#pragma unroll
    for (int mt = 0; mt < 2; mt++)
#pragma unroll
        for (int nt = 0; nt < 8; nt++)
#pragma unroll
            for (int j = 0; j < 4; j++) acc[mt][nt][j] = 0.f;

    const int ldr = tid >> 2, ldc = (tid & 3) * 8;

    for (int kc = 0; kc < 512; kc += 32) {
        __syncthreads();
#pragma unroll
        for (int half = 0; half < 2; half++) {
            int r = ldr + half * 64;
            *(uint4*)(sA[0] + r * SSTR + ldc) =
                *(const uint4*)(Ah + (size_t)(row0 + r) * 512 + kc + ldc);
            *(uint4*)(sA[1] + r * SSTR + ldc) =
                *(const uint4*)(Al + (size_t)(row0 + r) * 512 + kc + ldc);
            *(uint4*)(sB[0] + r * SSTR + ldc) =
                *(const uint4*)(Bh + (size_t)(col0 + r) * 512 + kc + ldc);
            *(uint4*)(sB[1] + r * SSTR + ldc) =
                *(const uint4*)(Bl + (size_t)(col0 + r) * 512 + kc + ldc);
        }
        __syncthreads();

#pragma unroll
        for (int ks = 0; ks < 2; ks++) {
            const int k0 = ks * 16;
            uint32_t af[2][2][4];
#pragma unroll
            for (int h = 0; h < 2; h++)
#pragma unroll
                for (int mt = 0; mt < 2; mt++) {
                    const __nv_bfloat16* base = sA[h] + (wr * 32 + mt * 16 + lr) * SSTR + k0 + lc;
                    af[h][mt][0] = *(const uint32_t*)(base);
                    af[h][mt][1] = *(const uint32_t*)(base + 8 * SSTR);
                    af[h][mt][2] = *(const uint32_t*)(base + 8);
                    af[h][mt][3] = *(const uint32_t*)(base + 8 * SSTR + 8);
                }
#pragma unroll
            for (int nt = 0; nt < 8; nt++) {
                const __nv_bfloat16* bb = sB[0] + (wc * 64 + nt * 8 + lr) * SSTR + k0 + lc;
                const __nv_bfloat16* bl = sB[1] + (wc * 64 + nt * 8 + lr) * SSTR + k0 + lc;
                uint32_t bh0 = *(const uint32_t*)(bb);
                uint32_t bh1 = *(const uint32_t*)(bb + 8);
                uint32_t bl0 = *(const uint32_t*)(bl);
                uint32_t bl1 = *(const uint32_t*)(bl + 8);
#pragma unroll
                for (int mt = 0; mt < 2; mt++) {
                    mma16816(acc[mt][nt], af[0][mt], bh0, bh1);
                    mma16816(acc[mt][nt], af[0][mt], bl0, bl1);
                    mma16816(acc[mt][nt], af[1][mt], bh0, bh1);
                }
            }
        }
    }

    const float* __restrict__ bias = bt.s[si].bias;
    float* __restrict__ C = bt.s[si].C;
    const int Mout = bt.s[si].Mout, epi = bt.s[si].epi;
#pragma unroll
    for (int mt = 0; mt < 2; mt++) {
        int r = row0 + wr * 32 + mt * 16 + lr;
#pragma unroll
        for (int nt = 0; nt < 8; nt++) {
            int c = col0 + wc * 64 + nt * 8 + lc;
            float b0 = __ldg(bias + c), b1 = __ldg(bias + c + 1);
            float v0 = acc[mt][nt][0] + b0, v1 = acc[mt][nt][1] + b1;
            float v2 = acc[mt][nt][2] + b0, v3 = acc[mt][nt][3] + b1;
            if (epi) {
                v0 = 1.f / (1.f + expf(-v0));
                v1 = 1.f / (1.f + expf(-v1));
                v2 = 1.f / (1.f + expf(-v2));
                v3 = 1.f / (1.f + expf(-v3));
            }
            *(float2*)(C + (size_t)r * Mout + c)       = make_float2(v0, v1);
            *(float2*)(C + (size_t)(r + 8) * Mout + c) = make_float2(v2, v3);
        }
    }
}

// ===================== HMMA flash attention =================================
// mode 0: local window (0 <= q-k < 512)   mode 1: compressed (q >= (k+1)*8)
// mode 2: topk (q >= tidx[k]).  Masked-uniform semantics preserved.
#define ASTR 72   // bf16 tile stride (36 words: conflict-free frag loads)
#define SST  68   // fp32 score stride

struct AttnParams {
    const float* Q[3]; const float* K[3]; const float* V[3]; float* O[3];
    int qs[3], ks[3], nk[3];
    const int* tidx;
};

__global__ __launch_bounds__(256) void attn_mma(AttnParams P)
{
    extern __shared__ char dynsm[];
    __nv_bfloat16* sQh = (__nv_bfloat16*)dynsm;
    __nv_bfloat16* sQl = sQh + 64 * ASTR;
    __nv_bfloat16* sKh = sQl + 64 * ASTR;
    __nv_bfloat16* sKl = sKh + 64 * ASTR;
    __nv_bfloat16* sVh = sKl + 64 * ASTR;
    __nv_bfloat16* sVl = sVh + 64 * ASTR;
    __nv_bfloat16* sPh = sVl + 64 * ASTR;
    __nv_bfloat16* sPl = sPh + 64 * ASTR;
    float* sS  = (float*)(sPl + 64 * ASTR);
    float* sAl = sS + 64 * SST;
    float* sIL = sAl + 64;
    int*   pos = (int*)(sIL + 64);

    const int mode = blockIdx.z >> 1, b = blockIdx.z & 1;
    const int h = blockIdx.y, q0 = blockIdx.x * 64;
    const int tid = threadIdx.x, wid = tid >> 5, lane = tid & 31;
    const int wr = wid & 3, wc = wid >> 2;
    const int lr = lane >> 2, lc = (lane & 3) * 2;

    const float* Qb = P.Q[mode]; const float* Kb = P.K[mode]; const float* Vb = P.V[mode];
    float* O = P.O[mode];
    const int qs = P.qs[mode], ks = P.ks[mode], nk = P.nk[mode];

    // load + scale + split Q
    for (int idx = tid; idx < 64 * 16; idx += 256) {
        int r = idx >> 4, d0 = (idx & 15) << 2;
        float4 q = *(const float4*)(Qb + (size_t)(b * S_LEN + q0 + r) * qs + h * HDIM + d0);
        q.x *= 0.125f; q.y *= 0.125f; q.z *= 0.125f; q.w *= 0.125f;
        __nv_bfloat16 h0 = __float2bfloat16(q.x), h1 = __float2bfloat16(q.y);
        __nv_bfloat16 h2 = __float2bfloat16(q.z), h3 = __float2bfloat16(q.w);
        *(__nv_bfloat162*)(sQh + r * ASTR + d0)     = __halves2bfloat162(h0, h1);
        *(__nv_bfloat162*)(sQh + r * ASTR + d0 + 2) = __halves2bfloat162(h2, h3);
        *(__nv_bfloat162*)(sQl + r * ASTR + d0) = __halves2bfloat162(
            __float2bfloat16(q.x - __bfloat162float(h0)),
            __float2bfloat16(q.y - __bfloat162float(h1)));
        *(__nv_bfloat162*)(sQl + r * ASTR + d0 + 2) = __halves2bfloat162(
            __float2bfloat16(q.z - __bfloat162float(h2)),
            __float2bfloat16(q.w - __bfloat162float(h3)));
    }

    float oacc[4][4];
#pragma unroll
    for (int nt = 0; nt < 4; nt++)
#pragma unroll
        for (int j = 0; j < 4; j++) oacc[nt][j] = 0.f;

    const int row = tid >> 2, jseg = tid & 3;
    const int q = q0 + row;
    float m = -INFINITY, l = 0.f;

    int kt0 = 0, ktend = nk;
    if (mode == 0) { kt0 = (q0 > 511) ? ((q0 - 511) & ~63) : 0; ktend = q0 + 64; }

    for (int kt = kt0; kt < ktend; kt += 64) {
        __syncthreads();
        for (int idx = tid; idx < 64 * 16; idx += 256) {
            int r = idx >> 4, d0 = (idx & 15) << 2;
            size_t gb = (size_t)(b * nk + kt + r);
            float4 kv = *(const float4*)(Kb + gb * ks + h * HDIM + d0);
            float4 vv = *(const float4*)(Vb + gb * ks + h * HDIM + d0);
            __nv_bfloat16 kh0 = __float2bfloat16(kv.x), kh1 = __float2bfloat16(kv.y);
            __nv_bfloat16 kh2 = __float2bfloat16(kv.z), kh3 = __float2bfloat16(kv.w);
            *(__nv_bfloat162*)(sKh + r * ASTR + d0)     = __halves2bfloat162(kh0, kh1);
            *(__nv_bfloat162*)(sKh + r * ASTR + d0 + 2) = __halves2bfloat162(kh2, kh3);
            *(__nv_bfloat162*)(sKl + r * ASTR + d0) = __halves2bfloat162(
                __float2bfloat16(kv.x - __bfloat162float(kh0)),
                __float2bfloat16(kv.y - __bfloat162float(kh1)));
            *(__nv_bfloat162*)(sKl + r * ASTR + d0 + 2) = __halves2bfloat162(
                __float2bfloat16(kv.z - __bfloat162float(kh2)),
                __float2bfloat16(kv.w - __bfloat162float(kh3)));
            __nv_bfloat16 vh0 = __float2bfloat16(vv.x), vh1 = __float2bfloat16(vv.y);
            __nv_bfloat16 vh2 = __float2bfloat16(vv.z), vh3 = __float2bfloat16(vv.w);
            *(__nv_bfloat162*)(sVh + r * ASTR + d0)     = __halves2bfloat162(vh0, vh1);
            *(__nv_bfloat162*)(sVh + r * ASTR + d0 + 2) = __halves2bfloat162(vh2, vh3);
            *(__nv_bfloat162*)(sVl + r * ASTR + d0) = __halves2bfloat162(
                __float2bfloat16(vv.x - __bfloat162float(vh0)),
                __float2bfloat16(vv.y - __bfloat162float(vh1)));
            *(__nv_bfloat162*)(sVl + r * ASTR + d0 + 2) = __halves2bfloat162(
                __float2bfloat16(vv.z - __bfloat162float(vh2)),
                __float2bfloat16(vv.w - __bfloat162float(vh3)));
        }
        if (tid < 64) {
            int j = kt + tid;
            pos[tid] = (mode == 0) ? j : (mode == 1 ? (j + 1) * 8 : P.tidx[b * 64 + j]);
        }
        __syncthreads();

        // ---- S = Q @ K^T (3-product) ----
        float sacc[4][4];
#pragma unroll
        for (int nt = 0; nt < 4; nt++)
#pragma unroll
            for (int j = 0; j < 4; j++) sacc[nt][j] = 0.f;
#pragma unroll
        for (int kss = 0; kss < 4; kss++) {
            const int k0 = kss * 16;
            uint32_t af[2][4];
#pragma unroll
            for (int hh = 0; hh < 2; hh++) {
                const __nv_bfloat16* base = (hh ? sQl : sQh) + (wr * 16 + lr) * ASTR + k0 + lc;
                af[hh][0] = *(const uint32_t*)(base);
                af[hh][1] = *(const uint32_t*)(base + 8 * ASTR);
                af[hh][2] = *(const uint32_t*)(base + 8);
                af[hh][3] = *(const uint32_t*)(base + 8 * ASTR + 8);
            }
#pragma unroll
            for (int nt = 0; nt < 4; nt++) {
                const __nv_bfloat16* bb = sKh + (wc * 32 + nt * 8 + lr) * ASTR + k0 + lc;
                const __nv_bfloat16* bl = sKl + (wc * 32 + nt * 8 + lr) * ASTR + k0 + lc;
                uint32_t bh0 = *(const uint32_t*)(bb);
                uint32_t bh1 = *(const uint32_t*)(bb + 8);
                uint32_t bl0 = *(const uint32_t*)(bl);
                uint32_t bl1 = *(const uint32_t*)(bl + 8);
                mma16816(sacc[nt], af[0], bh0, bh1);
                mma16816(sacc[nt], af[0], bl0, bl1);
                mma16816(sacc[nt], af[1], bh0, bh1);
            }
        }
#pragma unroll
        for (int nt = 0; nt < 4; nt++) {
            int r0 = wr * 16 + lr, c0 = wc * 32 + nt * 8 + lc;
            *(float2*)(sS + r0 * SST + c0)       = make_float2(sacc[nt][0], sacc[nt][1]);
            *(float2*)(sS + (r0 + 8) * SST + c0) = make_float2(sacc[nt][2], sacc[nt][3]);
        }
        __syncthreads();

        // ---- softmax (row ownership: row = tid>>2, keys j = 4*jj+jseg) ----
        float s[16], mt = -INFINITY;
#pragma unroll
        for (int jj = 0; jj < 16; jj++) {
            int j = 4 * jj + jseg;
            float sv = sS[row * SST + j];
            int p = pos[j];
            bool vis = (mode == 0) ? ((unsigned)(q - p) < 512u) : (q >= p);
            if (!vis) sv = NEGBIG;
            s[jj] = sv;
            mt = fmaxf(mt, sv);
        }
        mt = fmaxf(mt, __shfl_xor_sync(0xffffffffu, mt, 1));
        mt = fmaxf(mt, __shfl_xor_sync(0xffffffffu, mt, 2));
        float m_new = fmaxf(m, mt);

        float lt = 0.f;
#pragma unroll
        for (int jj = 0; jj < 16; jj++) {
            int j = 4 * jj + jseg;
            float p = expf(s[jj] - m_new);
            lt += p;
            __nv_bfloat16 ph = __float2bfloat16(p);
            sPh[row * ASTR + j] = ph;
            sPl[row * ASTR + j] = __float2bfloat16(p - __bfloat162float(ph));
        }
        lt += __shfl_xor_sync(0xffffffffu, lt, 1);
        lt += __shfl_xor_sync(0xffffffffu, lt, 2);
        float alpha = expf(m - m_new);
        l = l * alpha + lt;
        m = m_new;
        if (jseg == 0) sAl[row] = alpha;
        __syncthreads();

        // ---- rescale O, then O += P @ V ----
        float a0 = sAl[wr * 16 + lr], a1 = sAl[wr * 16 + lr + 8];
#pragma unroll
        for (int nt = 0; nt < 4; nt++) {
            oacc[nt][0] *= a0; oacc[nt][1] *= a0;
            oacc[nt][2] *= a1; oacc[nt][3] *= a1;
        }
        const int vrow = lane & 15;
#pragma unroll
        for (int kss = 0; kss < 4; kss++) {
            const int k0 = kss * 16;
            uint32_t af[2][4];
#pragma unroll
            for (int hh = 0; hh < 2; hh++) {
                const __nv_bfloat16* base = (hh ? sPl : sPh) + (wr * 16 + lr) * ASTR + k0 + lc;
                af[hh][0] = *(const uint32_t*)(base);
                af[hh][1] = *(const uint32_t*)(base + 8 * ASTR);
                af[hh][2] = *(const uint32_t*)(base + 8);
                af[hh][3] = *(const uint32_t*)(base + 8 * ASTR + 8);
            }
#pragma unroll
            for (int nt = 0; nt < 4; nt++) {
                int n0 = wc * 32 + nt * 8;
                uint32_t bh0, bh1, bl0, bl1;
                ldsm_x2_t(bh0, bh1, smem_u32(sVh + (k0 + vrow) * ASTR + n0));
                ldsm_x2_t(bl0, bl1, smem_u32(sVl + (k0 + vrow) * ASTR + n0));
                mma16816(oacc[nt], af[0], bh0, bh1);
                mma16816(oacc[nt], af[0], bl0, bl1);
                mma16816(oacc[nt], af[1], bh0, bh1);
            }
        }
    }

    if (jseg == 0) sIL[row] = 1.f / l;
    __syncthreads();
    float i0 = sIL[wr * 16 + lr], i1 = sIL[wr * 16 + lr + 8];
#pragma unroll
    for (int nt = 0; nt < 4; nt++) {
        int c = h * HDIM + wc * 32 + nt * 8 + lc;
        float* d0 = O + (size_t)(b * S_LEN + q0 + wr * 16 + lr) * 512 + c;
        float* d1 = O + (size_t)(b * S_LEN + q0 + wr * 16 + lr + 8) * 512 + c;
        *(float2*)d0 = make_float2(oacc[nt][0] * i0, oacc[nt][1] * i0);
        *(float2*)d1 = make_float2(oacc[nt][2] * i1, oacc[nt][3] * i1);
    }
}

// ===================== small kernels ========================================
__global__ void pool_kernel(const float* __restrict__ x, float* __restrict__ comp)
{
    int p = blockIdx.x % 192, b = blockIdx.x / 192;
    int d = threadIdx.x;
    float s = 0.f;
#pragma unroll
    for (int r = 0; r < 8; r++)
        s += x[(size_t)(b * S_LEN + p * 8 + r) * 512 + d];
    comp[(size_t)(b * 192 + p) * 512 + d] = s * 0.125f;
}

__global__ void imp_kernel(const float* __restrict__ x, const float* __restrict__ W,
                           const float* __restrict__ bias, float* __restrict__ imp)
{
    int t = blockIdx.x * 8 + (threadIdx.x >> 5);
    int lane = threadIdx.x & 31;
    float s = 0.f;
    for (int i = lane; i < 512; i += 32)
        s += x[(size_t)t * 512 + i] * W[i];
#pragma unroll
    for (int off = 16; off; off >>= 1)
        s += __shfl_xor_sync(0xffffffffu, s, off);
    if (!lane) imp[t] = s + bias[0];
}

__global__ void topk_kernel(const float* __restrict__ imp, int* __restrict__ tidx)
{
    int b = blockIdx.x;
    __shared__ float v[2048];
    __shared__ float bestv[256];
    __shared__ int   besti[256];
    int tid = threadIdx.x;
    for (int i = tid; i < 2048; i += 256) v[i] = imp[b * 2048 + i];
    __syncthreads();
    for (int r = 0; r < 64; r++) {
        float bv = -INFINITY; int bi = 0x7fffffff;
        for (int i = tid; i < 2048; i += 256) {
            float xv = v[i];
            if (xv > bv) { bv = xv; bi = i; }
        }
        bestv[tid] = bv; besti[tid] = bi;
        __syncthreads();
        for (int s2 = 128; s2 > 0; s2 >>= 1) {
            if (tid < s2) {
                float xo = bestv[tid + s2]; int io = besti[tid + s2];
                if (xo > bestv[tid] || (xo == bestv[tid] && io < besti[tid])) {
                    bestv[tid] = xo; besti[tid] = io;
                }
            }
            __syncthreads();
        }
        if (tid == 0) { tidx[b * 64 + r] = besti[0]; v[besti[0]] = -INFINITY; }
        __syncthreads();
    }
}

__global__ void gather_kernel(const float* __restrict__ x, const int* __restrict__ tidx,
                              float* __restrict__ sel)
{
    int row = blockIdx.x;
    int b = row >> 6;
    int src = tidx[row];
    for (int d = threadIdx.x; d < 512; d += 256)
        sel[(size_t)row * 512 + d] = x[(size_t)(b * S_LEN + src) * 512 + d];
}

__global__ void combine_kernel(const float* __restrict__ b0, const float* __restrict__ bC,
                               const float* __restrict__ bT, const float* __restrict__ gc,
                               const float* __restrict__ gt, float* __restrict__ out)
{
    int i = (blockIdx.x * 256 + threadIdx.x) * 4;
    float4 v0 = *(const float4*)(b0 + i);
    float4 vC = *(const float4*)(bC + i);
    float4 vT = *(const float4*)(bT + i);
    float4 c = *(const float4*)(gc + i);
    float4 t = *(const float4*)(gt + i);
    v0.x += c.x * vC.x + t.x * vT.x;
    v0.y += c.y * vC.y + t.y * vT.y;
    v0.z += c.z * vC.z + t.z * vT.z;
    v0.w += c.w * vC.w + t.w * vT.w;
    *(float4*)(out + i) = v0;
}

// ===================== launch ===============================================
extern "C" void kernel_launch(void* const* d_in, const int* in_sizes, int n_in,
                              void* d_out, int out_size)
{
    const float* x    = (const float*)d_in[0];
    const float* Wqkv = (const float*)d_in[1];  const float* bqkv = (const float*)d_in[2];
    const float* Wlo  = (const float*)d_in[3];  const float* blo  = (const float*)d_in[4];
    const float* Wcq  = (const float*)d_in[5];  const float* bcq  = (const float*)d_in[6];
    const float* Wck  = (const float*)d_in[7];  const float* bck  = (const float*)d_in[8];
    const float* Wcv  = (const float*)d_in[9];  const float* bcv  = (const float*)d_in[10];
    const float* Wco  = (const float*)d_in[11]; const float* bco  = (const float*)d_in[12];
    const float* Wgc  = (const float*)d_in[13]; const float* bgc  = (const float*)d_in[14];
    const float* Wimp = (const float*)d_in[15]; const float* bimp = (const float*)d_in[16];
    const float* Wtq  = (const float*)d_in[17]; const float* btq  = (const float*)d_in[18];
    const float* Wtk  = (const float*)d_in[19]; const float* btk  = (const float*)d_in[20];
    const float* Wtv  = (const float*)d_in[21]; const float* btv  = (const float*)d_in[22];
    const float* Wto  = (const float*)d_in[23]; const float* bto  = (const float*)d_in[24];
    const float* Wgt  = (const float*)d_in[25]; const float* bgt  = (const float*)d_in[26];
    float* out = (float*)d_out;

    float *qkv, *attnL, *qc, *attnC, *qt, *attnT, *gatec, *gatet;
    float *comp, *sel, *kc, *vc, *kt, *vt, *imp;
    int* tidx;
    __nv_bfloat16 *xh, *xl, *aLh, *aLl, *aCh, *aCl, *aTh, *aTl, *ch, *cl, *sh, *sl, *wh, *wl;
    cudaGetSymbolAddress((void**)&qkv,   g_qkv);
    cudaGetSymbolAddress((void**)&attnL, g_attnL);
    cudaGetSymbolAddress((void**)&qc,    g_qc);
    cudaGetSymbolAddress((void**)&attnC, g_attnC);
    cudaGetSymbolAddress((void**)&qt,    g_qt);
    cudaGetSymbolAddress((void**)&attnT, g_attnT);
    cudaGetSymbolAddress((void**)&gatec, g_gatec);
    cudaGetSymbolAddress((void**)&gatet, g_gatet);
    cudaGetSymbolAddress((void**)&comp,  g_comp);
    cudaGetSymbolAddress((void**)&sel,   g_sel);
    cudaGetSymbolAddress((void**)&kc,    g_kc);
    cudaGetSymbolAddress((void**)&vc,    g_vc);
    cudaGetSymbolAddress((void**)&kt,    g_kt);
    cudaGetSymbolAddress((void**)&vt,    g_vt);
    cudaGetSymbolAddress((void**)&imp,   g_imp);
    cudaGetSymbolAddress((void**)&tidx,  g_tidx);
    cudaGetSymbolAddress((void**)&xh,  g_xh);  cudaGetSymbolAddress((void**)&xl,  g_xl);
    cudaGetSymbolAddress((void**)&aLh, g_aLh); cudaGetSymbolAddress((void**)&aLl, g_aLl);
    cudaGetSymbolAddress((void**)&aCh, g_aCh); cudaGetSymbolAddress((void**)&aCl, g_aCl);
    cudaGetSymbolAddress((void**)&aTh, g_aTh); cudaGetSymbolAddress((void**)&aTl, g_aTl);
    cudaGetSymbolAddress((void**)&ch,  g_ch);  cudaGetSymbolAddress((void**)&cl,  g_cl);
    cudaGetSymbolAddress((void**)&sh,  g_sh);  cudaGetSymbolAddress((void**)&sl,  g_sl);
    cudaGetSymbolAddress((void**)&wh,  g_wh);  cudaGetSymbolAddress((void**)&wl,  g_wl);

    const int ATTN_SMEM = 8 * 64 * ASTR * 2 + 64 * SST * 4 + 3 * 64 * 4; // 91904
    cudaFuncSetAttribute(attn_mma, cudaFuncAttributeMaxDynamicSharedMemorySize, ATTN_SMEM);

    const int O_QKV = 0,    O_LO = 1536, O_CQ = 2048, O_CK = 2560, O_CV = 3072,
              O_CO = 3584,  O_GC = 4096, O_TQ = 4608, O_TK = 5120, O_TV = 5632,
              O_TO = 6144,  O_GT = 6656;
    #define WH(o) (wh + (size_t)(o) * 512)
    #define WL(o) (wl + (size_t)(o) * 512)

    // 0) convert weights (transpose, coalesced) and x
    {
        WBatch wb;
        wb.s[0]  = {Wqkv, WH(O_QKV), WL(O_QKV), 1536, 768};
        wb.s[1]  = {Wlo,  WH(O_LO),  WL(O_LO),  512, 256};
        wb.s[2]  = {Wcq,  WH(O_CQ),  WL(O_CQ),  512, 256};
        wb.s[3]  = {Wck,  WH(O_CK),  WL(O_CK),  512, 256};
        wb.s[4]  = {Wcv,  WH(O_CV),  WL(O_CV),  512, 256};
        wb.s[5]  = {Wco,  WH(O_CO),  WL(O_CO),  512, 256};
        wb.s[6]  = {Wgc,  WH(O_GC),  WL(O_GC),  512, 256};
        wb.s[7]  = {Wtq,  WH(O_TQ),  WL(O_TQ),  512, 256};
        wb.s[8]  = {Wtk,  WH(O_TK),  WL(O_TK),  512, 256};
        wb.s[9]  = {Wtv,  WH(O_TV),  WL(O_TV),  512, 256};
        wb.s[10] = {Wto,  WH(O_TO),  WL(O_TO),  512, 256};
        wb.s[11] = {Wgt,  WH(O_GT),  WL(O_GT),  512, 256};
        wb.n = 12;
        conv_w<<<768 + 11 * 256, 256>>>(wb);
    }
    {
        CBatch cb; cb.s[0] = {x, xh, xl, 2048}; cb.n = 1;
        conv_split<<<2048, 256>>>(cb);
    }

    // 1) batched x-projections (HMMA)
    {
        MBatch mb;
        mb.s[0] = {xh, xl, WH(O_QKV), WL(O_QKV), bqkv, qkv,   12, 0, 1536};
        mb.s[1] = {xh, xl, WH(O_CQ),  WL(O_CQ),  bcq,  qc,    4,  0, 512};
        mb.s[2] = {xh, xl, WH(O_GC),  WL(O_GC),  bgc,  gatec, 4,  1, 512};
        mb.s[3] = {xh, xl, WH(O_TQ),  WL(O_TQ),  btq,  qt,    4,  0, 512};
        mb.s[4] = {xh, xl, WH(O_GT),  WL(O_GT),  bgt,  gatet, 4,  1, 512};
        mb.n = 5;
        mma_gemm<<<dim3(28, 32), 256>>>(mb);
    }

    // 2) compressed branch
    pool_kernel<<<384, 512>>>(x, comp);
    {
        CBatch cb; cb.s[0] = {comp, ch, cl, 192}; cb.n = 1;
        conv_split<<<192, 256>>>(cb);
    }
    {
        MBatch mb;
        mb.s[0] = {ch, cl, WH(O_CK), WL(O_CK), bck, kc, 4, 0, 512};
        mb.s[1] = {ch, cl, WH(O_CV), WL(O_CV), bcv, vc, 4, 0, 512};
        mb.n = 2;
        mma_gemm<<<dim3(8, 3), 256>>>(mb);
    }

    // 3) top-k branch
    imp_kernel<<<512, 256>>>(x, Wimp, bimp, imp);
    topk_kernel<<<2, 256>>>(imp, tidx);
    gather_kernel<<<128, 256>>>(x, tidx, sel);
    {
        CBatch cb; cb.s[0] = {sel, sh, sl, 64}; cb.n = 1;
        conv_split<<<64, 256>>>(cb);
    }
    {
        MBatch mb;
        mb.s[0] = {sh, sl, WH(O_TK), WL(O_TK), btk, kt, 4, 0, 512};
        mb.s[1] = {sh, sl, WH(O_TV), WL(O_TV), btv, vt, 4, 0, 512};
        mb.n = 2;
        mma_gemm<<<dim3(8, 1), 256>>>(mb);
    }

    // 4) all three attentions (HMMA)
    {
        AttnParams P;
        P.Q[0] = qkv;   P.K[0] = qkv + 512; P.V[0] = qkv + 1024;
        P.O[0] = attnL; P.qs[0] = 1536;     P.ks[0] = 1536; P.nk[0] = 2048;
        P.Q[1] = qc;    P.K[1] = kc;        P.V[1] = vc;
        P.O[1] = attnC; P.qs[1] = 512;      P.ks[1] = 512;  P.nk[1] = 192;
        P.Q[2] = qt;    P.K[2] = kt;        P.V[2] = vt;
        P.O[2] = attnT; P.qs[2] = 512;      P.ks[2] = 512;  P.nk[2] = 64;
        P.tidx = tidx;
        attn_mma<<<dim3(32, 8, 6), 256, ATTN_SMEM>>>(P);
    }

    // 5) convert attn outputs, output projections, combine
    {
        CBatch cb;
        cb.s[0] = {attnL, aLh, aLl, 2048};
        cb.s[1] = {attnC, aCh, aCl, 2048};
        cb.s[2] = {attnT, aTh, aTl, 2048};
        cb.n = 3;
        conv_split<<<3 * 2048, 256>>>(cb);
    }
    float* buf0 = qkv;
    float* bufC = qkv + (size_t)NTOK * 512;
    float* bufT = qkv + (size_t)NTOK * 1024;
    {
        MBatch mb;
        mb.s[0] = {aLh, aLl, WH(O_LO), WL(O_LO), blo, buf0, 4, 0, 512};
        mb.s[1] = {aCh, aCl, WH(O_CO), WL(O_CO), bco, bufC, 4, 0, 512};
        mb.s[2] = {aTh, aTl, WH(O_TO), WL(O_TO), bto, bufT, 4, 0, 512};
        mb.n = 3;
        mma_gemm<<<dim3(12, 32), 256>>>(mb);
    }
    combine_kernel<<<NTOK * 512 / 1024, 256>>>(buf0, bufC, bufT, gatec, gatet, out);
}

// round 6
// speedup vs baseline: 4.5046x; 1.1374x over previous
#include <cuda_runtime.h>
#include <cuda_bf16.h>
#include <math.h>
#include <stdint.h>

#define S_LEN 2048
#define NTOK  4096
#define HDIM  64
#define NEGBIG -1e9f

// ===================== PTX helpers ==========================================
__device__ __forceinline__ void mma16816(float* c, const uint32_t* a,
                                         uint32_t b0, uint32_t b1) {
    asm volatile(
        "mma.sync.aligned.m16n8k16.row.col.f32.bf16.bf16.f32 "
        "{%0,%1,%2,%3}, {%4,%5,%6,%7}, {%8,%9}, {%0,%1,%2,%3};"
        : "+f"(c[0]), "+f"(c[1]), "+f"(c[2]), "+f"(c[3])
        : "r"(a[0]), "r"(a[1]), "r"(a[2]), "r"(a[3]), "r"(b0), "r"(b1));
}
__device__ __forceinline__ void ldsm_x2_t(uint32_t& r0, uint32_t& r1, uint32_t addr) {
    asm volatile("ldmatrix.sync.aligned.m8n8.x2.trans.shared.b16 {%0,%1}, [%2];"
                 : "=r"(r0), "=r"(r1) : "r"(addr));
}
__device__ __forceinline__ void ldsm_x2(uint32_t& r0, uint32_t& r1, uint32_t addr) {
    asm volatile("ldmatrix.sync.aligned.m8n8.x2.shared.b16 {%0,%1}, [%2];"
                 : "=r"(r0), "=r"(r1) : "r"(addr));
}
__device__ __forceinline__ void ldsm_x4(uint32_t* r, uint32_t addr) {
    asm volatile("ldmatrix.sync.aligned.m8n8.x4.shared.b16 {%0,%1,%2,%3}, [%4];"
                 : "=r"(r[0]), "=r"(r[1]), "=r"(r[2]), "=r"(r[3]) : "r"(addr));
}
__device__ __forceinline__ uint32_t smem_u32(const void* p) {
    uint32_t a;
    asm("{ .reg .u64 t; cvta.to.shared.u64 t, %1; cvt.u32.u64 %0, t; }"
        : "=r"(a) : "l"(p));
    return a;
}
__device__ __forceinline__ void cp16(uint32_t dst, const void* src) {
    asm volatile("cp.async.cg.shared.global [%0], [%1], 16;" :: "r"(dst), "l"(src));
}
#define CP_COMMIT() asm volatile("cp.async.commit_group;" ::: "memory")
#define CP_WAIT1()  asm volatile("cp.async.wait_group 1;" ::: "memory")
#define CP_WAIT0()  asm volatile("cp.async.wait_group 0;" ::: "memory")

// ===================== scratch ==============================================
__device__ __align__(16) float g_qkv  [NTOK*1536];   // + reused as 3 out-GEMM bufs
__device__ __align__(16) float g_qc   [NTOK*512];
__device__ __align__(16) float g_qt   [NTOK*512];
__device__ __align__(16) float g_gatec[NTOK*512];
__device__ __align__(16) float g_gatet[NTOK*512];
__device__ __align__(16) float g_comp [384*512];
__device__ __align__(16) float g_sel  [128*512];
__device__ __align__(16) float g_kc   [384*512];
__device__ __align__(16) float g_vc   [384*512];
__device__ __align__(16) float g_kt   [128*512];
__device__ __align__(16) float g_vt   [128*512];
__device__ __align__(16) float g_imp  [NTOK];
__device__ int   g_tidx [128];

// bf16 split arenas
__device__ __align__(16) __nv_bfloat16 g_xh[NTOK*512],  g_xl[NTOK*512];
__device__ __align__(16) __nv_bfloat16 g_aLh[NTOK*512], g_aLl[NTOK*512];
__device__ __align__(16) __nv_bfloat16 g_aCh[NTOK*512], g_aCl[NTOK*512];
__device__ __align__(16) __nv_bfloat16 g_aTh[NTOK*512], g_aTl[NTOK*512];
__device__ __align__(16) __nv_bfloat16 g_ch[384*512],   g_cl[384*512];
__device__ __align__(16) __nv_bfloat16 g_sh[128*512],   g_sl[128*512];
__device__ __align__(16) __nv_bfloat16 g_wh[7168*512],  g_wl[7168*512];

// ===================== converters ===========================================
struct CSeg { const float* src; __nv_bfloat16* hi; __nv_bfloat16* lo; int blk; };
struct CBatch { CSeg s[3]; int n; };

__global__ __launch_bounds__(256) void conv_split(CBatch bt)
{
    int b = blockIdx.x, si = 0;
    while (si < bt.n - 1 && b >= bt.s[si].blk) { b -= bt.s[si].blk; si++; }
    size_t e = (size_t)b * 1024 + threadIdx.x * 4;
    float4 v = *(const float4*)(bt.s[si].src + e);
    __nv_bfloat16 h0 = __float2bfloat16(v.x), h1 = __float2bfloat16(v.y);
    __nv_bfloat16 h2 = __float2bfloat16(v.z), h3 = __float2bfloat16(v.w);
    __nv_bfloat16 l0 = __float2bfloat16(v.x - __bfloat162float(h0));
    __nv_bfloat16 l1 = __float2bfloat16(v.y - __bfloat162float(h1));
    __nv_bfloat16 l2 = __float2bfloat16(v.z - __bfloat162float(h2));
    __nv_bfloat16 l3 = __float2bfloat16(v.w - __bfloat162float(h3));
    *(__nv_bfloat162*)(bt.s[si].hi + e)     = __halves2bfloat162(h0, h1);
    *(__nv_bfloat162*)(bt.s[si].hi + e + 2) = __halves2bfloat162(h2, h3);
    *(__nv_bfloat162*)(bt.s[si].lo + e)     = __halves2bfloat162(l0, l1);
    *(__nv_bfloat162*)(bt.s[si].lo + e + 2) = __halves2bfloat162(l2, l3);
}

struct WSeg { const float* W; __nv_bfloat16* hi; __nv_bfloat16* lo; int M; int blk; };
struct WBatch { WSeg s[12]; int n; };

__global__ __launch_bounds__(256) void conv_w(WBatch bt)
{
    __shared__ float ts[32][33];
    int b = blockIdx.x, si = 0;
    while (si < bt.n - 1 && b >= bt.s[si].blk) { b -= bt.s[si].blk; si++; }
    const float* __restrict__ W = bt.s[si].W;
    const int M = bt.s[si].M;
    const int ntn = M >> 5;
    const int tk = (b / ntn) * 32, tn = (b % ntn) * 32;
    const int tx = threadIdx.x & 31, ty = threadIdx.x >> 5;
#pragma unroll
    for (int i = 0; i < 4; i++)
        ts[ty + 8 * i][tx] = W[(size_t)(tk + ty + 8 * i) * M + tn + tx];
    __syncthreads();
#pragma unroll
    for (int i = 0; i < 4; i++) {
        int n = tn + ty + 8 * i, k = tk + tx;
        float w = ts[tx][ty + 8 * i];
        __nv_bfloat16 hh = __float2bfloat16(w);
        bt.s[si].hi[(size_t)n * 512 + k] = hh;
        bt.s[si].lo[(size_t)n * 512 + k] = __float2bfloat16(w - __bfloat162float(hh));
    }
}

// ===================== HMMA GEMM v2: cp.async double-buffer + ldmatrix ======
struct MSeg {
    const __nv_bfloat16 *Ah, *Al, *Bh, *Bl;
    const float* bias; float* C;
    int tiles, epi, Mout;
};
struct MBatch { MSeg s[5]; int n; };

#define SSTR 40
#define ARR  (128 * SSTR)   // elements per array

__global__ __launch_bounds__(256, 2) void mma_gemm(MBatch bt)
{
    extern __shared__ __nv_bfloat16 gsm[];   // [2 buf][4 arr][128*SSTR]

    int ct = blockIdx.x, si = 0;
    while (si < bt.n - 1 && ct >= bt.s[si].tiles) { ct -= bt.s[si].tiles; si++; }
    const __nv_bfloat16* __restrict__ srcs[4] =
        { bt.s[si].Ah, bt.s[si].Al, bt.s[si].Bh, bt.s[si].Bl };
    const int row0 = blockIdx.y * 128, col0 = ct * 128;
    const int rbase[4] = { row0, row0, col0, col0 };

    const int tid = threadIdx.x, wid = tid >> 5, lane = tid & 31;
    const int wr = wid & 3, wc = wid >> 2;
    const int lr = lane >> 2, lc = (lane & 3) * 2;

    float acc[2][8][4];
#pragma unroll
    for (int mt = 0; mt < 2; mt++)
#pragma unroll
        for (int nt = 0; nt < 8; nt++)
#pragma unroll
            for (int j = 0; j < 4; j++) acc[mt][nt][j] = 0.f;

    // cp.async load of one 32-wide k-chunk into buffer d
    const int idx0 = tid * 2;
    auto load_chunk = [&](int d, int kc) {
#pragma unroll
        for (int i = 0; i < 8; i++) {
            int a = i >> 1;
            int idx = idx0 + (i & 1);
            int r = idx >> 2, cg = idx & 3;
            uint32_t dst = smem_u32(gsm + (d * 4 + a) * ARR + r * SSTR + cg * 8);
            cp16(dst, srcs[a] + (size_t)(rbase[a] + r) * 512 + kc + cg * 8);
        }
        CP_COMMIT();
    };

    // ldmatrix lane addressing
    const int a_row = (lane & 7) + ((lane >> 3) & 1) * 8;   // + mt*16 + wr*32
    const int a_col = (lane >> 4) * 8;                      // + ks*16
    const int b_row = (lane & 7);                           // + nt*8 + wc*64
    const int b_col = ((lane >> 3) & 1) * 8;                // + ks*16 (lanes 0-15)

    load_chunk(0, 0);

    for (int c = 0; c < 16; c++) {
        if (c + 1 < 16) { load_chunk((c + 1) & 1, (c + 1) * 32); CP_WAIT1(); }
        else            { CP_WAIT0(); }
        __syncthreads();

        const int d = c & 1;
        __nv_bfloat16* bufAh = gsm + (d * 4 + 0) * ARR;
        __nv_bfloat16* bufAl = gsm + (d * 4 + 1) * ARR;
        __nv_bfloat16* bufBh = gsm + (d * 4 + 2) * ARR;
        __nv_bfloat16* bufBl = gsm + (d * 4 + 3) * ARR;

#pragma unroll
        for (int ks = 0; ks < 2; ks++) {
            const int k0 = ks * 16;
            uint32_t af[2][2][4];
#pragma unroll
            for (int h = 0; h < 2; h++)
#pragma unroll
                for (int mt = 0; mt < 2; mt++) {
                    uint32_t addr = smem_u32((h ? bufAl : bufAh) +
                        (wr * 32 + mt * 16 + a_row) * SSTR + k0 + a_col);
                    ldsm_x4(af[h][mt], addr);
                }
#pragma unroll
            for (int nt = 0; nt < 8; nt++) {
                uint32_t bh0, bh1, bl0, bl1;
                uint32_t ah = smem_u32(bufBh + (wc * 64 + nt * 8 + b_row) * SSTR + k0 + b_col);
                uint32_t al = smem_u32(bufBl + (wc * 64 + nt * 8 + b_row) * SSTR + k0 + b_col);
                ldsm_x2(bh0, bh1, ah);
                ldsm_x2(bl0, bl1, al);
#pragma unroll
                for (int mt = 0; mt < 2; mt++) {
                    mma16816(acc[mt][nt], af[0][mt], bh0, bh1);
                    mma16816(acc[mt][nt], af[0][mt], bl0, bl1);
                    mma16816(acc[mt][nt], af[1][mt], bh0, bh1);
                }
            }
        }
        __syncthreads();
    }

    const float* __restrict__ bias = bt.s[si].bias;
    float* __restrict__ C = bt.s[si].C;
    const int Mout = bt.s[si].Mout, epi = bt.s[si].epi;
#pragma unroll
    for (int mt = 0; mt < 2; mt++) {
        int r = row0 + wr * 32 + mt * 16 + lr;
#pragma unroll
        for (int nt = 0; nt < 8; nt++) {
            int c = col0 + wc * 64 + nt * 8 + lc;
            float b0 = __ldg(bias + c), b1 = __ldg(bias + c + 1);
            float v0 = acc[mt][nt][0] + b0, v1 = acc[mt][nt][1] + b1;
            float v2 = acc[mt][nt][2] + b0, v3 = acc[mt][nt][3] + b1;
            if (epi) {
                v0 = 1.f / (1.f + expf(-v0));
                v1 = 1.f / (1.f + expf(-v1));
                v2 = 1.f / (1.f + expf(-v2));
                v3 = 1.f / (1.f + expf(-v3));
            }
            *(float2*)(C + (size_t)r * Mout + c)       = make_float2(v0, v1);
            *(float2*)(C + (size_t)(r + 8) * Mout + c) = make_float2(v2, v3);
        }
    }
}

// ===================== HMMA flash attention (split-output fused) ============
#define ASTR 72
#define SST  68

struct AttnParams {
    const float* Q[3]; const float* K[3]; const float* V[3];
    __nv_bfloat16* Oh[3]; __nv_bfloat16* Ol[3];
    int qs[3], ks[3], nk[3];
    const int* tidx;
};

__global__ __launch_bounds__(256) void attn_mma(AttnParams P)
{
    extern __shared__ char dynsm[];
    __nv_bfloat16* sQh = (__nv_bfloat16*)dynsm;
    __nv_bfloat16* sQl = sQh + 64 * ASTR;
    __nv_bfloat16* sKh = sQl + 64 * ASTR;
    __nv_bfloat16* sKl = sKh + 64 * ASTR;
    __nv_bfloat16* sVh = sKl + 64 * ASTR;
    __nv_bfloat16* sVl = sVh + 64 * ASTR;
    __nv_bfloat16* sPh = sVl + 64 * ASTR;
    __nv_bfloat16* sPl = sPh + 64 * ASTR;
    float* sS  = (float*)(sPl + 64 * ASTR);
    float* sAl = sS + 64 * SST;
    float* sIL = sAl + 64;
    int*   pos = (int*)(sIL + 64);

    const int mode = blockIdx.z >> 1, b = blockIdx.z & 1;
    const int h = blockIdx.y, q0 = blockIdx.x * 64;
    const int tid = threadIdx.x, wid = tid >> 5, lane = tid & 31;
    const int wr = wid & 3, wc = wid >> 2;
    const int lr = lane >> 2, lc = (lane & 3) * 2;

    const float* Qb = P.Q[mode]; const float* Kb = P.K[mode]; const float* Vb = P.V[mode];
    const int qs = P.qs[mode], ks = P.ks[mode], nk = P.nk[mode];

    for (int idx = tid; idx < 64 * 16; idx += 256) {
        int r = idx >> 4, d0 = (idx & 15) << 2;
        float4 q = *(const float4*)(Qb + (size_t)(b * S_LEN + q0 + r) * qs + h * HDIM + d0);
        q.x *= 0.125f; q.y *= 0.125f; q.z *= 0.125f; q.w *= 0.125f;
        __nv_bfloat16 h0 = __float2bfloat16(q.x), h1 = __float2bfloat16(q.y);
        __nv_bfloat16 h2 = __float2bfloat16(q.z), h3 = __float2bfloat16(q.w);
        *(__nv_bfloat162*)(sQh + r * ASTR + d0)     = __halves2bfloat162(h0, h1);
        *(__nv_bfloat162*)(sQh + r * ASTR + d0 + 2) = __halves2bfloat162(h2, h3);
        *(__nv_bfloat162*)(sQl + r * ASTR + d0) = __halves2bfloat162(
            __float2bfloat16(q.x - __bfloat162float(h0)),
            __float2bfloat16(q.y - __bfloat162float(h1)));
        *(__nv_bfloat162*)(sQl + r * ASTR + d0 + 2) = __halves2bfloat162(
            __float2bfloat16(q.z - __bfloat162float(h2)),
            __float2bfloat16(q.w - __bfloat162float(h3)));
    }

    float oacc[4][4];
#pragma unroll
    for (int nt = 0; nt < 4; nt++)
#pragma unroll
        for (int j = 0; j < 4; j++) oacc[nt][j] = 0.f;

    const int row = tid >> 2, jseg = tid & 3;
    const int q = q0 + row;
    float m = -INFINITY, l = 0.f;

    int kt0 = 0, ktend = nk;
    if (mode == 0) { kt0 = (q0 > 511) ? ((q0 - 511) & ~63) : 0; ktend = q0 + 64; }

    for (int kt = kt0; kt < ktend; kt += 64) {
        __syncthreads();
        for (int idx = tid; idx < 64 * 16; idx += 256) {
            int r = idx >> 4, d0 = (idx & 15) << 2;
            size_t gb = (size_t)(b * nk + kt + r);
            float4 kv = *(const float4*)(Kb + gb * ks + h * HDIM + d0);
            float4 vv = *(const float4*)(Vb + gb * ks + h * HDIM + d0);
            __nv_bfloat16 kh0 = __float2bfloat16(kv.x), kh1 = __float2bfloat16(kv.y);
            __nv_bfloat16 kh2 = __float2bfloat16(kv.z), kh3 = __float2bfloat16(kv.w);
            *(__nv_bfloat162*)(sKh + r * ASTR + d0)     = __halves2bfloat162(kh0, kh1);
            *(__nv_bfloat162*)(sKh + r * ASTR + d0 + 2) = __halves2bfloat162(kh2, kh3);
            *(__nv_bfloat162*)(sKl + r * ASTR + d0) = __halves2bfloat162(
                __float2bfloat16(kv.x - __bfloat162float(kh0)),
                __float2bfloat16(kv.y - __bfloat162float(kh1)));
            *(__nv_bfloat162*)(sKl + r * ASTR + d0 + 2) = __halves2bfloat162(
                __float2bfloat16(kv.z - __bfloat162float(kh2)),
                __float2bfloat16(kv.w - __bfloat162float(kh3)));
            __nv_bfloat16 vh0 = __float2bfloat16(vv.x), vh1 = __float2bfloat16(vv.y);
            __nv_bfloat16 vh2 = __float2bfloat16(vv.z), vh3 = __float2bfloat16(vv.w);
            *(__nv_bfloat162*)(sVh + r * ASTR + d0)     = __halves2bfloat162(vh0, vh1);
            *(__nv_bfloat162*)(sVh + r * ASTR + d0 + 2) = __halves2bfloat162(vh2, vh3);
            *(__nv_bfloat162*)(sVl + r * ASTR + d0) = __halves2bfloat162(
                __float2bfloat16(vv.x - __bfloat162float(vh0)),
                __float2bfloat16(vv.y - __bfloat162float(vh1)));
            *(__nv_bfloat162*)(sVl + r * ASTR + d0 + 2) = __halves2bfloat162(
                __float2bfloat16(vv.z - __bfloat162float(vh2)),
                __float2bfloat16(vv.w - __bfloat162float(vh3)));
        }
        if (tid < 64) {
            int j = kt + tid;
            pos[tid] = (mode == 0) ? j : (mode == 1 ? (j + 1) * 8 : P.tidx[b * 64 + j]);
        }
        __syncthreads();

        float sacc[4][4];
#pragma unroll
        for (int nt = 0; nt < 4; nt++)
#pragma unroll
            for (int j = 0; j < 4; j++) sacc[nt][j] = 0.f;
#pragma unroll
        for (int kss = 0; kss < 4; kss++) {
            const int k0 = kss * 16;
            uint32_t af[2][4];
#pragma unroll
            for (int hh = 0; hh < 2; hh++) {
                const __nv_bfloat16* base = (hh ? sQl : sQh) + (wr * 16 + lr) * ASTR + k0 + lc;
                af[hh][0] = *(const uint32_t*)(base);
                af[hh][1] = *(const uint32_t*)(base + 8 * ASTR);
                af[hh][2] = *(const uint32_t*)(base + 8);
                af[hh][3] = *(const uint32_t*)(base + 8 * ASTR + 8);
            }
#pragma unroll
            for (int nt = 0; nt < 4; nt++) {
                const __nv_bfloat16* bb = sKh + (wc * 32 + nt * 8 + lr) * ASTR + k0 + lc;
                const __nv_bfloat16* bl = sKl + (wc * 32 + nt * 8 + lr) * ASTR + k0 + lc;
                uint32_t bh0 = *(const uint32_t*)(bb);
                uint32_t bh1 = *(const uint32_t*)(bb + 8);
                uint32_t bl0 = *(const uint32_t*)(bl);
                uint32_t bl1 = *(const uint32_t*)(bl + 8);
                mma16816(sacc[nt], af[0], bh0, bh1);
                mma16816(sacc[nt], af[0], bl0, bl1);
                mma16816(sacc[nt], af[1], bh0, bh1);
            }
        }
#pragma unroll
        for (int nt = 0; nt < 4; nt++) {
            int r0 = wr * 16 + lr, c0 = wc * 32 + nt * 8 + lc;
            *(float2*)(sS + r0 * SST + c0)       = make_float2(sacc[nt][0], sacc[nt][1]);
            *(float2*)(sS + (r0 + 8) * SST + c0) = make_float2(sacc[nt][2], sacc[nt][3]);
        }
        __syncthreads();

        float s[16], mt = -INFINITY;
#pragma unroll
        for (int jj = 0; jj < 16; jj++) {
            int j = 4 * jj + jseg;
            float sv = sS[row * SST + j];
            int p = pos[j];
            bool vis = (mode == 0) ? ((unsigned)(q - p) < 512u) : (q >= p);
            if (!vis) sv = NEGBIG;
            s[jj] = sv;
            mt = fmaxf(mt, sv);
        }
        mt = fmaxf(mt, __shfl_xor_sync(0xffffffffu, mt, 1));
        mt = fmaxf(mt, __shfl_xor_sync(0xffffffffu, mt, 2));
        float m_new = fmaxf(m, mt);

        float lt = 0.f;
#pragma unroll
        for (int jj = 0; jj < 16; jj++) {
            int j = 4 * jj + jseg;
            float p = expf(s[jj] - m_new);
            lt += p;
            __nv_bfloat16 ph = __float2bfloat16(p);
            sPh[row * ASTR + j] = ph;
            sPl[row * ASTR + j] = __float2bfloat16(p - __bfloat162float(ph));
        }
        lt += __shfl_xor_sync(0xffffffffu, lt, 1);
        lt += __shfl_xor_sync(0xffffffffu, lt, 2);
        float alpha = expf(m - m_new);
        l = l * alpha + lt;
        m = m_new;
        if (jseg == 0) sAl[row] = alpha;
        __syncthreads();

        float a0 = sAl[wr * 16 + lr], a1 = sAl[wr * 16 + lr + 8];
#pragma unroll
        for (int nt = 0; nt < 4; nt++) {
            oacc[nt][0] *= a0; oacc[nt][1] *= a0;
            oacc[nt][2] *= a1; oacc[nt][3] *= a1;
        }
        const int vrow = lane & 15;
#pragma unroll
        for (int kss = 0; kss < 4; kss++) {
            const int k0 = kss * 16;
            uint32_t af[2][4];
#pragma unroll
            for (int hh = 0; hh < 2; hh++) {
                const __nv_bfloat16* base = (hh ? sPl : sPh) + (wr * 16 + lr) * ASTR + k0 + lc;
                af[hh][0] = *(const uint32_t*)(base);
                af[hh][1] = *(const uint32_t*)(base + 8 * ASTR);
                af[hh][2] = *(const uint32_t*)(base + 8);
                af[hh][3] = *(const uint32_t*)(base + 8 * ASTR + 8);
            }
#pragma unroll
            for (int nt = 0; nt < 4; nt++) {
                int n0 = wc * 32 + nt * 8;
                uint32_t bh0, bh1, bl0, bl1;
                ldsm_x2_t(bh0, bh1, smem_u32(sVh + (k0 + vrow) * ASTR + n0));
                ldsm_x2_t(bl0, bl1, smem_u32(sVl + (k0 + vrow) * ASTR + n0));
                mma16816(oacc[nt], af[0], bh0, bh1);
                mma16816(oacc[nt], af[0], bl0, bl1);
                mma16816(oacc[nt], af[1], bh0, bh1);
            }
        }
    }

    if (jseg == 0) sIL[row] = 1.f / l;
    __syncthreads();
    float i0 = sIL[wr * 16 + lr], i1 = sIL[wr * 16 + lr + 8];
    __nv_bfloat16* Oh = P.Oh[mode];
    __nv_bfloat16* Ol = P.Ol[mode];
#pragma unroll
    for (int nt = 0; nt < 4; nt++) {
        int c = h * HDIM + wc * 32 + nt * 8 + lc;
        size_t o0 = (size_t)(b * S_LEN + q0 + wr * 16 + lr) * 512 + c;
        size_t o1 = (size_t)(b * S_LEN + q0 + wr * 16 + lr + 8) * 512 + c;
        float v0 = oacc[nt][0] * i0, v1 = oacc[nt][1] * i0;
        float v2 = oacc[nt][2] * i1, v3 = oacc[nt][3] * i1;
        __nv_bfloat16 h0 = __float2bfloat16(v0), h1 = __float2bfloat16(v1);
        __nv_bfloat16 h2 = __float2bfloat16(v2), h3 = __float2bfloat16(v3);
        *(__nv_bfloat162*)(Oh + o0) = __halves2bfloat162(h0, h1);
        *(__nv_bfloat162*)(Oh + o1) = __halves2bfloat162(h2, h3);
        *(__nv_bfloat162*)(Ol + o0) = __halves2bfloat162(
            __float2bfloat16(v0 - __bfloat162float(h0)),
            __float2bfloat16(v1 - __bfloat162float(h1)));
        *(__nv_bfloat162*)(Ol + o1) = __halves2bfloat162(
            __float2bfloat16(v2 - __bfloat162float(h2)),
            __float2bfloat16(v3 - __bfloat162float(h3)));
    }
}

// ===================== small kernels ========================================
__global__ void pool_kernel(const float* __restrict__ x, float* __restrict__ comp)
{
    int p = blockIdx.x % 192, b = blockIdx.x / 192;
    int d = threadIdx.x;
    float s = 0.f;
#pragma unroll
    for (int r = 0; r < 8; r++)
        s += x[(size_t)(b * S_LEN + p * 8 + r) * 512 + d];
    comp[(size_t)(b * 192 + p) * 512 + d] = s * 0.125f;
}

__global__ void imp_kernel(const float* __restrict__ x, const float* __restrict__ W,
                           const float* __restrict__ bias, float* __restrict__ imp)
{
    int t = blockIdx.x * 8 + (threadIdx.x >> 5);
    int lane = threadIdx.x & 31;
    float s = 0.f;
    for (int i = lane; i < 512; i += 32)
        s += x[(size_t)t * 512 + i] * W[i];
#pragma unroll
    for (int off = 16; off; off >>= 1)
        s += __shfl_xor_sync(0xffffffffu, s, off);
    if (!lane) imp[t] = s + bias[0];
}

__global__ void topk_kernel(const float* __restrict__ imp, int* __restrict__ tidx)
{
    int b = blockIdx.x;
    __shared__ float v[2048];
    __shared__ float bestv[256];
    __shared__ int   besti[256];
    int tid = threadIdx.x;
    for (int i = tid; i < 2048; i += 256) v[i] = imp[b * 2048 + i];
    __syncthreads();
    for (int r = 0; r < 64; r++) {
        float bv = -INFINITY; int bi = 0x7fffffff;
        for (int i = tid; i < 2048; i += 256) {
            float xv = v[i];
            if (xv > bv) { bv = xv; bi = i; }
        }
        bestv[tid] = bv; besti[tid] = bi;
        __syncthreads();
        for (int s2 = 128; s2 > 0; s2 >>= 1) {
            if (tid < s2) {
                float xo = bestv[tid + s2]; int io = besti[tid + s2];
                if (xo > bestv[tid] || (xo == bestv[tid] && io < besti[tid])) {
                    bestv[tid] = xo; besti[tid] = io;
                }
            }
            __syncthreads();
        }
        if (tid == 0) { tidx[b * 64 + r] = besti[0]; v[besti[0]] = -INFINITY; }
        __syncthreads();
    }
}

__global__ void gather_kernel(const float* __restrict__ x, const int* __restrict__ tidx,
                              float* __restrict__ sel)
{
    int row = blockIdx.x;
    int b = row >> 6;
    int src = tidx[row];
    for (int d = threadIdx.x; d < 512; d += 256)
        sel[(size_t)row * 512 + d] = x[(size_t)(b * S_LEN + src) * 512 + d];
}

__global__ void combine_kernel(const float* __restrict__ b0, const float* __restrict__ bC,
                               const float* __restrict__ bT, const float* __restrict__ gc,
                               const float* __restrict__ gt, float* __restrict__ out)
{
    int i = (blockIdx.x * 256 + threadIdx.x) * 4;
    float4 v0 = *(const float4*)(b0 + i);
    float4 vC = *(const float4*)(bC + i);
    float4 vT = *(const float4*)(bT + i);
    float4 c = *(const float4*)(gc + i);
    float4 t = *(const float4*)(gt + i);
    v0.x += c.x * vC.x + t.x * vT.x;
    v0.y += c.y * vC.y + t.y * vT.y;
    v0.z += c.z * vC.z + t.z * vT.z;
    v0.w += c.w * vC.w + t.w * vT.w;
    *(float4*)(out + i) = v0;
}

// ===================== launch ===============================================
extern "C" void kernel_launch(void* const* d_in, const int* in_sizes, int n_in,
                              void* d_out, int out_size)
{
    const float* x    = (const float*)d_in[0];
    const float* Wqkv = (const float*)d_in[1];  const float* bqkv = (const float*)d_in[2];
    const float* Wlo  = (const float*)d_in[3];  const float* blo  = (const float*)d_in[4];
    const float* Wcq  = (const float*)d_in[5];  const float* bcq  = (const float*)d_in[6];
    const float* Wck  = (const float*)d_in[7];  const float* bck  = (const float*)d_in[8];
    const float* Wcv  = (const float*)d_in[9];  const float* bcv  = (const float*)d_in[10];
    const float* Wco  = (const float*)d_in[11]; const float* bco  = (const float*)d_in[12];
    const float* Wgc  = (const float*)d_in[13]; const float* bgc  = (const float*)d_in[14];
    const float* Wimp = (const float*)d_in[15]; const float* bimp = (const float*)d_in[16];
    const float* Wtq  = (const float*)d_in[17]; const float* btq  = (const float*)d_in[18];
    const float* Wtk  = (const float*)d_in[19]; const float* btk  = (const float*)d_in[20];
    const float* Wtv  = (const float*)d_in[21]; const float* btv  = (const float*)d_in[22];
    const float* Wto  = (const float*)d_in[23]; const float* bto  = (const float*)d_in[24];
    const float* Wgt  = (const float*)d_in[25]; const float* bgt  = (const float*)d_in[26];
    float* out = (float*)d_out;

    float *qkv, *qc, *qt, *gatec, *gatet;
    float *comp, *sel, *kc, *vc, *kt, *vt, *imp;
    int* tidx;
    __nv_bfloat16 *xh, *xl, *aLh, *aLl, *aCh, *aCl, *aTh, *aTl, *ch, *cl, *sh, *sl, *wh, *wl;
    cudaGetSymbolAddress((void**)&qkv,   g_qkv);
    cudaGetSymbolAddress((void**)&qc,    g_qc);
    cudaGetSymbolAddress((void**)&qt,    g_qt);
    cudaGetSymbolAddress((void**)&gatec, g_gatec);
    cudaGetSymbolAddress((void**)&gatet, g_gatet);
    cudaGetSymbolAddress((void**)&comp,  g_comp);
    cudaGetSymbolAddress((void**)&sel,   g_sel);
    cudaGetSymbolAddress((void**)&kc,    g_kc);
    cudaGetSymbolAddress((void**)&vc,    g_vc);
    cudaGetSymbolAddress((void**)&kt,    g_kt);
    cudaGetSymbolAddress((void**)&vt,    g_vt);
    cudaGetSymbolAddress((void**)&imp,   g_imp);
    cudaGetSymbolAddress((void**)&tidx,  g_tidx);
    cudaGetSymbolAddress((void**)&xh,  g_xh);  cudaGetSymbolAddress((void**)&xl,  g_xl);
    cudaGetSymbolAddress((void**)&aLh, g_aLh); cudaGetSymbolAddress((void**)&aLl, g_aLl);
    cudaGetSymbolAddress((void**)&aCh, g_aCh); cudaGetSymbolAddress((void**)&aCl, g_aCl);
    cudaGetSymbolAddress((void**)&aTh, g_aTh); cudaGetSymbolAddress((void**)&aTl, g_aTl);
    cudaGetSymbolAddress((void**)&ch,  g_ch);  cudaGetSymbolAddress((void**)&cl,  g_cl);
    cudaGetSymbolAddress((void**)&sh,  g_sh);  cudaGetSymbolAddress((void**)&sl,  g_sl);
    cudaGetSymbolAddress((void**)&wh,  g_wh);  cudaGetSymbolAddress((void**)&wl,  g_wl);

    const int ATTN_SMEM = 8 * 64 * ASTR * 2 + 64 * SST * 4 + 3 * 64 * 4;
    cudaFuncSetAttribute(attn_mma, cudaFuncAttributeMaxDynamicSharedMemorySize, ATTN_SMEM);
    const int GEMM_SMEM = 2 * 4 * ARR * 2;   // 81920
    cudaFuncSetAttribute(mma_gemm, cudaFuncAttributeMaxDynamicSharedMemorySize, GEMM_SMEM);

    const int O_QKV = 0,    O_LO = 1536, O_CQ = 2048, O_CK = 2560, O_CV = 3072,
              O_CO = 3584,  O_GC = 4096, O_TQ = 4608, O_TK = 5120, O_TV = 5632,
              O_TO = 6144,  O_GT = 6656;
    #define WH(o) (wh + (size_t)(o) * 512)
    #define WL(o) (wl + (size_t)(o) * 512)

    // 0) convert weights (transpose, coalesced) and x
    {
        WBatch wb;
        wb.s[0]  = {Wqkv, WH(O_QKV), WL(O_QKV), 1536, 768};
        wb.s[1]  = {Wlo,  WH(O_LO),  WL(O_LO),  512, 256};
        wb.s[2]  = {Wcq,  WH(O_CQ),  WL(O_CQ),  512, 256};
        wb.s[3]  = {Wck,  WH(O_CK),  WL(O_CK),  512, 256};
        wb.s[4]  = {Wcv,  WH(O_CV),  WL(O_CV),  512, 256};
        wb.s[5]  = {Wco,  WH(O_CO),  WL(O_CO),  512, 256};
        wb.s[6]  = {Wgc,  WH(O_GC),  WL(O_GC),  512, 256};
        wb.s[7]  = {Wtq,  WH(O_TQ),  WL(O_TQ),  512, 256};
        wb.s[8]  = {Wtk,  WH(O_TK),  WL(O_TK),  512, 256};
        wb.s[9]  = {Wtv,  WH(O_TV),  WL(O_TV),  512, 256};
        wb.s[10] = {Wto,  WH(O_TO),  WL(O_TO),  512, 256};
        wb.s[11] = {Wgt,  WH(O_GT),  WL(O_GT),  512, 256};
        wb.n = 12;
        conv_w<<<768 + 11 * 256, 256>>>(wb);
    }
    {
        CBatch cb; cb.s[0] = {x, xh, xl, 2048}; cb.n = 1;
        conv_split<<<2048, 256>>>(cb);
    }

    // 1) batched x-projections (HMMA v2)
    {
        MBatch mb;
        mb.s[0] = {xh, xl, WH(O_QKV), WL(O_QKV), bqkv, qkv,   12, 0, 1536};
        mb.s[1] = {xh, xl, WH(O_CQ),  WL(O_CQ),  bcq,  qc,    4,  0, 512};
        mb.s[2] = {xh, xl, WH(O_GC),  WL(O_GC),  bgc,  gatec, 4,  1, 512};
        mb.s[3] = {xh, xl, WH(O_TQ),  WL(O_TQ),  btq,  qt,    4,  0, 512};
        mb.s[4] = {xh, xl, WH(O_GT),  WL(O_GT),  bgt,  gatet, 4,  1, 512};
        mb.n = 5;
        mma_gemm<<<dim3(28, 32), 256, GEMM_SMEM>>>(mb);
    }

    // 2) compressed branch
    pool_kernel<<<384, 512>>>(x, comp);
    {
        CBatch cb; cb.s[0] = {comp, ch, cl, 192}; cb.n = 1;
        conv_split<<<192, 256>>>(cb);
    }
    {
        MBatch mb;
        mb.s[0] = {ch, cl, WH(O_CK), WL(O_CK), bck, kc, 4, 0, 512};
        mb.s[1] = {ch, cl, WH(O_CV), WL(O_CV), bcv, vc, 4, 0, 512};
        mb.n = 2;
        mma_gemm<<<dim3(8, 3), 256, GEMM_SMEM>>>(mb);
    }

    // 3) top-k branch
    imp_kernel<<<512, 256>>>(x, Wimp, bimp, imp);
    topk_kernel<<<2, 256>>>(imp, tidx);
    gather_kernel<<<128, 256>>>(x, tidx, sel);
    {
        CBatch cb; cb.s[0] = {sel, sh, sl, 64}; cb.n = 1;
        conv_split<<<64, 256>>>(cb);
    }
    {
        MBatch mb;
        mb.s[0] = {sh, sl, WH(O_TK), WL(O_TK), btk, kt, 4, 0, 512};
        mb.s[1] = {sh, sl, WH(O_TV), WL(O_TV), btv, vt, 4, 0, 512};
        mb.n = 2;
        mma_gemm<<<dim3(8, 1), 256, GEMM_SMEM>>>(mb);
    }

    // 4) all three attentions (HMMA, fused split output)
    {
        AttnParams P;
        P.Q[0] = qkv;  P.K[0] = qkv + 512; P.V[0] = qkv + 1024;
        P.Oh[0] = aLh; P.Ol[0] = aLl; P.qs[0] = 1536; P.ks[0] = 1536; P.nk[0] = 2048;
        P.Q[1] = qc;   P.K[1] = kc;   P.V[1] = vc;
        P.Oh[1] = aCh; P.Ol[1] = aCl; P.qs[1] = 512;  P.ks[1] = 512;  P.nk[1] = 192;
        P.Q[2] = qt;   P.K[2] = kt;   P.V[2] = vt;
        P.Oh[2] = aTh; P.Ol[2] = aTl; P.qs[2] = 512;  P.ks[2] = 512;  P.nk[2] = 64;
        P.tidx = tidx;
        attn_mma<<<dim3(32, 8, 6), 256, ATTN_SMEM>>>(P);
    }

    // 5) output projections straight from split arenas, then combine
    float* buf0 = qkv;
    float* bufC = qkv + (size_t)NTOK * 512;
    float* bufT = qkv + (size_t)NTOK * 1024;
    {
        MBatch mb;
        mb.s[0] = {aLh, aLl, WH(O_LO), WL(O_LO), blo, buf0, 4, 0, 512};
        mb.s[1] = {aCh, aCl, WH(O_CO), WL(O_CO), bco, bufC, 4, 0, 512};
        mb.s[2] = {aTh, aTl, WH(O_TO), WL(O_TO), bto, bufT, 4, 0, 512};
        mb.n = 3;
        mma_gemm<<<dim3(12, 32), 256, GEMM_SMEM>>>(mb);
    }
    combine_kernel<<<NTOK * 512 / 1024, 256>>>(buf0, bufC, bufT, gatec, gatet, out);
}

// round 7
// speedup vs baseline: 4.9722x; 1.1038x over previous
#include <cuda_runtime.h>
#include <cuda_bf16.h>
#include <math.h>
#include <stdint.h>

#define S_LEN 2048
#define NTOK  4096
#define HDIM  64
#define NEGBIG -1e9f

// ===================== PTX helpers ==========================================
__device__ __forceinline__ void mma16816(float* c, const uint32_t* a,
                                         uint32_t b0, uint32_t b1) {
    asm volatile(
        "mma.sync.aligned.m16n8k16.row.col.f32.bf16.bf16.f32 "
        "{%0,%1,%2,%3}, {%4,%5,%6,%7}, {%8,%9}, {%0,%1,%2,%3};"
        : "+f"(c[0]), "+f"(c[1]), "+f"(c[2]), "+f"(c[3])
        : "r"(a[0]), "r"(a[1]), "r"(a[2]), "r"(a[3]), "r"(b0), "r"(b1));
}
__device__ __forceinline__ void ldsm_x2_t(uint32_t& r0, uint32_t& r1, uint32_t addr) {
    asm volatile("ldmatrix.sync.aligned.m8n8.x2.trans.shared.b16 {%0,%1}, [%2];"
                 : "=r"(r0), "=r"(r1) : "r"(addr));
}
__device__ __forceinline__ void ldsm_x2(uint32_t& r0, uint32_t& r1, uint32_t addr) {
    asm volatile("ldmatrix.sync.aligned.m8n8.x2.shared.b16 {%0,%1}, [%2];"
                 : "=r"(r0), "=r"(r1) : "r"(addr));
}
__device__ __forceinline__ void ldsm_x4(uint32_t* r, uint32_t addr) {
    asm volatile("ldmatrix.sync.aligned.m8n8.x4.shared.b16 {%0,%1,%2,%3}, [%4];"
                 : "=r"(r[0]), "=r"(r[1]), "=r"(r[2]), "=r"(r[3]) : "r"(addr));
}
__device__ __forceinline__ uint32_t smem_u32(const void* p) {
    uint32_t a;
    asm("{ .reg .u64 t; cvta.to.shared.u64 t, %1; cvt.u32.u64 %0, t; }"
        : "=r"(a) : "l"(p));
    return a;
}
__device__ __forceinline__ void cp16(uint32_t dst, const void* src) {
    asm volatile("cp.async.cg.shared.global [%0], [%1], 16;" :: "r"(dst), "l"(src));
}
#define CP_COMMIT() asm volatile("cp.async.commit_group;" ::: "memory")
#define CP_WAIT1()  asm volatile("cp.async.wait_group 1;" ::: "memory")
#define CP_WAIT0()  asm volatile("cp.async.wait_group 0;" ::: "memory")

// ===================== scratch ==============================================
__device__ __align__(16) float g_obuf [NTOK*1536];   // 3 out-proj fp32 buffers
__device__ __align__(16) float g_gatec[NTOK*512];
__device__ __align__(16) float g_gatet[NTOK*512];
__device__ __align__(16) float g_imp  [NTOK];
__device__ int   g_tidx [128];

// bf16 split arenas
__device__ __align__(16) __nv_bfloat16 g_xh[NTOK*512],   g_xl[NTOK*512];
__device__ __align__(16) __nv_bfloat16 g_qkvh[NTOK*1536],g_qkvl[NTOK*1536];
__device__ __align__(16) __nv_bfloat16 g_qch[NTOK*512],  g_qcl[NTOK*512];
__device__ __align__(16) __nv_bfloat16 g_qth[NTOK*512],  g_qtl[NTOK*512];
__device__ __align__(16) __nv_bfloat16 g_aLh[NTOK*512],  g_aLl[NTOK*512];
__device__ __align__(16) __nv_bfloat16 g_aCh[NTOK*512],  g_aCl[NTOK*512];
__device__ __align__(16) __nv_bfloat16 g_aTh[NTOK*512],  g_aTl[NTOK*512];
__device__ __align__(16) __nv_bfloat16 g_ch[384*512],    g_cl[384*512];
__device__ __align__(16) __nv_bfloat16 g_sh[128*512],    g_sl[128*512];
__device__ __align__(16) __nv_bfloat16 g_kch[384*512],   g_kcl[384*512];
__device__ __align__(16) __nv_bfloat16 g_vch[384*512],   g_vcl[384*512];
__device__ __align__(16) __nv_bfloat16 g_kth[128*512],   g_ktl[128*512];
__device__ __align__(16) __nv_bfloat16 g_vth[128*512],   g_vtl[128*512];
__device__ __align__(16) __nv_bfloat16 g_wh[7168*512],   g_wl[7168*512];

// ===================== converters ===========================================
__global__ __launch_bounds__(256) void conv_split_x(
    const float* __restrict__ src, __nv_bfloat16* __restrict__ hi,
    __nv_bfloat16* __restrict__ lo)
{
    size_t e = (size_t)blockIdx.x * 1024 + threadIdx.x * 4;
    float4 v = *(const float4*)(src + e);
    __nv_bfloat16 h0 = __float2bfloat16(v.x), h1 = __float2bfloat16(v.y);
    __nv_bfloat16 h2 = __float2bfloat16(v.z), h3 = __float2bfloat16(v.w);
    *(__nv_bfloat162*)(hi + e)     = __halves2bfloat162(h0, h1);
    *(__nv_bfloat162*)(hi + e + 2) = __halves2bfloat162(h2, h3);
    *(__nv_bfloat162*)(lo + e) = __halves2bfloat162(
        __float2bfloat16(v.x - __bfloat162float(h0)),
        __float2bfloat16(v.y - __bfloat162float(h1)));
    *(__nv_bfloat162*)(lo + e + 2) = __halves2bfloat162(
        __float2bfloat16(v.z - __bfloat162float(h2)),
        __float2bfloat16(v.w - __bfloat162float(h3)));
}

struct WSeg { const float* W; __nv_bfloat16* hi; __nv_bfloat16* lo; int M; int blk; };
struct WBatch { WSeg s[12]; int n; };

__global__ __launch_bounds__(256) void conv_w(WBatch bt)
{
    __shared__ float ts[32][33];
    int b = blockIdx.x, si = 0;
    while (si < bt.n - 1 && b >= bt.s[si].blk) { b -= bt.s[si].blk; si++; }
    const float* __restrict__ W = bt.s[si].W;
    const int M = bt.s[si].M;
    const int ntn = M >> 5;
    const int tk = (b / ntn) * 32, tn = (b % ntn) * 32;
    const int tx = threadIdx.x & 31, ty = threadIdx.x >> 5;
#pragma unroll
    for (int i = 0; i < 4; i++)
        ts[ty + 8 * i][tx] = W[(size_t)(tk + ty + 8 * i) * M + tn + tx];
    __syncthreads();
#pragma unroll
    for (int i = 0; i < 4; i++) {
        int n = tn + ty + 8 * i, k = tk + tx;
        float w = ts[tx][ty + 8 * i];
        __nv_bfloat16 hh = __float2bfloat16(w);
        bt.s[si].hi[(size_t)n * 512 + k] = hh;
        bt.s[si].lo[(size_t)n * 512 + k] = __float2bfloat16(w - __bfloat162float(hh));
    }
}

// ===================== HMMA GEMM v3: flattened tiles, split epilogues =======
// epi 0: fp32 store   1: sigmoid fp32   2: split hi/lo
// epi 3: split, all cols *0.125         4: split, cols<512 *0.125 (fused qkv)
struct MSeg {
    const __nv_bfloat16 *Ah, *Al, *Bh, *Bl;
    const float* bias;
    float* C; __nv_bfloat16 *Ch, *Cl;
    int tx, ty, epi, Mout;
};
struct MBatch { MSeg s[9]; int n; };

#define SSTR 40
#define ARR  (128 * SSTR)

__global__ __launch_bounds__(256, 2) void mma_gemm(MBatch bt)
{
    extern __shared__ __nv_bfloat16 gsm[];

    int t = blockIdx.x, si = 0;
    while (si < bt.n - 1 && t >= bt.s[si].tx * bt.s[si].ty) {
        t -= bt.s[si].tx * bt.s[si].ty; si++;
    }
    const MSeg sg = bt.s[si];
    const int col0 = (t % sg.tx) * 128, row0 = (t / sg.tx) * 128;
    const __nv_bfloat16* __restrict__ srcs[4] = { sg.Ah, sg.Al, sg.Bh, sg.Bl };
    const int rbase[4] = { row0, row0, col0, col0 };

    const int tid = threadIdx.x, wid = tid >> 5, lane = tid & 31;
    const int wr = wid & 3, wc = wid >> 2;
    const int lr = lane >> 2, lc = (lane & 3) * 2;

    float acc[2][8][4];
#pragma unroll
    for (int mt = 0; mt < 2; mt++)
#pragma unroll
        for (int nt = 0; nt < 8; nt++)
#pragma unroll
            for (int j = 0; j < 4; j++) acc[mt][nt][j] = 0.f;

    const int idx0 = tid * 2;
    auto load_chunk = [&](int d, int kc) {
#pragma unroll
        for (int i = 0; i < 8; i++) {
            int a = i >> 1;
            int idx = idx0 + (i & 1);
            int r = idx >> 2, cg = idx & 3;
            uint32_t dst = smem_u32(gsm + (d * 4 + a) * ARR + r * SSTR + cg * 8);
            cp16(dst, srcs[a] + (size_t)(rbase[a] + r) * 512 + kc + cg * 8);
        }
        CP_COMMIT();
    };

    const int a_row = (lane & 7) + ((lane >> 3) & 1) * 8;
    const int a_col = (lane >> 4) * 8;
    const int b_row = (lane & 7);
    const int b_col = ((lane >> 3) & 1) * 8;

    load_chunk(0, 0);

    for (int c = 0; c < 16; c++) {
        if (c + 1 < 16) { load_chunk((c + 1) & 1, (c + 1) * 32); CP_WAIT1(); }
        else            { CP_WAIT0(); }
        __syncthreads();

        const int d = c & 1;
        __nv_bfloat16* bufAh = gsm + (d * 4 + 0) * ARR;
        __nv_bfloat16* bufAl = gsm + (d * 4 + 1) * ARR;
        __nv_bfloat16* bufBh = gsm + (d * 4 + 2) * ARR;
        __nv_bfloat16* bufBl = gsm + (d * 4 + 3) * ARR;

#pragma unroll
        for (int ks = 0; ks < 2; ks++) {
            const int k0 = ks * 16;
            uint32_t af[2][2][4];
#pragma unroll
            for (int h = 0; h < 2; h++)
#pragma unroll
                for (int mt = 0; mt < 2; mt++) {
                    uint32_t addr = smem_u32((h ? bufAl : bufAh) +
                        (wr * 32 + mt * 16 + a_row) * SSTR + k0 + a_col);
                    ldsm_x4(af[h][mt], addr);
                }
#pragma unroll
            for (int nt = 0; nt < 8; nt++) {
                uint32_t bh0, bh1, bl0, bl1;
                uint32_t ah = smem_u32(bufBh + (wc * 64 + nt * 8 + b_row) * SSTR + k0 + b_col);
                uint32_t al = smem_u32(bufBl + (wc * 64 + nt * 8 + b_row) * SSTR + k0 + b_col);
                ldsm_x2(bh0, bh1, ah);
                ldsm_x2(bl0, bl1, al);
#pragma unroll
                for (int mt = 0; mt < 2; mt++) {
                    mma16816(acc[mt][nt], af[0][mt], bh0, bh1);
                    mma16816(acc[mt][nt], af[0][mt], bl0, bl1);
                    mma16816(acc[mt][nt], af[1][mt], bh0, bh1);
                }
            }
        }
        __syncthreads();
    }

    const float* __restrict__ bias = sg.bias;
    const int Mout = sg.Mout, epi = sg.epi;
#pragma unroll
    for (int mt = 0; mt < 2; mt++) {
        int r = row0 + wr * 32 + mt * 16 + lr;
#pragma unroll
        for (int nt = 0; nt < 8; nt++) {
            int c = col0 + wc * 64 + nt * 8 + lc;
            float b0 = __ldg(bias + c), b1 = __ldg(bias + c + 1);
            float v0 = acc[mt][nt][0] + b0, v1 = acc[mt][nt][1] + b1;
            float v2 = acc[mt][nt][2] + b0, v3 = acc[mt][nt][3] + b1;
            size_t o0 = (size_t)r * Mout + c;
            size_t o1 = (size_t)(r + 8) * Mout + c;
            if (epi == 0) {
                *(float2*)(sg.C + o0) = make_float2(v0, v1);
                *(float2*)(sg.C + o1) = make_float2(v2, v3);
            } else if (epi == 1) {
                *(float2*)(sg.C + o0) = make_float2(
                    1.f / (1.f + expf(-v0)), 1.f / (1.f + expf(-v1)));
                *(float2*)(sg.C + o1) = make_float2(
                    1.f / (1.f + expf(-v2)), 1.f / (1.f + expf(-v3)));
            } else {
                if (epi == 3 || (epi == 4 && c < 512)) {
                    v0 *= 0.125f; v1 *= 0.125f; v2 *= 0.125f; v3 *= 0.125f;
                }
                __nv_bfloat16 h0 = __float2bfloat16(v0), h1 = __float2bfloat16(v1);
                __nv_bfloat16 h2 = __float2bfloat16(v2), h3 = __float2bfloat16(v3);
                *(__nv_bfloat162*)(sg.Ch + o0) = __halves2bfloat162(h0, h1);
                *(__nv_bfloat162*)(sg.Ch + o1) = __halves2bfloat162(h2, h3);
                *(__nv_bfloat162*)(sg.Cl + o0) = __halves2bfloat162(
                    __float2bfloat16(v0 - __bfloat162float(h0)),
                    __float2bfloat16(v1 - __bfloat162float(h1)));
                *(__nv_bfloat162*)(sg.Cl + o1) = __halves2bfloat162(
                    __float2bfloat16(v2 - __bfloat162float(h2)),
                    __float2bfloat16(v3 - __bfloat162float(h3)));
            }
        }
    }
}

// ===================== HMMA flash attention (bf16-arena inputs) =============
#define ASTR 72
#define SST  68

struct AttnParams {
    const __nv_bfloat16 *Qh[3], *Ql[3], *Kh[3], *Kl[3], *Vh[3], *Vl[3];
    __nv_bfloat16 *Oh[3], *Ol[3];
    int qs[3], ks[3], nk[3];
    const int* tidx;
};

__global__ __launch_bounds__(256) void attn_mma(AttnParams P)
{
    extern __shared__ char dynsm[];
    __nv_bfloat16* sQh = (__nv_bfloat16*)dynsm;
    __nv_bfloat16* sQl = sQh + 64 * ASTR;
    __nv_bfloat16* sKh = sQl + 64 * ASTR;
    __nv_bfloat16* sKl = sKh + 64 * ASTR;
    __nv_bfloat16* sVh = sKl + 64 * ASTR;
    __nv_bfloat16* sVl = sVh + 64 * ASTR;
    __nv_bfloat16* sPh = sVl + 64 * ASTR;
    __nv_bfloat16* sPl = sPh + 64 * ASTR;
    float* sS  = (float*)(sPl + 64 * ASTR);
    float* sAl = sS + 64 * SST;
    float* sIL = sAl + 64;
    int*   pos = (int*)(sIL + 64);

    const int mode = blockIdx.z >> 1, b = blockIdx.z & 1;
    const int h = blockIdx.y, q0 = blockIdx.x * 64;
    const int tid = threadIdx.x, wid = tid >> 5, lane = tid & 31;
    const int wr = wid & 3, wc = wid >> 2;
    const int lr = lane >> 2, lc = (lane & 3) * 2;

    const __nv_bfloat16* Qh = P.Qh[mode]; const __nv_bfloat16* Ql = P.Ql[mode];
    const __nv_bfloat16* Kh = P.Kh[mode]; const __nv_bfloat16* Kl = P.Kl[mode];
    const __nv_bfloat16* Vh = P.Vh[mode]; const __nv_bfloat16* Vl = P.Vl[mode];
    const int qs = P.qs[mode], ks = P.ks[mode], nk = P.nk[mode];

    // Q tiles: straight bf16 copy (scale already folded in projection epilogue)
    for (int idx = tid; idx < 64 * 8; idx += 256) {
        int r = idx >> 3, d0 = (idx & 7) * 8;
        size_t g = (size_t)(b * S_LEN + q0 + r) * qs + h * HDIM + d0;
        *(uint4*)(sQh + r * ASTR + d0) = *(const uint4*)(Qh + g);
        *(uint4*)(sQl + r * ASTR + d0) = *(const uint4*)(Ql + g);
    }

    float oacc[4][4];
#pragma unroll
    for (int nt = 0; nt < 4; nt++)
#pragma unroll
        for (int j = 0; j < 4; j++) oacc[nt][j] = 0.f;

    const int row = tid >> 2, jseg = tid & 3;
    const int q = q0 + row;
    float m = -INFINITY, l = 0.f;

    int kt0 = 0, ktend = nk;
    if (mode == 0) { kt0 = (q0 > 511) ? ((q0 - 511) & ~63) : 0; ktend = q0 + 64; }

    for (int kt = kt0; kt < ktend; kt += 64) {
        __syncthreads();
        for (int idx = tid; idx < 64 * 8; idx += 256) {
            int r = idx >> 3, d0 = (idx & 7) * 8;
            size_t g = (size_t)(b * nk + kt + r) * ks + h * HDIM + d0;
            *(uint4*)(sKh + r * ASTR + d0) = *(const uint4*)(Kh + g);
            *(uint4*)(sKl + r * ASTR + d0) = *(const uint4*)(Kl + g);
            *(uint4*)(sVh + r * ASTR + d0) = *(const uint4*)(Vh + g);
            *(uint4*)(sVl + r * ASTR + d0) = *(const uint4*)(Vl + g);
        }
        if (tid < 64) {
            int j = kt + tid;
            pos[tid] = (mode == 0) ? j : (mode == 1 ? (j + 1) * 8 : P.tidx[b * 64 + j]);
        }
        __syncthreads();

        float sacc[4][4];
#pragma unroll
        for (int nt = 0; nt < 4; nt++)
#pragma unroll
            for (int j = 0; j < 4; j++) sacc[nt][j] = 0.f;
#pragma unroll
        for (int kss = 0; kss < 4; kss++) {
            const int k0 = kss * 16;
            uint32_t af[2][4];
#pragma unroll
            for (int hh = 0; hh < 2; hh++) {
                const __nv_bfloat16* base = (hh ? sQl : sQh) + (wr * 16 + lr) * ASTR + k0 + lc;
                af[hh][0] = *(const uint32_t*)(base);
                af[hh][1] = *(const uint32_t*)(base + 8 * ASTR);
                af[hh][2] = *(const uint32_t*)(base + 8);
                af[hh][3] = *(const uint32_t*)(base + 8 * ASTR + 8);
            }
#pragma unroll
            for (int nt = 0; nt < 4; nt++) {
                const __nv_bfloat16* bb = sKh + (wc * 32 + nt * 8 + lr) * ASTR + k0 + lc;
                const __nv_bfloat16* bl = sKl + (wc * 32 + nt * 8 + lr) * ASTR + k0 + lc;
                uint32_t bh0 = *(const uint32_t*)(bb);
                uint32_t bh1 = *(const uint32_t*)(bb + 8);
                uint32_t bl0 = *(const uint32_t*)(bl);
                uint32_t bl1 = *(const uint32_t*)(bl + 8);
                mma16816(sacc[nt], af[0], bh0, bh1);
                mma16816(sacc[nt], af[0], bl0, bl1);
                mma16816(sacc[nt], af[1], bh0, bh1);
            }
        }
#pragma unroll
        for (int nt = 0; nt < 4; nt++) {
            int r0 = wr * 16 + lr, c0 = wc * 32 + nt * 8 + lc;
            *(float2*)(sS + r0 * SST + c0)       = make_float2(sacc[nt][0], sacc[nt][1]);
            *(float2*)(sS + (r0 + 8) * SST + c0) = make_float2(sacc[nt][2], sacc[nt][3]);
        }
        __syncthreads();

        float s[16], mt = -INFINITY;
#pragma unroll
        for (int jj = 0; jj < 16; jj++) {
            int j = 4 * jj + jseg;
            float sv = sS[row * SST + j];
            int p = pos[j];
            bool vis = (mode == 0) ? ((unsigned)(q - p) < 512u) : (q >= p);
            if (!vis) sv = NEGBIG;
            s[jj] = sv;
            mt = fmaxf(mt, sv);
        }
        mt = fmaxf(mt, __shfl_xor_sync(0xffffffffu, mt, 1));
        mt = fmaxf(mt, __shfl_xor_sync(0xffffffffu, mt, 2));
        float m_new = fmaxf(m, mt);

        float lt = 0.f;
#pragma unroll
        for (int jj = 0; jj < 16; jj++) {
            int j = 4 * jj + jseg;
            float p = expf(s[jj] - m_new);
            lt += p;
            __nv_bfloat16 ph = __float2bfloat16(p);
            sPh[row * ASTR + j] = ph;
            sPl[row * ASTR + j] = __float2bfloat16(p - __bfloat162float(ph));
        }
        lt += __shfl_xor_sync(0xffffffffu, lt, 1);
        lt += __shfl_xor_sync(0xffffffffu, lt, 2);
        float alpha = expf(m - m_new);
        l = l * alpha + lt;
        m = m_new;
        if (jseg == 0) sAl[row] = alpha;
        __syncthreads();

        float a0 = sAl[wr * 16 + lr], a1 = sAl[wr * 16 + lr + 8];
#pragma unroll
        for (int nt = 0; nt < 4; nt++) {
            oacc[nt][0] *= a0; oacc[nt][1] *= a0;
            oacc[nt][2] *= a1; oacc[nt][3] *= a1;
        }
        const int vrow = lane & 15;
#pragma unroll
        for (int kss = 0; kss < 4; kss++) {
            const int k0 = kss * 16;
            uint32_t af[2][4];
#pragma unroll
            for (int hh = 0; hh < 2; hh++) {
                const __nv_bfloat16* base = (hh ? sPl : sPh) + (wr * 16 + lr) * ASTR + k0 + lc;
                af[hh][0] = *(const uint32_t*)(base);
                af[hh][1] = *(const uint32_t*)(base + 8 * ASTR);
                af[hh][2] = *(const uint32_t*)(base + 8);
                af[hh][3] = *(const uint32_t*)(base + 8 * ASTR + 8);
            }
#pragma unroll
            for (int nt = 0; nt < 4; nt++) {
                int n0 = wc * 32 + nt * 8;
                uint32_t bh0, bh1, bl0, bl1;
                ldsm_x2_t(bh0, bh1, smem_u32(sVh + (k0 + vrow) * ASTR + n0));
                ldsm_x2_t(bl0, bl1, smem_u32(sVl + (k0 + vrow) * ASTR + n0));
                mma16816(oacc[nt], af[0], bh0, bh1);
                mma16816(oacc[nt], af[0], bl0, bl1);
                mma16816(oacc[nt], af[1], bh0, bh1);
            }
        }
    }

    if (jseg == 0) sIL[row] = 1.f / l;
    __syncthreads();
    float i0 = sIL[wr * 16 + lr], i1 = sIL[wr * 16 + lr + 8];
    __nv_bfloat16* Oh = P.Oh[mode];
    __nv_bfloat16* Ol = P.Ol[mode];
#pragma unroll
    for (int nt = 0; nt < 4; nt++) {
        int c = h * HDIM + wc * 32 + nt * 8 + lc;
        size_t o0 = (size_t)(b * S_LEN + q0 + wr * 16 + lr) * 512 + c;
        size_t o1 = (size_t)(b * S_LEN + q0 + wr * 16 + lr + 8) * 512 + c;
        float v0 = oacc[nt][0] * i0, v1 = oacc[nt][1] * i0;
        float v2 = oacc[nt][2] * i1, v3 = oacc[nt][3] * i1;
        __nv_bfloat16 h0 = __float2bfloat16(v0), h1 = __float2bfloat16(v1);
        __nv_bfloat16 h2 = __float2bfloat16(v2), h3 = __float2bfloat16(v3);
        *(__nv_bfloat162*)(Oh + o0) = __halves2bfloat162(h0, h1);
        *(__nv_bfloat162*)(Oh + o1) = __halves2bfloat162(h2, h3);
        *(__nv_bfloat162*)(Ol + o0) = __halves2bfloat162(
            __float2bfloat16(v0 - __bfloat162float(h0)),
            __float2bfloat16(v1 - __bfloat162float(h1)));
        *(__nv_bfloat162*)(Ol + o1) = __halves2bfloat162(
            __float2bfloat16(v2 - __bfloat162float(h2)),
            __float2bfloat16(v3 - __bfloat162float(h3)));
    }
}

// ===================== small kernels (split-fused) ==========================
__global__ void pool_kernel(const float* __restrict__ x,
                            __nv_bfloat16* __restrict__ ch,
                            __nv_bfloat16* __restrict__ cl)
{
    int p = blockIdx.x % 192, b = blockIdx.x / 192;
    int d = threadIdx.x;
    float s = 0.f;
#pragma unroll
    for (int r = 0; r < 8; r++)
        s += x[(size_t)(b * S_LEN + p * 8 + r) * 512 + d];
    float v = s * 0.125f;
    __nv_bfloat16 hh = __float2bfloat16(v);
    size_t off = (size_t)(b * 192 + p) * 512 + d;
    ch[off] = hh;
    cl[off] = __float2bfloat16(v - __bfloat162float(hh));
}

__global__ void imp_kernel(const float* __restrict__ x, const float* __restrict__ W,
                           const float* __restrict__ bias, float* __restrict__ imp)
{
    int t = blockIdx.x * 8 + (threadIdx.x >> 5);
    int lane = threadIdx.x & 31;
    float s = 0.f;
    for (int i = lane; i < 512; i += 32)
        s += x[(size_t)t * 512 + i] * W[i];
#pragma unroll
    for (int off = 16; off; off >>= 1)
        s += __shfl_xor_sync(0xffffffffu, s, off);
    if (!lane) imp[t] = s + bias[0];
}

__global__ void topk_kernel(const float* __restrict__ imp, int* __restrict__ tidx)
{
    int b = blockIdx.x;
    __shared__ float v[2048];
    __shared__ float bestv[256];
    __shared__ int   besti[256];
    int tid = threadIdx.x;
    for (int i = tid; i < 2048; i += 256) v[i] = imp[b * 2048 + i];
    __syncthreads();
    for (int r = 0; r < 64; r++) {
        float bv = -INFINITY; int bi = 0x7fffffff;
        for (int i = tid; i < 2048; i += 256) {
            float xv = v[i];
            if (xv > bv) { bv = xv; bi = i; }
        }
        bestv[tid] = bv; besti[tid] = bi;
        __syncthreads();
        for (int s2 = 128; s2 > 0; s2 >>= 1) {
            if (tid < s2) {
                float xo = bestv[tid + s2]; int io = besti[tid + s2];
                if (xo > bestv[tid] || (xo == bestv[tid] && io < besti[tid])) {
                    bestv[tid] = xo; besti[tid] = io;
                }
            }
            __syncthreads();
        }
        if (tid == 0) { tidx[b * 64 + r] = besti[0]; v[besti[0]] = -INFINITY; }
        __syncthreads();
    }
}

__global__ void gather_kernel(const float* __restrict__ x, const int* __restrict__ tidx,
                              __nv_bfloat16* __restrict__ sh,
                              __nv_bfloat16* __restrict__ sl)
{
    int rowb = blockIdx.x;
    int b = rowb >> 6;
    int src = tidx[rowb];
    for (int d = threadIdx.x; d < 512; d += 256) {
        float v = x[(size_t)(b * S_LEN + src) * 512 + d];
        __nv_bfloat16 hh = __float2bfloat16(v);
        size_t off = (size_t)rowb * 512 + d;
        sh[off] = hh;
        sl[off] = __float2bfloat16(v - __bfloat162float(hh));
    }
}

__global__ void combine_kernel(const float* __restrict__ b0, const float* __restrict__ bC,
                               const float* __restrict__ bT, const float* __restrict__ gc,
                               const float* __restrict__ gt, float* __restrict__ out)
{
    int i = (blockIdx.x * 256 + threadIdx.x) * 4;
    float4 v0 = *(const float4*)(b0 + i);
    float4 vC = *(const float4*)(bC + i);
    float4 vT = *(const float4*)(bT + i);
    float4 c = *(const float4*)(gc + i);
    float4 t = *(const float4*)(gt + i);
    v0.x += c.x * vC.x + t.x * vT.x;
    v0.y += c.y * vC.y + t.y * vT.y;
    v0.z += c.z * vC.z + t.z * vT.z;
    v0.w += c.w * vC.w + t.w * vT.w;
    *(float4*)(out + i) = v0;
}

// ===================== launch ===============================================
extern "C" void kernel_launch(void* const* d_in, const int* in_sizes, int n_in,
                              void* d_out, int out_size)
{
    const float* x    = (const float*)d_in[0];
    const float* Wqkv = (const float*)d_in[1];  const float* bqkv = (const float*)d_in[2];
    const float* Wlo  = (const float*)d_in[3];  const float* blo  = (const float*)d_in[4];
    const float* Wcq  = (const float*)d_in[5];  const float* bcq  = (const float*)d_in[6];
    const float* Wck  = (const float*)d_in[7];  const float* bck  = (const float*)d_in[8];
    const float* Wcv  = (const float*)d_in[9];  const float* bcv  = (const float*)d_in[10];
    const float* Wco  = (const float*)d_in[11]; const float* bco  = (const float*)d_in[12];
    const float* Wgc  = (const float*)d_in[13]; const float* bgc  = (const float*)d_in[14];
    const float* Wimp = (const float*)d_in[15]; const float* bimp = (const float*)d_in[16];
    const float* Wtq  = (const float*)d_in[17]; const float* btq  = (const float*)d_in[18];
    const float* Wtk  = (const float*)d_in[19]; const float* btk  = (const float*)d_in[20];
    const float* Wtv  = (const float*)d_in[21]; const float* btv  = (const float*)d_in[22];
    const float* Wto  = (const float*)d_in[23]; const float* bto  = (const float*)d_in[24];
    const float* Wgt  = (const float*)d_in[25]; const float* bgt  = (const float*)d_in[26];
    float* out = (float*)d_out;

    float *obuf, *gatec, *gatet, *imp;
    int* tidx;
    __nv_bfloat16 *xh, *xl, *qkvh, *qkvl, *qch, *qcl, *qth, *qtl;
    __nv_bfloat16 *aLh, *aLl, *aCh, *aCl, *aTh, *aTl;
    __nv_bfloat16 *ch, *cl, *sh, *sl, *kch, *kcl, *vch, *vcl, *kth, *ktl, *vth, *vtl;
    __nv_bfloat16 *wh, *wl;
    cudaGetSymbolAddress((void**)&obuf,  g_obuf);
    cudaGetSymbolAddress((void**)&gatec, g_gatec);
    cudaGetSymbolAddress((void**)&gatet, g_gatet);
    cudaGetSymbolAddress((void**)&imp,   g_imp);
    cudaGetSymbolAddress((void**)&tidx,  g_tidx);
    cudaGetSymbolAddress((void**)&xh,   g_xh);   cudaGetSymbolAddress((void**)&xl,   g_xl);
    cudaGetSymbolAddress((void**)&qkvh, g_qkvh); cudaGetSymbolAddress((void**)&qkvl, g_qkvl);
    cudaGetSymbolAddress((void**)&qch,  g_qch);  cudaGetSymbolAddress((void**)&qcl,  g_qcl);
    cudaGetSymbolAddress((void**)&qth,  g_qth);  cudaGetSymbolAddress((void**)&qtl,  g_qtl);
    cudaGetSymbolAddress((void**)&aLh,  g_aLh);  cudaGetSymbolAddress((void**)&aLl,  g_aLl);
    cudaGetSymbolAddress((void**)&aCh,  g_aCh);  cudaGetSymbolAddress((void**)&aCl,  g_aCl);
    cudaGetSymbolAddress((void**)&aTh,  g_aTh);  cudaGetSymbolAddress((void**)&aTl,  g_aTl);
    cudaGetSymbolAddress((void**)&ch,   g_ch);   cudaGetSymbolAddress((void**)&cl,   g_cl);
    cudaGetSymbolAddress((void**)&sh,   g_sh);   cudaGetSymbolAddress((void**)&sl,   g_sl);
    cudaGetSymbolAddress((void**)&kch,  g_kch);  cudaGetSymbolAddress((void**)&kcl,  g_kcl);
    cudaGetSymbolAddress((void**)&vch,  g_vch);  cudaGetSymbolAddress((void**)&vcl,  g_vcl);
    cudaGetSymbolAddress((void**)&kth,  g_kth);  cudaGetSymbolAddress((void**)&ktl,  g_ktl);
    cudaGetSymbolAddress((void**)&vth,  g_vth);  cudaGetSymbolAddress((void**)&vtl,  g_vtl);
    cudaGetSymbolAddress((void**)&wh,   g_wh);   cudaGetSymbolAddress((void**)&wl,   g_wl);

    const int ATTN_SMEM = 8 * 64 * ASTR * 2 + 64 * SST * 4 + 3 * 64 * 4;
    cudaFuncSetAttribute(attn_mma, cudaFuncAttributeMaxDynamicSharedMemorySize, ATTN_SMEM);
    const int GEMM_SMEM = 2 * 4 * ARR * 2;
    cudaFuncSetAttribute(mma_gemm, cudaFuncAttributeMaxDynamicSharedMemorySize, GEMM_SMEM);

    const int O_QKV = 0,    O_LO = 1536, O_CQ = 2048, O_CK = 2560, O_CV = 3072,
              O_CO = 3584,  O_GC = 4096, O_TQ = 4608, O_TK = 5120, O_TV = 5632,
              O_TO = 6144,  O_GT = 6656;
    #define WH(o) (wh + (size_t)(o) * 512)
    #define WL(o) (wl + (size_t)(o) * 512)

    // 0) weight conversion + x split + branch prep (all only depend on inputs)
    {
        WBatch wb;
        wb.s[0]  = {Wqkv, WH(O_QKV), WL(O_QKV), 1536, 768};
        wb.s[1]  = {Wlo,  WH(O_LO),  WL(O_LO),  512, 256};
        wb.s[2]  = {Wcq,  WH(O_CQ),  WL(O_CQ),  512, 256};
        wb.s[3]  = {Wck,  WH(O_CK),  WL(O_CK),  512, 256};
        wb.s[4]  = {Wcv,  WH(O_CV),  WL(O_CV),  512, 256};
        wb.s[5]  = {Wco,  WH(O_CO),  WL(O_CO),  512, 256};
        wb.s[6]  = {Wgc,  WH(O_GC),  WL(O_GC),  512, 256};
        wb.s[7]  = {Wtq,  WH(O_TQ),  WL(O_TQ),  512, 256};
        wb.s[8]  = {Wtk,  WH(O_TK),  WL(O_TK),  512, 256};
        wb.s[9]  = {Wtv,  WH(O_TV),  WL(O_TV),  512, 256};
        wb.s[10] = {Wto,  WH(O_TO),  WL(O_TO),  512, 256};
        wb.s[11] = {Wgt,  WH(O_GT),  WL(O_GT),  512, 256};
        wb.n = 12;
        conv_w<<<768 + 11 * 256, 256>>>(wb);
    }
    conv_split_x<<<2048, 256>>>(x, xh, xl);
    pool_kernel<<<384, 512>>>(x, ch, cl);
    imp_kernel<<<512, 256>>>(x, Wimp, bimp, imp);
    topk_kernel<<<2, 256>>>(imp, tidx);
    gather_kernel<<<128, 256>>>(x, tidx, sh, sl);

    // 1) MEGA GEMM: all 9 pre-attention projections in one launch (928 tiles)
    {
        MBatch mb;
        mb.s[0] = {xh, xl, WH(O_QKV), WL(O_QKV), bqkv, nullptr, qkvh, qkvl, 12, 32, 4, 1536};
        mb.s[1] = {xh, xl, WH(O_CQ),  WL(O_CQ),  bcq,  nullptr, qch,  qcl,  4,  32, 3, 512};
        mb.s[2] = {xh, xl, WH(O_GC),  WL(O_GC),  bgc,  gatec,  nullptr, nullptr, 4, 32, 1, 512};
        mb.s[3] = {xh, xl, WH(O_TQ),  WL(O_TQ),  btq,  nullptr, qth,  qtl,  4,  32, 3, 512};
        mb.s[4] = {xh, xl, WH(O_GT),  WL(O_GT),  bgt,  gatet,  nullptr, nullptr, 4, 32, 1, 512};
        mb.s[5] = {ch, cl, WH(O_CK),  WL(O_CK),  bck,  nullptr, kch,  kcl,  4,  3,  2, 512};
        mb.s[6] = {ch, cl, WH(O_CV),  WL(O_CV),  bcv,  nullptr, vch,  vcl,  4,  3,  2, 512};
        mb.s[7] = {sh, sl, WH(O_TK),  WL(O_TK),  btk,  nullptr, kth,  ktl,  4,  1,  2, 512};
        mb.s[8] = {sh, sl, WH(O_TV),  WL(O_TV),  btv,  nullptr, vth,  vtl,  4,  1,  2, 512};
        mb.n = 9;
        mma_gemm<<<928, 256, GEMM_SMEM>>>(mb);
    }

    // 2) all three attentions (HMMA, bf16 arenas in, split arenas out)
    {
        AttnParams P;
        P.Qh[0] = qkvh;        P.Ql[0] = qkvl;
        P.Kh[0] = qkvh + 512;  P.Kl[0] = qkvl + 512;
        P.Vh[0] = qkvh + 1024; P.Vl[0] = qkvl + 1024;
        P.Oh[0] = aLh; P.Ol[0] = aLl; P.qs[0] = 1536; P.ks[0] = 1536; P.nk[0] = 2048;
        P.Qh[1] = qch; P.Ql[1] = qcl; P.Kh[1] = kch; P.Kl[1] = kcl;
        P.Vh[1] = vch; P.Vl[1] = vcl;
        P.Oh[1] = aCh; P.Ol[1] = aCl; P.qs[1] = 512; P.ks[1] = 512; P.nk[1] = 192;
        P.Qh[2] = qth; P.Ql[2] = qtl; P.Kh[2] = kth; P.Kl[2] = ktl;
        P.Vh[2] = vth; P.Vl[2] = vtl;
        P.Oh[2] = aTh; P.Ol[2] = aTl; P.qs[2] = 512; P.ks[2] = 512; P.nk[2] = 64;
        P.tidx = tidx;
        attn_mma<<<dim3(32, 8, 6), 256, ATTN_SMEM>>>(P);
    }

    // 3) output projections (one launch, 384 tiles) + combine
    float* buf0 = obuf;
    float* bufC = obuf + (size_t)NTOK * 512;
    float* bufT = obuf + (size_t)NTOK * 1024;
    {
        MBatch mb;
        mb.s[0] = {aLh, aLl, WH(O_LO), WL(O_LO), blo, buf0, nullptr, nullptr, 4, 32, 0, 512};
        mb.s[1] = {aCh, aCl, WH(O_CO), WL(O_CO), bco, bufC, nullptr, nullptr, 4, 32, 0, 512};
        mb.s[2] = {aTh, aTl, WH(O_TO), WL(O_TO), bto, bufT, nullptr, nullptr, 4, 32, 0, 512};
        mb.n = 3;
        mma_gemm<<<384, 256, GEMM_SMEM>>>(mb);
    }
    combine_kernel<<<NTOK * 512 / 1024, 256>>>(buf0, bufC, bufT, gatec, gatet, out);
}

// round 8
// speedup vs baseline: 5.1329x; 1.0323x over previous
#include <cuda_runtime.h>
#include <cuda_bf16.h>
#include <math.h>
#include <stdint.h>

#define S_LEN 2048
#define NTOK  4096
#define HDIM  64
#define NEGBIG -1e9f

// ===================== PTX helpers ==========================================
__device__ __forceinline__ void mma16816(float* c, const uint32_t* a,
                                         uint32_t b0, uint32_t b1) {
    asm volatile(
        "mma.sync.aligned.m16n8k16.row.col.f32.bf16.bf16.f32 "
        "{%0,%1,%2,%3}, {%4,%5,%6,%7}, {%8,%9}, {%0,%1,%2,%3};"
        : "+f"(c[0]), "+f"(c[1]), "+f"(c[2]), "+f"(c[3])
        : "r"(a[0]), "r"(a[1]), "r"(a[2]), "r"(a[3]), "r"(b0), "r"(b1));
}
__device__ __forceinline__ void ldsm_x2_t(uint32_t& r0, uint32_t& r1, uint32_t addr) {
    asm volatile("ldmatrix.sync.aligned.m8n8.x2.trans.shared.b16 {%0,%1}, [%2];"
                 : "=r"(r0), "=r"(r1) : "r"(addr));
}
__device__ __forceinline__ void ldsm_x2(uint32_t& r0, uint32_t& r1, uint32_t addr) {
    asm volatile("ldmatrix.sync.aligned.m8n8.x2.shared.b16 {%0,%1}, [%2];"
                 : "=r"(r0), "=r"(r1) : "r"(addr));
}
__device__ __forceinline__ void ldsm_x4(uint32_t* r, uint32_t addr) {
    asm volatile("ldmatrix.sync.aligned.m8n8.x4.shared.b16 {%0,%1,%2,%3}, [%4];"
                 : "=r"(r[0]), "=r"(r[1]), "=r"(r[2]), "=r"(r[3]) : "r"(addr));
}
__device__ __forceinline__ uint32_t smem_u32(const void* p) {
    uint32_t a;
    asm("{ .reg .u64 t; cvta.to.shared.u64 t, %1; cvt.u32.u64 %0, t; }"
        : "=r"(a) : "l"(p));
    return a;
}
__device__ __forceinline__ void cp16(uint32_t dst, const void* src) {
    asm volatile("cp.async.cg.shared.global [%0], [%1], 16;" :: "r"(dst), "l"(src));
}
#define CP_COMMIT() asm volatile("cp.async.commit_group;" ::: "memory")
#define CP_WAIT1()  asm volatile("cp.async.wait_group 1;" ::: "memory")
#define CP_WAIT0()  asm volatile("cp.async.wait_group 0;" ::: "memory")

// ===================== scratch ==============================================
__device__ __align__(16) float g_obuf [NTOK*1536];
__device__ __align__(16) float g_gatec[NTOK*512];
__device__ __align__(16) float g_gatet[NTOK*512];
__device__ __align__(16) float g_imp  [NTOK];
__device__ int   g_tidx [128];

__device__ __align__(16) __nv_bfloat16 g_xh[NTOK*512],   g_xl[NTOK*512];
__device__ __align__(16) __nv_bfloat16 g_qkvh[NTOK*1536],g_qkvl[NTOK*1536];
__device__ __align__(16) __nv_bfloat16 g_qch[NTOK*512],  g_qcl[NTOK*512];
__device__ __align__(16) __nv_bfloat16 g_qth[NTOK*512],  g_qtl[NTOK*512];
__device__ __align__(16) __nv_bfloat16 g_aLh[NTOK*512],  g_aLl[NTOK*512];
__device__ __align__(16) __nv_bfloat16 g_aCh[NTOK*512],  g_aCl[NTOK*512];
__device__ __align__(16) __nv_bfloat16 g_aTh[NTOK*512],  g_aTl[NTOK*512];
__device__ __align__(16) __nv_bfloat16 g_ch[384*512],    g_cl[384*512];
__device__ __align__(16) __nv_bfloat16 g_sh[128*512],    g_sl[128*512];
__device__ __align__(16) __nv_bfloat16 g_kch[384*512],   g_kcl[384*512];
__device__ __align__(16) __nv_bfloat16 g_vch[384*512],   g_vcl[384*512];
__device__ __align__(16) __nv_bfloat16 g_kth[128*512],   g_ktl[128*512];
__device__ __align__(16) __nv_bfloat16 g_vth[128*512],   g_vtl[128*512];
__device__ __align__(16) __nv_bfloat16 g_wh[7168*512],   g_wl[7168*512];

// ===================== fused x-prep: split + pool + imp =====================
__global__ __launch_bounds__(512) void xprep_kernel(
    const float* __restrict__ x, const float* __restrict__ Wimp,
    const float* __restrict__ bimp,
    __nv_bfloat16* __restrict__ xh, __nv_bfloat16* __restrict__ xl,
    __nv_bfloat16* __restrict__ ch, __nv_bfloat16* __restrict__ cl,
    float* __restrict__ imp)
{
    __shared__ float wred[16][8];
    const int g = blockIdx.x;          // 2 batches * 256 groups of 8 rows
    const int b = g >> 8, p = g & 255;
    const int d = threadIdx.x;
    const int lane = d & 31, wid = d >> 5;
    const float w = Wimp[d];

    float psum = 0.f, part[8];
#pragma unroll
    for (int r = 0; r < 8; r++) {
        size_t row = (size_t)(b * S_LEN + p * 8 + r);
        float v = x[row * 512 + d];
        __nv_bfloat16 hh = __float2bfloat16(v);
        xh[row * 512 + d] = hh;
        xl[row * 512 + d] = __float2bfloat16(v - __bfloat162float(hh));
        psum += v;
        part[r] = v * w;
    }
    if (p < 192) {
        float v = psum * 0.125f;
        __nv_bfloat16 hh = __float2bfloat16(v);
        size_t off = (size_t)(b * 192 + p) * 512 + d;
        ch[off] = hh;
        cl[off] = __float2bfloat16(v - __bfloat162float(hh));
    }
#pragma unroll
    for (int r = 0; r < 8; r++) {
        float t = part[r];
#pragma unroll
        for (int off = 16; off; off >>= 1)
            t += __shfl_xor_sync(0xffffffffu, t, off);
        if (!lane) wred[wid][r] = t;
    }
    __syncthreads();
    if (d < 8) {
        float s = 0.f;
#pragma unroll
        for (int ww = 0; ww < 16; ww++) s += wred[ww][d];
        imp[b * S_LEN + p * 8 + d] = s + bimp[0];
    }
}

// ===================== weight converter =====================================
struct WSeg { const float* W; __nv_bfloat16* hi; __nv_bfloat16* lo; int M; int blk; };
struct WBatch { WSeg s[12]; int n; };

__global__ __launch_bounds__(256) void conv_w(WBatch bt)
{
    __shared__ float ts[32][33];
    int b = blockIdx.x, si = 0;
    while (si < bt.n - 1 && b >= bt.s[si].blk) { b -= bt.s[si].blk; si++; }
    const float* __restrict__ W = bt.s[si].W;
    const int M = bt.s[si].M;
    const int ntn = M >> 5;
    const int tk = (b / ntn) * 32, tn = (b % ntn) * 32;
    const int tx = threadIdx.x & 31, ty = threadIdx.x >> 5;
#pragma unroll
    for (int i = 0; i < 4; i++)
        ts[ty + 8 * i][tx] = W[(size_t)(tk + ty + 8 * i) * M + tn + tx];
    __syncthreads();
#pragma unroll
    for (int i = 0; i < 4; i++) {
        int n = tn + ty + 8 * i, k = tk + tx;
        float w = ts[tx][ty + 8 * i];
        __nv_bfloat16 hh = __float2bfloat16(w);
        bt.s[si].hi[(size_t)n * 512 + k] = hh;
        bt.s[si].lo[(size_t)n * 512 + k] = __float2bfloat16(w - __bfloat162float(hh));
    }
}

// ===================== HMMA GEMM v4: product-outermost ILP ==================
struct MSeg {
    const __nv_bfloat16 *Ah, *Al, *Bh, *Bl;
    const float* bias;
    float* C; __nv_bfloat16 *Ch, *Cl;
    int tx, ty, epi, Mout;
};
struct MBatch { MSeg s[9]; int n; };

#define SSTR 40
#define ARR  (128 * SSTR)

__global__ __launch_bounds__(256, 2) void mma_gemm(MBatch bt)
{
    extern __shared__ __nv_bfloat16 gsm[];

    int t = blockIdx.x, si = 0;
    while (si < bt.n - 1 && t >= bt.s[si].tx * bt.s[si].ty) {
        t -= bt.s[si].tx * bt.s[si].ty; si++;
    }
    const MSeg sg = bt.s[si];
    const int col0 = (t % sg.tx) * 128, row0 = (t / sg.tx) * 128;
    const __nv_bfloat16* __restrict__ srcs[4] = { sg.Ah, sg.Al, sg.Bh, sg.Bl };
    const int rbase[4] = { row0, row0, col0, col0 };

    const int tid = threadIdx.x, wid = tid >> 5, lane = tid & 31;
    const int wr = wid & 3, wc = wid >> 2;
    const int lr = lane >> 2, lc = (lane & 3) * 2;

    float acc[2][8][4];
#pragma unroll
    for (int mt = 0; mt < 2; mt++)
#pragma unroll
        for (int nt = 0; nt < 8; nt++)
#pragma unroll
            for (int j = 0; j < 4; j++) acc[mt][nt][j] = 0.f;

    const int idx0 = tid * 2;
    auto load_chunk = [&](int d, int kc) {
#pragma unroll
        for (int i = 0; i < 8; i++) {
            int a = i >> 1;
            int idx = idx0 + (i & 1);
            int r = idx >> 2, cg = idx & 3;
            uint32_t dst = smem_u32(gsm + (d * 4 + a) * ARR + r * SSTR + cg * 8);
            cp16(dst, srcs[a] + (size_t)(rbase[a] + r) * 512 + kc + cg * 8);
        }
        CP_COMMIT();
    };

    const int a_row = (lane & 7) + ((lane >> 3) & 1) * 8;
    const int a_col = (lane >> 4) * 8;
    const int b_row = (lane & 7);
    const int b_col = ((lane >> 3) & 1) * 8;

    load_chunk(0, 0);

    for (int c = 0; c < 16; c++) {
        if (c + 1 < 16) { load_chunk((c + 1) & 1, (c + 1) * 32); CP_WAIT1(); }
        else            { CP_WAIT0(); }
        __syncthreads();

        const int d = c & 1;
        __nv_bfloat16* bufAh = gsm + (d * 4 + 0) * ARR;
        __nv_bfloat16* bufAl = gsm + (d * 4 + 1) * ARR;
        __nv_bfloat16* bufBh = gsm + (d * 4 + 2) * ARR;
        __nv_bfloat16* bufBl = gsm + (d * 4 + 3) * ARR;

#pragma unroll
        for (int ks = 0; ks < 2; ks++) {
            const int k0 = ks * 16;
            // A-hi fragments
            uint32_t af0[2][4];
#pragma unroll
            for (int mt = 0; mt < 2; mt++)
                ldsm_x4(af0[mt], smem_u32(bufAh + (wr * 32 + mt * 16 + a_row) * SSTR + k0 + a_col));
            // p0: Ah x Bh — hold B-hi frags for reuse in p2
            uint32_t bh[8][2];
#pragma unroll
            for (int nt = 0; nt < 8; nt++) {
                ldsm_x2(bh[nt][0], bh[nt][1],
                        smem_u32(bufBh + (wc * 64 + nt * 8 + b_row) * SSTR + k0 + b_col));
                mma16816(acc[0][nt], af0[0], bh[nt][0], bh[nt][1]);
                mma16816(acc[1][nt], af0[1], bh[nt][0], bh[nt][1]);
            }
            // p1: Ah x Bl
#pragma unroll
            for (int nt = 0; nt < 8; nt++) {
                uint32_t bl0, bl1;
                ldsm_x2(bl0, bl1,
                        smem_u32(bufBl + (wc * 64 + nt * 8 + b_row) * SSTR + k0 + b_col));
                mma16816(acc[0][nt], af0[0], bl0, bl1);
                mma16816(acc[1][nt], af0[1], bl0, bl1);
            }
            // p2: Al x Bh (reuse held frags)
            uint32_t af1[2][4];
#pragma unroll
            for (int mt = 0; mt < 2; mt++)
                ldsm_x4(af1[mt], smem_u32(bufAl + (wr * 32 + mt * 16 + a_row) * SSTR + k0 + a_col));
#pragma unroll
            for (int nt = 0; nt < 8; nt++) {
                mma16816(acc[0][nt], af1[0], bh[nt][0], bh[nt][1]);
                mma16816(acc[1][nt], af1[1], bh[nt][0], bh[nt][1]);
            }
        }
        __syncthreads();
    }

    const float* __restrict__ bias = sg.bias;
    const int Mout = sg.Mout, epi = sg.epi;
#pragma unroll
    for (int mt = 0; mt < 2; mt++) {
        int r = row0 + wr * 32 + mt * 16 + lr;
#pragma unroll
        for (int nt = 0; nt < 8; nt++) {
            int c = col0 + wc * 64 + nt * 8 + lc;
            float b0 = __ldg(bias + c), b1 = __ldg(bias + c + 1);
            float v0 = acc[mt][nt][0] + b0, v1 = acc[mt][nt][1] + b1;
            float v2 = acc[mt][nt][2] + b0, v3 = acc[mt][nt][3] + b1;
            size_t o0 = (size_t)r * Mout + c;
            size_t o1 = (size_t)(r + 8) * Mout + c;
            if (epi == 0) {
                *(float2*)(sg.C + o0) = make_float2(v0, v1);
                *(float2*)(sg.C + o1) = make_float2(v2, v3);
            } else if (epi == 1) {
                *(float2*)(sg.C + o0) = make_float2(
                    1.f / (1.f + expf(-v0)), 1.f / (1.f + expf(-v1)));
                *(float2*)(sg.C + o1) = make_float2(
                    1.f / (1.f + expf(-v2)), 1.f / (1.f + expf(-v3)));
            } else {
                if (epi == 3 || (epi == 4 && c < 512)) {
                    v0 *= 0.125f; v1 *= 0.125f; v2 *= 0.125f; v3 *= 0.125f;
                }
                __nv_bfloat16 h0 = __float2bfloat16(v0), h1 = __float2bfloat16(v1);
                __nv_bfloat16 h2 = __float2bfloat16(v2), h3 = __float2bfloat16(v3);
                *(__nv_bfloat162*)(sg.Ch + o0) = __halves2bfloat162(h0, h1);
                *(__nv_bfloat162*)(sg.Ch + o1) = __halves2bfloat162(h2, h3);
                *(__nv_bfloat162*)(sg.Cl + o0) = __halves2bfloat162(
                    __float2bfloat16(v0 - __bfloat162float(h0)),
                    __float2bfloat16(v1 - __bfloat162float(h1)));
                *(__nv_bfloat162*)(sg.Cl + o1) = __halves2bfloat162(
                    __float2bfloat16(v2 - __bfloat162float(h2)),
                    __float2bfloat16(v3 - __bfloat162float(h3)));
            }
        }
    }
}

// ===================== HMMA flash attention (ILP-reordered) =================
#define ASTR 72
#define SST  68

struct AttnParams {
    const __nv_bfloat16 *Qh[3], *Ql[3], *Kh[3], *Kl[3], *Vh[3], *Vl[3];
    __nv_bfloat16 *Oh[3], *Ol[3];
    int qs[3], ks[3], nk[3];
    const int* tidx;
};

__global__ __launch_bounds__(256) void attn_mma(AttnParams P)
{
    extern __shared__ char dynsm[];
    __nv_bfloat16* sQh = (__nv_bfloat16*)dynsm;
    __nv_bfloat16* sQl = sQh + 64 * ASTR;
    __nv_bfloat16* sKh = sQl + 64 * ASTR;
    __nv_bfloat16* sKl = sKh + 64 * ASTR;
    __nv_bfloat16* sVh = sKl + 64 * ASTR;
    __nv_bfloat16* sVl = sVh + 64 * ASTR;
    __nv_bfloat16* sPh = sVl + 64 * ASTR;
    __nv_bfloat16* sPl = sPh + 64 * ASTR;
    float* sS  = (float*)(sPl + 64 * ASTR);
    float* sAl = sS + 64 * SST;
    float* sIL = sAl + 64;
    int*   pos = (int*)(sIL + 64);

    const int mode = blockIdx.z >> 1, b = blockIdx.z & 1;
    const int h = blockIdx.y, q0 = blockIdx.x * 64;
    const int tid = threadIdx.x, wid = tid >> 5, lane = tid & 31;
    const int wr = wid & 3, wc = wid >> 2;
    const int lr = lane >> 2, lc = (lane & 3) * 2;

    const __nv_bfloat16* Qh = P.Qh[mode]; const __nv_bfloat16* Ql = P.Ql[mode];
    const __nv_bfloat16* Kh = P.Kh[mode]; const __nv_bfloat16* Kl = P.Kl[mode];
    const __nv_bfloat16* Vh = P.Vh[mode]; const __nv_bfloat16* Vl = P.Vl[mode];
    const int qs = P.qs[mode], ks = P.ks[mode], nk = P.nk[mode];

    for (int idx = tid; idx < 64 * 8; idx += 256) {
        int r = idx >> 3, d0 = (idx & 7) * 8;
        size_t g = (size_t)(b * S_LEN + q0 + r) * qs + h * HDIM + d0;
        *(uint4*)(sQh + r * ASTR + d0) = *(const uint4*)(Qh + g);
        *(uint4*)(sQl + r * ASTR + d0) = *(const uint4*)(Ql + g);
    }

    float oacc[4][4];
#pragma unroll
    for (int nt = 0; nt < 4; nt++)
#pragma unroll
        for (int j = 0; j < 4; j++) oacc[nt][j] = 0.f;

    const int row = tid >> 2, jseg = tid & 3;
    const int q = q0 + row;
    float m = -INFINITY, l = 0.f;

    int kt0 = 0, ktend = nk;
    if (mode == 0) { kt0 = (q0 > 511) ? ((q0 - 511) & ~63) : 0; ktend = q0 + 64; }

    for (int kt = kt0; kt < ktend; kt += 64) {
        __syncthreads();
        for (int idx = tid; idx < 64 * 8; idx += 256) {
            int r = idx >> 3, d0 = (idx & 7) * 8;
            size_t g = (size_t)(b * nk + kt + r) * ks + h * HDIM + d0;
            *(uint4*)(sKh + r * ASTR + d0) = *(const uint4*)(Kh + g);
            *(uint4*)(sKl + r * ASTR + d0) = *(const uint4*)(Kl + g);
            *(uint4*)(sVh + r * ASTR + d0) = *(const uint4*)(Vh + g);
            *(uint4*)(sVl + r * ASTR + d0) = *(const uint4*)(Vl + g);
        }
        if (tid < 64) {
            int j = kt + tid;
            pos[tid] = (mode == 0) ? j : (mode == 1 ? (j + 1) * 8 : P.tidx[b * 64 + j]);
        }
        __syncthreads();

        // ---- S = Q K^T, product-outermost ----
        float sacc[4][4];
#pragma unroll
        for (int nt = 0; nt < 4; nt++)
#pragma unroll
            for (int j = 0; j < 4; j++) sacc[nt][j] = 0.f;
#pragma unroll
        for (int kss = 0; kss < 4; kss++) {
            const int k0 = kss * 16;
            uint32_t qf0[4];
            {
                const __nv_bfloat16* base = sQh + (wr * 16 + lr) * ASTR + k0 + lc;
                qf0[0] = *(const uint32_t*)(base);
                qf0[1] = *(const uint32_t*)(base + 8 * ASTR);
                qf0[2] = *(const uint32_t*)(base + 8);
                qf0[3] = *(const uint32_t*)(base + 8 * ASTR + 8);
            }
            uint32_t kh[4][2], kl[4][2];
#pragma unroll
            for (int nt = 0; nt < 4; nt++) {
                const __nv_bfloat16* bb = sKh + (wc * 32 + nt * 8 + lr) * ASTR + k0 + lc;
                const __nv_bfloat16* bl = sKl + (wc * 32 + nt * 8 + lr) * ASTR + k0 + lc;
                kh[nt][0] = *(const uint32_t*)(bb);
                kh[nt][1] = *(const uint32_t*)(bb + 8);
                kl[nt][0] = *(const uint32_t*)(bl);
                kl[nt][1] = *(const uint32_t*)(bl + 8);
            }
#pragma unroll
            for (int nt = 0; nt < 4; nt++)
                mma16816(sacc[nt], qf0, kh[nt][0], kh[nt][1]);
#pragma unroll
            for (int nt = 0; nt < 4; nt++)
                mma16816(sacc[nt], qf0, kl[nt][0], kl[nt][1]);
            uint32_t qf1[4];
            {
                const __nv_bfloat16* base = sQl + (wr * 16 + lr) * ASTR + k0 + lc;
                qf1[0] = *(const uint32_t*)(base);
                qf1[1] = *(const uint32_t*)(base + 8 * ASTR);
                qf1[2] = *(const uint32_t*)(base + 8);
                qf1[3] = *(const uint32_t*)(base + 8 * ASTR + 8);
            }
#pragma unroll
            for (int nt = 0; nt < 4; nt++)
                mma16816(sacc[nt], qf1, kh[nt][0], kh[nt][1]);
        }
#pragma unroll
        for (int nt = 0; nt < 4; nt++) {
            int r0 = wr * 16 + lr, c0 = wc * 32 + nt * 8 + lc;
            *(float2*)(sS + r0 * SST + c0)       = make_float2(sacc[nt][0], sacc[nt][1]);
            *(float2*)(sS + (r0 + 8) * SST + c0) = make_float2(sacc[nt][2], sacc[nt][3]);
        }
        __syncthreads();

        float s[16], mt = -INFINITY;
#pragma unroll
        for (int jj = 0; jj < 16; jj++) {
            int j = 4 * jj + jseg;
            float sv = sS[row * SST + j];
            int p = pos[j];
            bool vis = (mode == 0) ? ((unsigned)(q - p) < 512u) : (q >= p);
            if (!vis) sv = NEGBIG;
            s[jj] = sv;
            mt = fmaxf(mt, sv);
        }
        mt = fmaxf(mt, __shfl_xor_sync(0xffffffffu, mt, 1));
        mt = fmaxf(mt, __shfl_xor_sync(0xffffffffu, mt, 2));
        float m_new = fmaxf(m, mt);

        float lt = 0.f;
#pragma unroll
        for (int jj = 0; jj < 16; jj++) {
            int j = 4 * jj + jseg;
            float p = expf(s[jj] - m_new);
            lt += p;
            __nv_bfloat16 ph = __float2bfloat16(p);
            sPh[row * ASTR + j] = ph;
            sPl[row * ASTR + j] = __float2bfloat16(p - __bfloat162float(ph));
        }
        lt += __shfl_xor_sync(0xffffffffu, lt, 1);
        lt += __shfl_xor_sync(0xffffffffu, lt, 2);
        float alpha = expf(m - m_new);
        l = l * alpha + lt;
        m = m_new;
        if (jseg == 0) sAl[row] = alpha;
        __syncthreads();

        float a0 = sAl[wr * 16 + lr], a1 = sAl[wr * 16 + lr + 8];
#pragma unroll
        for (int nt = 0; nt < 4; nt++) {
            oacc[nt][0] *= a0; oacc[nt][1] *= a0;
            oacc[nt][2] *= a1; oacc[nt][3] *= a1;
        }
        // ---- O += P V, product-outermost ----
        const int vrow = lane & 15;
#pragma unroll
        for (int kss = 0; kss < 4; kss++) {
            const int k0 = kss * 16;
            uint32_t pf0[4];
            {
                const __nv_bfloat16* base = sPh + (wr * 16 + lr) * ASTR + k0 + lc;
                pf0[0] = *(const uint32_t*)(base);
                pf0[1] = *(const uint32_t*)(base + 8 * ASTR);
                pf0[2] = *(const uint32_t*)(base + 8);
                pf0[3] = *(const uint32_t*)(base + 8 * ASTR + 8);
            }
            uint32_t vh[4][2], vl[4][2];
#pragma unroll
            for (int nt = 0; nt < 4; nt++) {
                int n0 = wc * 32 + nt * 8;
                ldsm_x2_t(vh[nt][0], vh[nt][1], smem_u32(sVh + (k0 + vrow) * ASTR + n0));
                ldsm_x2_t(vl[nt][0], vl[nt][1], smem_u32(sVl + (k0 + vrow) * ASTR + n0));
            }
#pragma unroll
            for (int nt = 0; nt < 4; nt++)
                mma16816(oacc[nt], pf0, vh[nt][0], vh[nt][1]);
#pragma unroll
            for (int nt = 0; nt < 4; nt++)
                mma16816(oacc[nt], pf0, vl[nt][0], vl[nt][1]);
            uint32_t pf1[4];
            {
                const __nv_bfloat16* base = sPl + (wr * 16 + lr) * ASTR + k0 + lc;
                pf1[0] = *(const uint32_t*)(base);
                pf1[1] = *(const uint32_t*)(base + 8 * ASTR);
                pf1[2] = *(const uint32_t*)(base + 8);
                pf1[3] = *(const uint32_t*)(base + 8 * ASTR + 8);
            }
#pragma unroll
            for (int nt = 0; nt < 4; nt++)
                mma16816(oacc[nt], pf1, vh[nt][0], vh[nt][1]);
        }
    }

    if (jseg == 0) sIL[row] = 1.f / l;
    __syncthreads();
    float i0 = sIL[wr * 16 + lr], i1 = sIL[wr * 16 + lr + 8];
    __nv_bfloat16* Oh = P.Oh[mode];
    __nv_bfloat16* Ol = P.Ol[mode];
#pragma unroll
    for (int nt = 0; nt < 4; nt++) {
        int c = h * HDIM + wc * 32 + nt * 8 + lc;
        size_t o0 = (size_t)(b * S_LEN + q0 + wr * 16 + lr) * 512 + c;
        size_t o1 = (size_t)(b * S_LEN + q0 + wr * 16 + lr + 8) * 512 + c;
        float v0 = oacc[nt][0] * i0, v1 = oacc[nt][1] * i0;
        float v2 = oacc[nt][2] * i1, v3 = oacc[nt][3] * i1;
        __nv_bfloat16 h0 = __float2bfloat16(v0), h1 = __float2bfloat16(v1);
        __nv_bfloat16 h2 = __float2bfloat16(v2), h3 = __float2bfloat16(v3);
        *(__nv_bfloat162*)(Oh + o0) = __halves2bfloat162(h0, h1);
        *(__nv_bfloat162*)(Oh + o1) = __halves2bfloat162(h2, h3);
        *(__nv_bfloat162*)(Ol + o0) = __halves2bfloat162(
            __float2bfloat16(v0 - __bfloat162float(h0)),
            __float2bfloat16(v1 - __bfloat162float(h1)));
        *(__nv_bfloat162*)(Ol + o1) = __halves2bfloat162(
            __float2bfloat16(v2 - __bfloat162float(h2)),
            __float2bfloat16(v3 - __bfloat162float(h3)));
    }
}

// ===================== small kernels ========================================
__global__ void topk_kernel(const float* __restrict__ imp, int* __restrict__ tidx)
{
    int b = blockIdx.x;
    __shared__ float v[2048];
    __shared__ float bestv[256];
    __shared__ int   besti[256];
    int tid = threadIdx.x;
    for (int i = tid; i < 2048; i += 256) v[i] = imp[b * 2048 + i];
    __syncthreads();
    for (int r = 0; r < 64; r++) {
        float bv = -INFINITY; int bi = 0x7fffffff;
        for (int i = tid; i < 2048; i += 256) {
            float xv = v[i];
            if (xv > bv) { bv = xv; bi = i; }
        }
        bestv[tid] = bv; besti[tid] = bi;
        __syncthreads();
        for (int s2 = 128; s2 > 0; s2 >>= 1) {
            if (tid < s2) {
                float xo = bestv[tid + s2]; int io = besti[tid + s2];
                if (xo > bestv[tid] || (xo == bestv[tid] && io < besti[tid])) {
                    bestv[tid] = xo; besti[tid] = io;
                }
            }
            __syncthreads();
        }
        if (tid == 0) { tidx[b * 64 + r] = besti[0]; v[besti[0]] = -INFINITY; }
        __syncthreads();
    }
}

__global__ void gather_kernel(const float* __restrict__ x, const int* __restrict__ tidx,
                              __nv_bfloat16* __restrict__ sh,
                              __nv_bfloat16* __restrict__ sl)
{
    int rowb = blockIdx.x;
    int b = rowb >> 6;
    int src = tidx[rowb];
    for (int d = threadIdx.x; d < 512; d += 256) {
        float v = x[(size_t)(b * S_LEN + src) * 512 + d];
        __nv_bfloat16 hh = __float2bfloat16(v);
        size_t off = (size_t)rowb * 512 + d;
        sh[off] = hh;
        sl[off] = __float2bfloat16(v - __bfloat162float(hh));
    }
}

__global__ void combine_kernel(const float* __restrict__ b0, const float* __restrict__ bC,
                               const float* __restrict__ bT, const float* __restrict__ gc,
                               const float* __restrict__ gt, float* __restrict__ out)
{
    int i = (blockIdx.x * 256 + threadIdx.x) * 4;
    float4 v0 = *(const float4*)(b0 + i);
    float4 vC = *(const float4*)(bC + i);
    float4 vT = *(const float4*)(bT + i);
    float4 c = *(const float4*)(gc + i);
    float4 t = *(const float4*)(gt + i);
    v0.x += c.x * vC.x + t.x * vT.x;
    v0.y += c.y * vC.y + t.y * vT.y;
    v0.z += c.z * vC.z + t.z * vT.z;
    v0.w += c.w * vC.w + t.w * vT.w;
    *(float4*)(out + i) = v0;
}

// ===================== launch ===============================================
extern "C" void kernel_launch(void* const* d_in, const int* in_sizes, int n_in,
                              void* d_out, int out_size)
{
    const float* x    = (const float*)d_in[0];
    const float* Wqkv = (const float*)d_in[1];  const float* bqkv = (const float*)d_in[2];
    const float* Wlo  = (const float*)d_in[3];  const float* blo  = (const float*)d_in[4];
    const float* Wcq  = (const float*)d_in[5];  const float* bcq  = (const float*)d_in[6];
    const float* Wck  = (const float*)d_in[7];  const float* bck  = (const float*)d_in[8];
    const float* Wcv  = (const float*)d_in[9];  const float* bcv  = (const float*)d_in[10];
    const float* Wco  = (const float*)d_in[11]; const float* bco  = (const float*)d_in[12];
    const float* Wgc  = (const float*)d_in[13]; const float* bgc  = (const float*)d_in[14];
    const float* Wimp = (const float*)d_in[15]; const float* bimp = (const float*)d_in[16];
    const float* Wtq  = (const float*)d_in[17]; const float* btq  = (const float*)d_in[18];
    const float* Wtk  = (const float*)d_in[19]; const float* btk  = (const float*)d_in[20];
    const float* Wtv  = (const float*)d_in[21]; const float* btv  = (const float*)d_in[22];
    const float* Wto  = (const float*)d_in[23]; const float* bto  = (const float*)d_in[24];
    const float* Wgt  = (const float*)d_in[25]; const float* bgt  = (const float*)d_in[26];
    float* out = (float*)d_out;

    float *obuf, *gatec, *gatet, *imp;
    int* tidx;
    __nv_bfloat16 *xh, *xl, *qkvh, *qkvl, *qch, *qcl, *qth, *qtl;
    __nv_bfloat16 *aLh, *aLl, *aCh, *aCl, *aTh, *aTl;
    __nv_bfloat16 *ch, *cl, *sh, *sl, *kch, *kcl, *vch, *vcl, *kth, *ktl, *vth, *vtl;
    __nv_bfloat16 *wh, *wl;
    cudaGetSymbolAddress((void**)&obuf,  g_obuf);
    cudaGetSymbolAddress((void**)&gatec, g_gatec);
    cudaGetSymbolAddress((void**)&gatet, g_gatet);
    cudaGetSymbolAddress((void**)&imp,   g_imp);
    cudaGetSymbolAddress((void**)&tidx,  g_tidx);
    cudaGetSymbolAddress((void**)&xh,   g_xh);   cudaGetSymbolAddress((void**)&xl,   g_xl);
    cudaGetSymbolAddress((void**)&qkvh, g_qkvh); cudaGetSymbolAddress((void**)&qkvl, g_qkvl);
    cudaGetSymbolAddress((void**)&qch,  g_qch);  cudaGetSymbolAddress((void**)&qcl,  g_qcl);
    cudaGetSymbolAddress((void**)&qth,  g_qth);  cudaGetSymbolAddress((void**)&qtl,  g_qtl);
    cudaGetSymbolAddress((void**)&aLh,  g_aLh);  cudaGetSymbolAddress((void**)&aLl,  g_aLl);
    cudaGetSymbolAddress((void**)&aCh,  g_aCh);  cudaGetSymbolAddress((void**)&aCl,  g_aCl);
    cudaGetSymbolAddress((void**)&aTh,  g_aTh);  cudaGetSymbolAddress((void**)&aTl,  g_aTl);
    cudaGetSymbolAddress((void**)&ch,   g_ch);   cudaGetSymbolAddress((void**)&cl,   g_cl);
    cudaGetSymbolAddress((void**)&sh,   g_sh);   cudaGetSymbolAddress((void**)&sl,   g_sl);
    cudaGetSymbolAddress((void**)&kch,  g_kch);  cudaGetSymbolAddress((void**)&kcl,  g_kcl);
    cudaGetSymbolAddress((void**)&vch,  g_vch);  cudaGetSymbolAddress((void**)&vcl,  g_vcl);
    cudaGetSymbolAddress((void**)&kth,  g_kth);  cudaGetSymbolAddress((void**)&ktl,  g_ktl);
    cudaGetSymbolAddress((void**)&vth,  g_vth);  cudaGetSymbolAddress((void**)&vtl,  g_vtl);
    cudaGetSymbolAddress((void**)&wh,   g_wh);   cudaGetSymbolAddress((void**)&wl,   g_wl);

    const int ATTN_SMEM = 8 * 64 * ASTR * 2 + 64 * SST * 4 + 3 * 64 * 4;
    cudaFuncSetAttribute(attn_mma, cudaFuncAttributeMaxDynamicSharedMemorySize, ATTN_SMEM);
    const int GEMM_SMEM = 2 * 4 * ARR * 2;
    cudaFuncSetAttribute(mma_gemm, cudaFuncAttributeMaxDynamicSharedMemorySize, GEMM_SMEM);

    const int O_QKV = 0,    O_LO = 1536, O_CQ = 2048, O_CK = 2560, O_CV = 3072,
              O_CO = 3584,  O_GC = 4096, O_TQ = 4608, O_TK = 5120, O_TV = 5632,
              O_TO = 6144,  O_GT = 6656;
    #define WH(o) (wh + (size_t)(o) * 512)
    #define WL(o) (wl + (size_t)(o) * 512)

    // 0) weight conversion + fused x prep + topk branch prep
    {
        WBatch wb;
        wb.s[0]  = {Wqkv, WH(O_QKV), WL(O_QKV), 1536, 768};
        wb.s[1]  = {Wlo,  WH(O_LO),  WL(O_LO),  512, 256};
        wb.s[2]  = {Wcq,  WH(O_CQ),  WL(O_CQ),  512, 256};
        wb.s[3]  = {Wck,  WH(O_CK),  WL(O_CK),  512, 256};
        wb.s[4]  = {Wcv,  WH(O_CV),  WL(O_CV),  512, 256};
        wb.s[5]  = {Wco,  WH(O_CO),  WL(O_CO),  512, 256};
        wb.s[6]  = {Wgc,  WH(O_GC),  WL(O_GC),  512, 256};
        wb.s[7]  = {Wtq,  WH(O_TQ),  WL(O_TQ),  512, 256};
        wb.s[8]  = {Wtk,  WH(O_TK),  WL(O_TK),  512, 256};
        wb.s[9]  = {Wtv,  WH(O_TV),  WL(O_TV),  512, 256};
        wb.s[10] = {Wto,  WH(O_TO),  WL(O_TO),  512, 256};
        wb.s[11] = {Wgt,  WH(O_GT),  WL(O_GT),  512, 256};
        wb.n = 12;
        conv_w<<<768 + 11 * 256, 256>>>(wb);
    }
    xprep_kernel<<<512, 512>>>(x, Wimp, bimp, xh, xl, ch, cl, imp);
    topk_kernel<<<2, 256>>>(imp, tidx);
    gather_kernel<<<128, 256>>>(x, tidx, sh, sl);

    // 1) MEGA GEMM: all 9 pre-attention projections (928 tiles)
    {
        MBatch mb;
        mb.s[0] = {xh, xl, WH(O_QKV), WL(O_QKV), bqkv, nullptr, qkvh, qkvl, 12, 32, 4, 1536};
        mb.s[1] = {xh, xl, WH(O_CQ),  WL(O_CQ),  bcq,  nullptr, qch,  qcl,  4,  32, 3, 512};
        mb.s[2] = {xh, xl, WH(O_GC),  WL(O_GC),  bgc,  gatec,  nullptr, nullptr, 4, 32, 1, 512};
        mb.s[3] = {xh, xl, WH(O_TQ),  WL(O_TQ),  btq,  nullptr, qth,  qtl,  4,  32, 3, 512};
        mb.s[4] = {xh, xl, WH(O_GT),  WL(O_GT),  bgt,  gatet,  nullptr, nullptr, 4, 32, 1, 512};
        mb.s[5] = {ch, cl, WH(O_CK),  WL(O_CK),  bck,  nullptr, kch,  kcl,  4,  3,  2, 512};
        mb.s[6] = {ch, cl, WH(O_CV),  WL(O_CV),  bcv,  nullptr, vch,  vcl,  4,  3,  2, 512};
        mb.s[7] = {sh, sl, WH(O_TK),  WL(O_TK),  btk,  nullptr, kth,  ktl,  4,  1,  2, 512};
        mb.s[8] = {sh, sl, WH(O_TV),  WL(O_TV),  btv,  nullptr, vth,  vtl,  4,  1,  2, 512};
        mb.n = 9;
        mma_gemm<<<928, 256, GEMM_SMEM>>>(mb);
    }

    // 2) attentions
    {
        AttnParams P;
        P.Qh[0] = qkvh;        P.Ql[0] = qkvl;
        P.Kh[0] = qkvh + 512;  P.Kl[0] = qkvl + 512;
        P.Vh[0] = qkvh + 1024; P.Vl[0] = qkvl + 1024;
        P.Oh[0] = aLh; P.Ol[0] = aLl; P.qs[0] = 1536; P.ks[0] = 1536; P.nk[0] = 2048;
        P.Qh[1] = qch; P.Ql[1] = qcl; P.Kh[1] = kch; P.Kl[1] = kcl;
        P.Vh[1] = vch; P.Vl[1] = vcl;
        P.Oh[1] = aCh; P.Ol[1] = aCl; P.qs[1] = 512; P.ks[1] = 512; P.nk[1] = 192;
        P.Qh[2] = qth; P.Ql[2] = qtl; P.Kh[2] = kth; P.Kl[2] = ktl;
        P.Vh[2] = vth; P.Vl[2] = vtl;
        P.Oh[2] = aTh; P.Ol[2] = aTl; P.qs[2] = 512; P.ks[2] = 512; P.nk[2] = 64;
        P.tidx = tidx;
        attn_mma<<<dim3(32, 8, 6), 256, ATTN_SMEM>>>(P);
    }

    // 3) output projections + combine
    float* buf0 = obuf;
    float* bufC = obuf + (size_t)NTOK * 512;
    float* bufT = obuf + (size_t)NTOK * 1024;
    {
        MBatch mb;
        mb.s[0] = {aLh, aLl, WH(O_LO), WL(O_LO), blo, buf0, nullptr, nullptr, 4, 32, 0, 512};
        mb.s[1] = {aCh, aCl, WH(O_CO), WL(O_CO), bco, bufC, nullptr, nullptr, 4, 32, 0, 512};
        mb.s[2] = {aTh, aTl, WH(O_TO), WL(O_TO), bto, bufT, nullptr, nullptr, 4, 32, 0, 512};
        mb.n = 3;
        mma_gemm<<<384, 256, GEMM_SMEM>>>(mb);
    }
    combine_kernel<<<NTOK * 512 / 1024, 256>>>(buf0, bufC, bufT, gatec, gatet, out);
}

// round 9
// speedup vs baseline: 5.2660x; 1.0259x over previous
#include <cuda_runtime.h>
#include <cuda_bf16.h>
#include <math.h>
#include <stdint.h>

#define S_LEN 2048
#define NTOK  4096
#define HDIM  64
#define NEGBIG -1e9f

// ===================== PTX helpers ==========================================
__device__ __forceinline__ void mma16816(float* c, const uint32_t* a,
                                         uint32_t b0, uint32_t b1) {
    asm volatile(
        "mma.sync.aligned.m16n8k16.row.col.f32.bf16.bf16.f32 "
        "{%0,%1,%2,%3}, {%4,%5,%6,%7}, {%8,%9}, {%0,%1,%2,%3};"
        : "+f"(c[0]), "+f"(c[1]), "+f"(c[2]), "+f"(c[3])
        : "r"(a[0]), "r"(a[1]), "r"(a[2]), "r"(a[3]), "r"(b0), "r"(b1));
}
__device__ __forceinline__ void ldsm_x4(uint32_t* r, uint32_t addr) {
    asm volatile("ldmatrix.sync.aligned.m8n8.x4.shared.b16 {%0,%1,%2,%3}, [%4];"
                 : "=r"(r[0]), "=r"(r[1]), "=r"(r[2]), "=r"(r[3]) : "r"(addr));
}
__device__ __forceinline__ void ldsm_x4_t(uint32_t* r, uint32_t addr) {
    asm volatile("ldmatrix.sync.aligned.m8n8.x4.trans.shared.b16 {%0,%1,%2,%3}, [%4];"
                 : "=r"(r[0]), "=r"(r[1]), "=r"(r[2]), "=r"(r[3]) : "r"(addr));
}
__device__ __forceinline__ uint32_t smem_u32(const void* p) {
    uint32_t a;
    asm("{ .reg .u64 t; cvta.to.shared.u64 t, %1; cvt.u32.u64 %0, t; }"
        : "=r"(a) : "l"(p));
    return a;
}
__device__ __forceinline__ void cp16(uint32_t dst, const void* src) {
    asm volatile("cp.async.cg.shared.global [%0], [%1], 16;" :: "r"(dst), "l"(src));
}
#define CP_COMMIT() asm volatile("cp.async.commit_group;" ::: "memory")
#define CP_WAIT0()  asm volatile("cp.async.wait_group 0;" ::: "memory")

// ===================== scratch ==============================================
__device__ __align__(16) float g_obuf [NTOK*1536];
__device__ __align__(16) float g_gatec[NTOK*512];
__device__ __align__(16) float g_gatet[NTOK*512];
__device__ __align__(16) float g_imp  [NTOK];
__device__ int   g_tidx [128];

__device__ __align__(16) __nv_bfloat16 g_xh[NTOK*512],   g_xl[NTOK*512];
__device__ __align__(16) __nv_bfloat16 g_qkvh[NTOK*1536],g_qkvl[NTOK*1536];
__device__ __align__(16) __nv_bfloat16 g_qch[NTOK*512],  g_qcl[NTOK*512];
__device__ __align__(16) __nv_bfloat16 g_qth[NTOK*512],  g_qtl[NTOK*512];
__device__ __align__(16) __nv_bfloat16 g_aLh[NTOK*512],  g_aLl[NTOK*512];
__device__ __align__(16) __nv_bfloat16 g_aCh[NTOK*512],  g_aCl[NTOK*512];
__device__ __align__(16) __nv_bfloat16 g_aTh[NTOK*512],  g_aTl[NTOK*512];
__device__ __align__(16) __nv_bfloat16 g_ch[384*512],    g_cl[384*512];
__device__ __align__(16) __nv_bfloat16 g_sh[128*512],    g_sl[128*512];
__device__ __align__(16) __nv_bfloat16 g_kch[384*512],   g_kcl[384*512];
__device__ __align__(16) __nv_bfloat16 g_vch[384*512],   g_vcl[384*512];
__device__ __align__(16) __nv_bfloat16 g_kth[128*512],   g_ktl[128*512];
__device__ __align__(16) __nv_bfloat16 g_vth[128*512],   g_vtl[128*512];
__device__ __align__(16) __nv_bfloat16 g_wh[7168*512],   g_wl[7168*512];

// ===================== fused x-prep: split + pool + imp =====================
__global__ __launch_bounds__(512) void xprep_kernel(
    const float* __restrict__ x, const float* __restrict__ Wimp,
    const float* __restrict__ bimp,
    __nv_bfloat16* __restrict__ xh, __nv_bfloat16* __restrict__ xl,
    __nv_bfloat16* __restrict__ ch, __nv_bfloat16* __restrict__ cl,
    float* __restrict__ imp)
{
    __shared__ float wred[16][8];
    const int g = blockIdx.x;
    const int b = g >> 8, p = g & 255;
    const int d = threadIdx.x;
    const int lane = d & 31, wid = d >> 5;
    const float w = Wimp[d];

    float psum = 0.f, part[8];
#pragma unroll
    for (int r = 0; r < 8; r++) {
        size_t row = (size_t)(b * S_LEN + p * 8 + r);
        float v = x[row * 512 + d];
        __nv_bfloat16 hh = __float2bfloat16(v);
        xh[row * 512 + d] = hh;
        xl[row * 512 + d] = __float2bfloat16(v - __bfloat162float(hh));
        psum += v;
        part[r] = v * w;
    }
    if (p < 192) {
        float v = psum * 0.125f;
        __nv_bfloat16 hh = __float2bfloat16(v);
        size_t off = (size_t)(b * 192 + p) * 512 + d;
        ch[off] = hh;
        cl[off] = __float2bfloat16(v - __bfloat162float(hh));
    }
#pragma unroll
    for (int r = 0; r < 8; r++) {
        float t = part[r];
#pragma unroll
        for (int off = 16; off; off >>= 1)
            t += __shfl_xor_sync(0xffffffffu, t, off);
        if (!lane) wred[wid][r] = t;
    }
    __syncthreads();
    if (d < 8) {
        float s = 0.f;
#pragma unroll
        for (int ww = 0; ww < 16; ww++) s += wred[ww][d];
        imp[b * S_LEN + p * 8 + d] = s + bimp[0];
    }
}

// ===================== weight converter =====================================
struct WSeg { const float* W; __nv_bfloat16* hi; __nv_bfloat16* lo; int M; int blk; };
struct WBatch { WSeg s[12]; int n; };

__global__ __launch_bounds__(256) void conv_w(WBatch bt)
{
    __shared__ float ts[32][33];
    int b = blockIdx.x, si = 0;
    while (si < bt.n - 1 && b >= bt.s[si].blk) { b -= bt.s[si].blk; si++; }
    const float* __restrict__ W = bt.s[si].W;
    const int M = bt.s[si].M;
    const int ntn = M >> 5;
    const int tk = (b / ntn) * 32, tn = (b % ntn) * 32;
    const int tx = threadIdx.x & 31, ty = threadIdx.x >> 5;
#pragma unroll
    for (int i = 0; i < 4; i++)
        ts[ty + 8 * i][tx] = W[(size_t)(tk + ty + 8 * i) * M + tn + tx];
    __syncthreads();
#pragma unroll
    for (int i = 0; i < 4; i++) {
        int n = tn + ty + 8 * i, k = tk + tx;
        float w = ts[tx][ty + 8 * i];
        __nv_bfloat16 hh = __float2bfloat16(w);
        bt.s[si].hi[(size_t)n * 512 + k] = hh;
        bt.s[si].lo[(size_t)n * 512 + k] = __float2bfloat16(w - __bfloat162float(hh));
    }
}

// ===================== HMMA GEMM v5: x4 ldmatrix + 1 sync/chunk =============
struct MSeg {
    const __nv_bfloat16 *Ah, *Al, *Bh, *Bl;
    const float* bias;
    float* C; __nv_bfloat16 *Ch, *Cl;
    int tx, ty, epi, Mout;
};
struct MBatch { MSeg s[9]; int n; };

#define SSTR 40
#define ARR  (128 * SSTR)

__global__ __launch_bounds__(256, 2) void mma_gemm(MBatch bt)
{
    extern __shared__ __nv_bfloat16 gsm[];

    int t = blockIdx.x, si = 0;
    while (si < bt.n - 1 && t >= bt.s[si].tx * bt.s[si].ty) {
        t -= bt.s[si].tx * bt.s[si].ty; si++;
    }
    const MSeg sg = bt.s[si];
    const int col0 = (t % sg.tx) * 128, row0 = (t / sg.tx) * 128;
    const __nv_bfloat16* __restrict__ srcs[4] = { sg.Ah, sg.Al, sg.Bh, sg.Bl };
    const int rbase[4] = { row0, row0, col0, col0 };

    const int tid = threadIdx.x, wid = tid >> 5, lane = tid & 31;
    const int wr = wid & 3, wc = wid >> 2;
    const int lr = lane >> 2, lc = (lane & 3) * 2;

    float acc[2][8][4];
#pragma unroll
    for (int mt = 0; mt < 2; mt++)
#pragma unroll
        for (int nt = 0; nt < 8; nt++)
#pragma unroll
            for (int j = 0; j < 4; j++) acc[mt][nt][j] = 0.f;

    const int idx0 = tid * 2;
    auto load_chunk = [&](int d, int kc) {
#pragma unroll
        for (int i = 0; i < 8; i++) {
            int a = i >> 1;
            int idx = idx0 + (i & 1);
            int r = idx >> 2, cg = idx & 3;
            uint32_t dst = smem_u32(gsm + (d * 4 + a) * ARR + r * SSTR + cg * 8);
            cp16(dst, srcs[a] + (size_t)(rbase[a] + r) * 512 + kc + cg * 8);
        }
        CP_COMMIT();
    };

    // x4 lane mappings
    const int a_row = (lane & 7) + ((lane >> 3) & 1) * 8;      // A / m-major
    const int a_col = (lane >> 4) * 8;
    const int b_row = (lane & 7) + ((lane >> 4) & 1) * 8;      // B pair / n-major
    const int b_col = ((lane >> 3) & 1) * 8;

    load_chunk(0, 0);

    for (int c = 0; c < 16; c++) {
        CP_WAIT0();
        __syncthreads();
        if (c + 1 < 16) load_chunk((c + 1) & 1, (c + 1) * 32);

        const int d = c & 1;
        __nv_bfloat16* bufAh = gsm + (d * 4 + 0) * ARR;
        __nv_bfloat16* bufAl = gsm + (d * 4 + 1) * ARR;
        __nv_bfloat16* bufBh = gsm + (d * 4 + 2) * ARR;
        __nv_bfloat16* bufBl = gsm + (d * 4 + 3) * ARR;

#pragma unroll
        for (int ks = 0; ks < 2; ks++) {
            const int k0 = ks * 16;
            uint32_t af0[2][4];
#pragma unroll
            for (int mt = 0; mt < 2; mt++)
                ldsm_x4(af0[mt], smem_u32(bufAh + (wr * 32 + mt * 16 + a_row) * SSTR + k0 + a_col));
            // p0: Ah x Bh — hold bh for p2 reuse
            uint32_t bh[4][4];
#pragma unroll
            for (int pr = 0; pr < 4; pr++) {
                ldsm_x4(bh[pr], smem_u32(bufBh + (wc * 64 + pr * 16 + b_row) * SSTR + k0 + b_col));
#pragma unroll
                for (int half = 0; half < 2; half++) {
                    int nt = pr * 2 + half;
                    mma16816(acc[0][nt], af0[0], bh[pr][half * 2], bh[pr][half * 2 + 1]);
                    mma16816(acc[1][nt], af0[1], bh[pr][half * 2], bh[pr][half * 2 + 1]);
                }
            }
            // p1: Ah x Bl (pairs, transient regs)
#pragma unroll
            for (int pr = 0; pr < 4; pr++) {
                uint32_t bl[4];
                ldsm_x4(bl, smem_u32(bufBl + (wc * 64 + pr * 16 + b_row) * SSTR + k0 + b_col));
#pragma unroll
                for (int half = 0; half < 2; half++) {
                    int nt = pr * 2 + half;
                    mma16816(acc[0][nt], af0[0], bl[half * 2], bl[half * 2 + 1]);
                    mma16816(acc[1][nt], af0[1], bl[half * 2], bl[half * 2 + 1]);
                }
            }
            // p2: Al x Bh
            uint32_t af1[2][4];
#pragma unroll
            for (int mt = 0; mt < 2; mt++)
                ldsm_x4(af1[mt], smem_u32(bufAl + (wr * 32 + mt * 16 + a_row) * SSTR + k0 + a_col));
#pragma unroll
            for (int pr = 0; pr < 4; pr++)
#pragma unroll
                for (int half = 0; half < 2; half++) {
                    int nt = pr * 2 + half;
                    mma16816(acc[0][nt], af1[0], bh[pr][half * 2], bh[pr][half * 2 + 1]);
                    mma16816(acc[1][nt], af1[1], bh[pr][half * 2], bh[pr][half * 2 + 1]);
                }
        }
    }

    const float* __restrict__ bias = sg.bias;
    const int Mout = sg.Mout, epi = sg.epi;
#pragma unroll
    for (int mt = 0; mt < 2; mt++) {
        int r = row0 + wr * 32 + mt * 16 + lr;
#pragma unroll
        for (int nt = 0; nt < 8; nt++) {
            int c = col0 + wc * 64 + nt * 8 + lc;
            float b0 = __ldg(bias + c), b1 = __ldg(bias + c + 1);
            float v0 = acc[mt][nt][0] + b0, v1 = acc[mt][nt][1] + b1;
            float v2 = acc[mt][nt][2] + b0, v3 = acc[mt][nt][3] + b1;
            size_t o0 = (size_t)r * Mout + c;
            size_t o1 = (size_t)(r + 8) * Mout + c;
            if (epi == 0) {
                *(float2*)(sg.C + o0) = make_float2(v0, v1);
                *(float2*)(sg.C + o1) = make_float2(v2, v3);
            } else if (epi == 1) {
                *(float2*)(sg.C + o0) = make_float2(
                    1.f / (1.f + expf(-v0)), 1.f / (1.f + expf(-v1)));
                *(float2*)(sg.C + o1) = make_float2(
                    1.f / (1.f + expf(-v2)), 1.f / (1.f + expf(-v3)));
            } else {
                if (epi == 3 || (epi == 4 && c < 512)) {
                    v0 *= 0.125f; v1 *= 0.125f; v2 *= 0.125f; v3 *= 0.125f;
                }
                __nv_bfloat16 h0 = __float2bfloat16(v0), h1 = __float2bfloat16(v1);
                __nv_bfloat16 h2 = __float2bfloat16(v2), h3 = __float2bfloat16(v3);
                *(__nv_bfloat162*)(sg.Ch + o0) = __halves2bfloat162(h0, h1);
                *(__nv_bfloat162*)(sg.Ch + o1) = __halves2bfloat162(h2, h3);
                *(__nv_bfloat162*)(sg.Cl + o0) = __halves2bfloat162(
                    __float2bfloat16(v0 - __bfloat162float(h0)),
                    __float2bfloat16(v1 - __bfloat162float(h1)));
                *(__nv_bfloat162*)(sg.Cl + o1) = __halves2bfloat162(
                    __float2bfloat16(v2 - __bfloat162float(h2)),
                    __float2bfloat16(v3 - __bfloat162float(h3)));
            }
        }
    }
}

// ===================== HMMA flash attention (x4 ldmatrix frags) =============
#define ASTR 72
#define SST  68

struct AttnParams {
    const __nv_bfloat16 *Qh[3], *Ql[3], *Kh[3], *Kl[3], *Vh[3], *Vl[3];
    __nv_bfloat16 *Oh[3], *Ol[3];
    int qs[3], ks[3], nk[3];
    const int* tidx;
};

__global__ __launch_bounds__(256) void attn_mma(AttnParams P)
{
    extern __shared__ char dynsm[];
    __nv_bfloat16* sQh = (__nv_bfloat16*)dynsm;
    __nv_bfloat16* sQl = sQh + 64 * ASTR;
    __nv_bfloat16* sKh = sQl + 64 * ASTR;
    __nv_bfloat16* sKl = sKh + 64 * ASTR;
    __nv_bfloat16* sVh = sKl + 64 * ASTR;
    __nv_bfloat16* sVl = sVh + 64 * ASTR;
    __nv_bfloat16* sPh = sVl + 64 * ASTR;
    __nv_bfloat16* sPl = sPh + 64 * ASTR;
    float* sS  = (float*)(sPl + 64 * ASTR);
    float* sAl = sS + 64 * SST;
    float* sIL = sAl + 64;
    int*   pos = (int*)(sIL + 64);

    const int mode = blockIdx.z >> 1, b = blockIdx.z & 1;
    const int h = blockIdx.y, q0 = blockIdx.x * 64;
    const int tid = threadIdx.x, wid = tid >> 5, lane = tid & 31;
    const int wr = wid & 3, wc = wid >> 2;
    const int lr = lane >> 2, lc = (lane & 3) * 2;

    // x4 lane mappings
    const int a_row = (lane & 7) + ((lane >> 3) & 1) * 8;   // Q/P (m-major)
    const int a_col = (lane >> 4) * 8;
    const int b_row = (lane & 7) + ((lane >> 4) & 1) * 8;   // K (n-major)
    const int b_col = ((lane >> 3) & 1) * 8;
    const int v_row = (lane & 7) + ((lane >> 3) & 1) * 8;   // V (k-major, trans)
    const int v_col = ((lane >> 4) & 1) * 8;

    const __nv_bfloat16* Qh = P.Qh[mode]; const __nv_bfloat16* Ql = P.Ql[mode];
    const __nv_bfloat16* Kh = P.Kh[mode]; const __nv_bfloat16* Kl = P.Kl[mode];
    const __nv_bfloat16* Vh = P.Vh[mode]; const __nv_bfloat16* Vl = P.Vl[mode];
    const int qs = P.qs[mode], ks = P.ks[mode], nk = P.nk[mode];

    for (int idx = tid; idx < 64 * 8; idx += 256) {
        int r = idx >> 3, d0 = (idx & 7) * 8;
        size_t g = (size_t)(b * S_LEN + q0 + r) * qs + h * HDIM + d0;
        *(uint4*)(sQh + r * ASTR + d0) = *(const uint4*)(Qh + g);
        *(uint4*)(sQl + r * ASTR + d0) = *(const uint4*)(Ql + g);
    }

    float oacc[4][4];
#pragma unroll
    for (int nt = 0; nt < 4; nt++)
#pragma unroll
        for (int j = 0; j < 4; j++) oacc[nt][j] = 0.f;

    const int row = tid >> 2, jseg = tid & 3;
    const int q = q0 + row;
    float m = -INFINITY, l = 0.f;

    int kt0 = 0, ktend = nk;
    if (mode == 0) { kt0 = (q0 > 511) ? ((q0 - 511) & ~63) : 0; ktend = q0 + 64; }

    for (int kt = kt0; kt < ktend; kt += 64) {
        __syncthreads();
        for (int idx = tid; idx < 64 * 8; idx += 256) {
            int r = idx >> 3, d0 = (idx & 7) * 8;
            size_t g = (size_t)(b * nk + kt + r) * ks + h * HDIM + d0;
            *(uint4*)(sKh + r * ASTR + d0) = *(const uint4*)(Kh + g);
            *(uint4*)(sKl + r * ASTR + d0) = *(const uint4*)(Kl + g);
            *(uint4*)(sVh + r * ASTR + d0) = *(const uint4*)(Vh + g);
            *(uint4*)(sVl + r * ASTR + d0) = *(const uint4*)(Vl + g);
        }
        if (tid < 64) {
            int j = kt + tid;
            pos[tid] = (mode == 0) ? j : (mode == 1 ? (j + 1) * 8 : P.tidx[b * 64 + j]);
        }
        __syncthreads();

        // ---- S = Q K^T ----
        float sacc[4][4];
#pragma unroll
        for (int nt = 0; nt < 4; nt++)
#pragma unroll
            for (int j = 0; j < 4; j++) sacc[nt][j] = 0.f;
#pragma unroll
        for (int kss = 0; kss < 4; kss++) {
            const int k0 = kss * 16;
            uint32_t qf0[4];
            ldsm_x4(qf0, smem_u32(sQh + (wr * 16 + a_row) * ASTR + k0 + a_col));
            uint32_t kh[2][4];
#pragma unroll
            for (int pr = 0; pr < 2; pr++)
                ldsm_x4(kh[pr], smem_u32(sKh + (wc * 32 + pr * 16 + b_row) * ASTR + k0 + b_col));
#pragma unroll
            for (int pr = 0; pr < 2; pr++)
#pragma unroll
                for (int half = 0; half < 2; half++)
                    mma16816(sacc[pr * 2 + half], qf0, kh[pr][half * 2], kh[pr][half * 2 + 1]);
#pragma unroll
            for (int pr = 0; pr < 2; pr++) {
                uint32_t kl[4];
                ldsm_x4(kl, smem_u32(sKl + (wc * 32 + pr * 16 + b_row) * ASTR + k0 + b_col));
#pragma unroll
                for (int half = 0; half < 2; half++)
                    mma16816(sacc[pr * 2 + half], qf0, kl[half * 2], kl[half * 2 + 1]);
            }
            uint32_t qf1[4];
            ldsm_x4(qf1, smem_u32(sQl + (wr * 16 + a_row) * ASTR + k0 + a_col));
#pragma unroll
            for (int pr = 0; pr < 2; pr++)
#pragma unroll
                for (int half = 0; half < 2; half++)
                    mma16816(sacc[pr * 2 + half], qf1, kh[pr][half * 2], kh[pr][half * 2 + 1]);
        }
#pragma unroll
        for (int nt = 0; nt < 4; nt++) {
            int r0 = wr * 16 + lr, c0 = wc * 32 + nt * 8 + lc;
            *(float2*)(sS + r0 * SST + c0)       = make_float2(sacc[nt][0], sacc[nt][1]);
            *(float2*)(sS + (r0 + 8) * SST + c0) = make_float2(sacc[nt][2], sacc[nt][3]);
        }
        __syncthreads();

        float s[16], mt = -INFINITY;
#pragma unroll
        for (int jj = 0; jj < 16; jj++) {
            int j = 4 * jj + jseg;
            float sv = sS[row * SST + j];
            int p = pos[j];
            bool vis = (mode == 0) ? ((unsigned)(q - p) < 512u) : (q >= p);
            if (!vis) sv = NEGBIG;
            s[jj] = sv;
            mt = fmaxf(mt, sv);
        }
        mt = fmaxf(mt, __shfl_xor_sync(0xffffffffu, mt, 1));
        mt = fmaxf(mt, __shfl_xor_sync(0xffffffffu, mt, 2));
        float m_new = fmaxf(m, mt);

        float lt = 0.f;
#pragma unroll
        for (int jj = 0; jj < 16; jj++) {
            int j = 4 * jj + jseg;
            float p = expf(s[jj] - m_new);
            lt += p;
            __nv_bfloat16 ph = __float2bfloat16(p);
            sPh[row * ASTR + j] = ph;
            sPl[row * ASTR + j] = __float2bfloat16(p - __bfloat162float(ph));
        }
        lt += __shfl_xor_sync(0xffffffffu, lt, 1);
        lt += __shfl_xor_sync(0xffffffffu, lt, 2);
        float alpha = expf(m - m_new);
        l = l * alpha + lt;
        m = m_new;
        if (jseg == 0) sAl[row] = alpha;
        __syncthreads();

        float a0 = sAl[wr * 16 + lr], a1 = sAl[wr * 16 + lr + 8];
#pragma unroll
        for (int nt = 0; nt < 4; nt++) {
            oacc[nt][0] *= a0; oacc[nt][1] *= a0;
            oacc[nt][2] *= a1; oacc[nt][3] *= a1;
        }
        // ---- O += P V ----
#pragma unroll
        for (int kss = 0; kss < 4; kss++) {
            const int k0 = kss * 16;
            uint32_t pf0[4];
            ldsm_x4(pf0, smem_u32(sPh + (wr * 16 + a_row) * ASTR + k0 + a_col));
            uint32_t vh[2][4];
#pragma unroll
            for (int pr = 0; pr < 2; pr++)
                ldsm_x4_t(vh[pr], smem_u32(sVh + (k0 + v_row) * ASTR + wc * 32 + pr * 16 + v_col));
#pragma unroll
            for (int pr = 0; pr < 2; pr++)
#pragma unroll
                for (int half = 0; half < 2; half++)
                    mma16816(oacc[pr * 2 + half], pf0, vh[pr][half * 2], vh[pr][half * 2 + 1]);
#pragma unroll
            for (int pr = 0; pr < 2; pr++) {
                uint32_t vl[4];
                ldsm_x4_t(vl, smem_u32(sVl + (k0 + v_row) * ASTR + wc * 32 + pr * 16 + v_col));
#pragma unroll
                for (int half = 0; half < 2; half++)
                    mma16816(oacc[pr * 2 + half], pf0, vl[half * 2], vl[half * 2 + 1]);
            }
            uint32_t pf1[4];
            ldsm_x4(pf1, smem_u32(sPl + (wr * 16 + a_row) * ASTR + k0 + a_col));
#pragma unroll
            for (int pr = 0; pr < 2; pr++)
#pragma unroll
                for (int half = 0; half < 2; half++)
                    mma16816(oacc[pr * 2 + half], pf1, vh[pr][half * 2], vh[pr][half * 2 + 1]);
        }
    }

    if (jseg == 0) sIL[row] = 1.f / l;
    __syncthreads();
    float i0 = sIL[wr * 16 + lr], i1 = sIL[wr * 16 + lr + 8];
    __nv_bfloat16* Oh = P.Oh[mode];
    __nv_bfloat16* Ol = P.Ol[mode];
#pragma unroll
    for (int nt = 0; nt < 4; nt++) {
        int c = h * HDIM + wc * 32 + nt * 8 + lc;
        size_t o0 = (size_t)(b * S_LEN + q0 + wr * 16 + lr) * 512 + c;
        size_t o1 = (size_t)(b * S_LEN + q0 + wr * 16 + lr + 8) * 512 + c;
        float v0 = oacc[nt][0] * i0, v1 = oacc[nt][1] * i0;
        float v2 = oacc[nt][2] * i1, v3 = oacc[nt][3] * i1;
        __nv_bfloat16 h0 = __float2bfloat16(v0), h1 = __float2bfloat16(v1);
        __nv_bfloat16 h2 = __float2bfloat16(v2), h3 = __float2bfloat16(v3);
        *(__nv_bfloat162*)(Oh + o0) = __halves2bfloat162(h0, h1);
        *(__nv_bfloat162*)(Oh + o1) = __halves2bfloat162(h2, h3);
        *(__nv_bfloat162*)(Ol + o0) = __halves2bfloat162(
            __float2bfloat16(v0 - __bfloat162float(h0)),
            __float2bfloat16(v1 - __bfloat162float(h1)));
        *(__nv_bfloat162*)(Ol + o1) = __halves2bfloat162(
            __float2bfloat16(v2 - __bfloat162float(h2)),
            __float2bfloat16(v3 - __bfloat162float(h3)));
    }
}

// ===================== small kernels ========================================
__global__ void topk_kernel(const float* __restrict__ imp, int* __restrict__ tidx)
{
    int b = blockIdx.x;
    __shared__ float v[2048];
    __shared__ float bestv[256];
    __shared__ int   besti[256];
    int tid = threadIdx.x;
    for (int i = tid; i < 2048; i += 256) v[i] = imp[b * 2048 + i];
    __syncthreads();
    for (int r = 0; r < 64; r++) {
        float bv = -INFINITY; int bi = 0x7fffffff;
        for (int i = tid; i < 2048; i += 256) {
            float xv = v[i];
            if (xv > bv) { bv = xv; bi = i; }
        }
        bestv[tid] = bv; besti[tid] = bi;
        __syncthreads();
        for (int s2 = 128; s2 > 0; s2 >>= 1) {
            if (tid < s2) {
                float xo = bestv[tid + s2]; int io = besti[tid + s2];
                if (xo > bestv[tid] || (xo == bestv[tid] && io < besti[tid])) {
                    bestv[tid] = xo; besti[tid] = io;
                }
            }
            __syncthreads();
        }
        if (tid == 0) { tidx[b * 64 + r] = besti[0]; v[besti[0]] = -INFINITY; }
        __syncthreads();
    }
}

__global__ void gather_kernel(const float* __restrict__ x, const int* __restrict__ tidx,
                              __nv_bfloat16* __restrict__ sh,
                              __nv_bfloat16* __restrict__ sl)
{
    int rowb = blockIdx.x;
    int b = rowb >> 6;
    int src = tidx[rowb];
    for (int d = threadIdx.x; d < 512; d += 256) {
        float v = x[(size_t)(b * S_LEN + src) * 512 + d];
        __nv_bfloat16 hh = __float2bfloat16(v);
        size_t off = (size_t)rowb * 512 + d;
        sh[off] = hh;
        sl[off] = __float2bfloat16(v - __bfloat162float(hh));
    }
}

__global__ void combine_kernel(const float* __restrict__ b0, const float* __restrict__ bC,
                               const float* __restrict__ bT, const float* __restrict__ gc,
                               const float* __restrict__ gt, float* __restrict__ out)
{
    int i = (blockIdx.x * 256 + threadIdx.x) * 4;
    float4 v0 = *(const float4*)(b0 + i);
    float4 vC = *(const float4*)(bC + i);
    float4 vT = *(const float4*)(bT + i);
    float4 c = *(const float4*)(gc + i);
    float4 t = *(const float4*)(gt + i);
    v0.x += c.x * vC.x + t.x * vT.x;
    v0.y += c.y * vC.y + t.y * vT.y;
    v0.z += c.z * vC.z + t.z * vT.z;
    v0.w += c.w * vC.w + t.w * vT.w;
    *(float4*)(out + i) = v0;
}

// ===================== launch ===============================================
extern "C" void kernel_launch(void* const* d_in, const int* in_sizes, int n_in,
                              void* d_out, int out_size)
{
    const float* x    = (const float*)d_in[0];
    const float* Wqkv = (const float*)d_in[1];  const float* bqkv = (const float*)d_in[2];
    const float* Wlo  = (const float*)d_in[3];  const float* blo  = (const float*)d_in[4];
    const float* Wcq  = (const float*)d_in[5];  const float* bcq  = (const float*)d_in[6];
    const float* Wck  = (const float*)d_in[7];  const float* bck  = (const float*)d_in[8];
    const float* Wcv  = (const float*)d_in[9];  const float* bcv  = (const float*)d_in[10];
    const float* Wco  = (const float*)d_in[11]; const float* bco  = (const float*)d_in[12];
    const float* Wgc  = (const float*)d_in[13]; const float* bgc  = (const float*)d_in[14];
    const float* Wimp = (const float*)d_in[15]; const float* bimp = (const float*)d_in[16];
    const float* Wtq  = (const float*)d_in[17]; const float* btq  = (const float*)d_in[18];
    const float* Wtk  = (const float*)d_in[19]; const float* btk  = (const float*)d_in[20];
    const float* Wtv  = (const float*)d_in[21]; const float* btv  = (const float*)d_in[22];
    const float* Wto  = (const float*)d_in[23]; const float* bto  = (const float*)d_in[24];
    const float* Wgt  = (const float*)d_in[25]; const float* bgt  = (const float*)d_in[26];
    float* out = (float*)d_out;

    float *obuf, *gatec, *gatet, *imp;
    int* tidx;
    __nv_bfloat16 *xh, *xl, *qkvh, *qkvl, *qch, *qcl, *qth, *qtl;
    __nv_bfloat16 *aLh, *aLl, *aCh, *aCl, *aTh, *aTl;
    __nv_bfloat16 *ch, *cl, *sh, *sl, *kch, *kcl, *vch, *vcl, *kth, *ktl, *vth, *vtl;
    __nv_bfloat16 *wh, *wl;
    cudaGetSymbolAddress((void**)&obuf,  g_obuf);
    cudaGetSymbolAddress((void**)&gatec, g_gatec);
    cudaGetSymbolAddress((void**)&gatet, g_gatet);
    cudaGetSymbolAddress((void**)&imp,   g_imp);
    cudaGetSymbolAddress((void**)&tidx,  g_tidx);
    cudaGetSymbolAddress((void**)&xh,   g_xh);   cudaGetSymbolAddress((void**)&xl,   g_xl);
    cudaGetSymbolAddress((void**)&qkvh, g_qkvh); cudaGetSymbolAddress((void**)&qkvl, g_qkvl);
    cudaGetSymbolAddress((void**)&qch,  g_qch);  cudaGetSymbolAddress((void**)&qcl,  g_qcl);
    cudaGetSymbolAddress((void**)&qth,  g_qth);  cudaGetSymbolAddress((void**)&qtl,  g_qtl);
    cudaGetSymbolAddress((void**)&aLh,  g_aLh);  cudaGetSymbolAddress((void**)&aLl,  g_aLl);
    cudaGetSymbolAddress((void**)&aCh,  g_aCh);  cudaGetSymbolAddress((void**)&aCl,  g_aCl);
    cudaGetSymbolAddress((void**)&aTh,  g_aTh);  cudaGetSymbolAddress((void**)&aTl,  g_aTl);
    cudaGetSymbolAddress((void**)&ch,   g_ch);   cudaGetSymbolAddress((void**)&cl,   g_cl);
    cudaGetSymbolAddress((void**)&sh,   g_sh);   cudaGetSymbolAddress((void**)&sl,   g_sl);
    cudaGetSymbolAddress((void**)&kch,  g_kch);  cudaGetSymbolAddress((void**)&kcl,  g_kcl);
    cudaGetSymbolAddress((void**)&vch,  g_vch);  cudaGetSymbolAddress((void**)&vcl,  g_vcl);
    cudaGetSymbolAddress((void**)&kth,  g_kth);  cudaGetSymbolAddress((void**)&ktl,  g_ktl);
    cudaGetSymbolAddress((void**)&vth,  g_vth);  cudaGetSymbolAddress((void**)&vtl,  g_vtl);
    cudaGetSymbolAddress((void**)&wh,   g_wh);   cudaGetSymbolAddress((void**)&wl,   g_wl);

    const int ATTN_SMEM = 8 * 64 * ASTR * 2 + 64 * SST * 4 + 3 * 64 * 4;
    cudaFuncSetAttribute(attn_mma, cudaFuncAttributeMaxDynamicSharedMemorySize, ATTN_SMEM);
    const int GEMM_SMEM = 2 * 4 * ARR * 2;
    cudaFuncSetAttribute(mma_gemm, cudaFuncAttributeMaxDynamicSharedMemorySize, GEMM_SMEM);

    const int O_QKV = 0,    O_LO = 1536, O_CQ = 2048, O_CK = 2560, O_CV = 3072,
              O_CO = 3584,  O_GC = 4096, O_TQ = 4608, O_TK = 5120, O_TV = 5632,
              O_TO = 6144,  O_GT = 6656;
    #define WH(o) (wh + (size_t)(o) * 512)
    #define WL(o) (wl + (size_t)(o) * 512)

    {
        WBatch wb;
        wb.s[0]  = {Wqkv, WH(O_QKV), WL(O_QKV), 1536, 768};
        wb.s[1]  = {Wlo,  WH(O_LO),  WL(O_LO),  512, 256};
        wb.s[2]  = {Wcq,  WH(O_CQ),  WL(O_CQ),  512, 256};
        wb.s[3]  = {Wck,  WH(O_CK),  WL(O_CK),  512, 256};
        wb.s[4]  = {Wcv,  WH(O_CV),  WL(O_CV),  512, 256};
        wb.s[5]  = {Wco,  WH(O_CO),  WL(O_CO),  512, 256};
        wb.s[6]  = {Wgc,  WH(O_GC),  WL(O_GC),  512, 256};
        wb.s[7]  = {Wtq,  WH(O_TQ),  WL(O_TQ),  512, 256};
        wb.s[8]  = {Wtk,  WH(O_TK),  WL(O_TK),  512, 256};
        wb.s[9]  = {Wtv,  WH(O_TV),  WL(O_TV),  512, 256};
        wb.s[10] = {Wto,  WH(O_TO),  WL(O_TO),  512, 256};
        wb.s[11] = {Wgt,  WH(O_GT),  WL(O_GT),  512, 256};
        wb.n = 12;
        conv_w<<<768 + 11 * 256, 256>>>(wb);
    }
    xprep_kernel<<<512, 512>>>(x, Wimp, bimp, xh, xl, ch, cl, imp);
    topk_kernel<<<2, 256>>>(imp, tidx);
    gather_kernel<<<128, 256>>>(x, tidx, sh, sl);

    {
        MBatch mb;
        mb.s[0] = {xh, xl, WH(O_QKV), WL(O_QKV), bqkv, nullptr, qkvh, qkvl, 12, 32, 4, 1536};
        mb.s[1] = {xh, xl, WH(O_CQ),  WL(O_CQ),  bcq,  nullptr, qch,  qcl,  4,  32, 3, 512};
        mb.s[2] = {xh, xl, WH(O_GC),  WL(O_GC),  bgc,  gatec,  nullptr, nullptr, 4, 32, 1, 512};
        mb.s[3] = {xh, xl, WH(O_TQ),  WL(O_TQ),  btq,  nullptr, qth,  qtl,  4,  32, 3, 512};
        mb.s[4] = {xh, xl, WH(O_GT),  WL(O_GT),  bgt,  gatet,  nullptr, nullptr, 4, 32, 1, 512};
        mb.s[5] = {ch, cl, WH(O_CK),  WL(O_CK),  bck,  nullptr, kch,  kcl,  4,  3,  2, 512};
        mb.s[6] = {ch, cl, WH(O_CV),  WL(O_CV),  bcv,  nullptr, vch,  vcl,  4,  3,  2, 512};
        mb.s[7] = {sh, sl, WH(O_TK),  WL(O_TK),  btk,  nullptr, kth,  ktl,  4,  1,  2, 512};
        mb.s[8] = {sh, sl, WH(O_TV),  WL(O_TV),  btv,  nullptr, vth,  vtl,  4,  1,  2, 512};
        mb.n = 9;
        mma_gemm<<<928, 256, GEMM_SMEM>>>(mb);
    }

    {
        AttnParams P;
        P.Qh[0] = qkvh;        P.Ql[0] = qkvl;
        P.Kh[0] = qkvh + 512;  P.Kl[0] = qkvl + 512;
        P.Vh[0] = qkvh + 1024; P.Vl[0] = qkvl + 1024;
        P.Oh[0] = aLh; P.Ol[0] = aLl; P.qs[0] = 1536; P.ks[0] = 1536; P.nk[0] = 2048;
        P.Qh[1] = qch; P.Ql[1] = qcl; P.Kh[1] = kch; P.Kl[1] = kcl;
        P.Vh[1] = vch; P.Vl[1] = vcl;
        P.Oh[1] = aCh; P.Ol[1] = aCl; P.qs[1] = 512; P.ks[1] = 512; P.nk[1] = 192;
        P.Qh[2] = qth; P.Ql[2] = qtl; P.Kh[2] = kth; P.Kl[2] = ktl;
        P.Vh[2] = vth; P.Vl[2] = vtl;
        P.Oh[2] = aTh; P.Ol[2] = aTl; P.qs[2] = 512; P.ks[2] = 512; P.nk[2] = 64;
        P.tidx = tidx;
        attn_mma<<<dim3(32, 8, 6), 256, ATTN_SMEM>>>(P);
    }

    float* buf0 = obuf;
    float* bufC = obuf + (size_t)NTOK * 512;
    float* bufT = obuf + (size_t)NTOK * 1024;
    {
        MBatch mb;
        mb.s[0] = {aLh, aLl, WH(O_LO), WL(O_LO), blo, buf0, nullptr, nullptr, 4, 32, 0, 512};
        mb.s[1] = {aCh, aCl, WH(O_CO), WL(O_CO), bco, bufC, nullptr, nullptr, 4, 32, 0, 512};
        mb.s[2] = {aTh, aTl, WH(O_TO), WL(O_TO), bto, bufT, nullptr, nullptr, 4, 32, 0, 512};
        mb.n = 3;
        mma_gemm<<<384, 256, GEMM_SMEM>>>(mb);
    }
    combine_kernel<<<NTOK * 512 / 1024, 256>>>(buf0, bufC, bufT, gatec, gatet, out);
}

// round 10
// speedup vs baseline: 7.0461x; 1.3380x over previous
#include <cuda_runtime.h>
#include <cuda_fp16.h>
#include <math.h>
#include <stdint.h>

#define S_LEN 2048
#define NTOK  4096
#define HDIM  64
#define NEGBIG -1e9f

// ===================== PTX helpers ==========================================
__device__ __forceinline__ void mma16816(float* c, const uint32_t* a,
                                         uint32_t b0, uint32_t b1) {
    asm volatile(
        "mma.sync.aligned.m16n8k16.row.col.f32.f16.f16.f32 "
        "{%0,%1,%2,%3}, {%4,%5,%6,%7}, {%8,%9}, {%0,%1,%2,%3};"
        : "+f"(c[0]), "+f"(c[1]), "+f"(c[2]), "+f"(c[3])
        : "r"(a[0]), "r"(a[1]), "r"(a[2]), "r"(a[3]), "r"(b0), "r"(b1));
}
__device__ __forceinline__ void ldsm_x4(uint32_t* r, uint32_t addr) {
    asm volatile("ldmatrix.sync.aligned.m8n8.x4.shared.b16 {%0,%1,%2,%3}, [%4];"
                 : "=r"(r[0]), "=r"(r[1]), "=r"(r[2]), "=r"(r[3]) : "r"(addr));
}
__device__ __forceinline__ void ldsm_x4_t(uint32_t* r, uint32_t addr) {
    asm volatile("ldmatrix.sync.aligned.m8n8.x4.trans.shared.b16 {%0,%1,%2,%3}, [%4];"
                 : "=r"(r[0]), "=r"(r[1]), "=r"(r[2]), "=r"(r[3]) : "r"(addr));
}
__device__ __forceinline__ uint32_t smem_u32(const void* p) {
    uint32_t a;
    asm("{ .reg .u64 t; cvta.to.shared.u64 t, %1; cvt.u32.u64 %0, t; }"
        : "=r"(a) : "l"(p));
    return a;
}
__device__ __forceinline__ void cp16(uint32_t dst, const void* src) {
    asm volatile("cp.async.cg.shared.global [%0], [%1], 16;" :: "r"(dst), "l"(src));
}
#define CP_COMMIT() asm volatile("cp.async.commit_group;" ::: "memory")
#define CP_WAIT0()  asm volatile("cp.async.wait_group 0;" ::: "memory")

// ===================== scratch ==============================================
__device__ __align__(16) float g_obuf [NTOK*1536];
__device__ __align__(16) float g_gatec[NTOK*512];
__device__ __align__(16) float g_gatet[NTOK*512];
__device__ __align__(16) float g_imp  [NTOK];
__device__ int   g_tidx [128];

// fp16 arenas: A-operands hi-only; B-operands hi+lo
__device__ __align__(16) __half g_xh[NTOK*512];
__device__ __align__(16) __half g_qkvh[NTOK*1536], g_qkvl[NTOK*1536];
__device__ __align__(16) __half g_qch[NTOK*512];
__device__ __align__(16) __half g_qth[NTOK*512];
__device__ __align__(16) __half g_aLh[NTOK*512];
__device__ __align__(16) __half g_aCh[NTOK*512];
__device__ __align__(16) __half g_aTh[NTOK*512];
__device__ __align__(16) __half g_ch[384*512];
__device__ __align__(16) __half g_sh[128*512];
__device__ __align__(16) __half g_kch[384*512], g_kcl[384*512];
__device__ __align__(16) __half g_vch[384*512], g_vcl[384*512];
__device__ __align__(16) __half g_kth[128*512], g_ktl[128*512];
__device__ __align__(16) __half g_vth[128*512], g_vtl[128*512];
__device__ __align__(16) __half g_wh[7168*512], g_wl[7168*512];

// ===================== fused x-prep: convert + pool + imp ===================
__global__ __launch_bounds__(512) void xprep_kernel(
    const float* __restrict__ x, const float* __restrict__ Wimp,
    const float* __restrict__ bimp,
    __half* __restrict__ xh, __half* __restrict__ ch, float* __restrict__ imp)
{
    __shared__ float wred[16][8];
    const int g = blockIdx.x;
    const int b = g >> 8, p = g & 255;
    const int d = threadIdx.x;
    const int lane = d & 31, wid = d >> 5;
    const float w = Wimp[d];

    float psum = 0.f, part[8];
#pragma unroll
    for (int r = 0; r < 8; r++) {
        size_t row = (size_t)(b * S_LEN + p * 8 + r);
        float v = x[row * 512 + d];
        xh[row * 512 + d] = __float2half(v);
        psum += v;
        part[r] = v * w;
    }
    if (p < 192) {
        size_t off = (size_t)(b * 192 + p) * 512 + d;
        ch[off] = __float2half(psum * 0.125f);
    }
#pragma unroll
    for (int r = 0; r < 8; r++) {
        float t = part[r];
#pragma unroll
        for (int off = 16; off; off >>= 1)
            t += __shfl_xor_sync(0xffffffffu, t, off);
        if (!lane) wred[wid][r] = t;
    }
    __syncthreads();
    if (d < 8) {
        float s = 0.f;
#pragma unroll
        for (int ww = 0; ww < 16; ww++) s += wred[ww][d];
        imp[b * S_LEN + p * 8 + d] = s + bimp[0];
    }
}

// ===================== weight converter (hi+lo fp16, transposed) ============
struct WSeg { const float* W; __half* hi; __half* lo; int M; int blk; };
struct WBatch { WSeg s[12]; int n; };

__global__ __launch_bounds__(256) void conv_w(WBatch bt)
{
    __shared__ float ts[32][33];
    int b = blockIdx.x, si = 0;
    while (si < bt.n - 1 && b >= bt.s[si].blk) { b -= bt.s[si].blk; si++; }
    const float* __restrict__ W = bt.s[si].W;
    const int M = bt.s[si].M;
    const int ntn = M >> 5;
    const int tk = (b / ntn) * 32, tn = (b % ntn) * 32;
    const int tx = threadIdx.x & 31, ty = threadIdx.x >> 5;
#pragma unroll
    for (int i = 0; i < 4; i++)
        ts[ty + 8 * i][tx] = W[(size_t)(tk + ty + 8 * i) * M + tn + tx];
    __syncthreads();
#pragma unroll
    for (int i = 0; i < 4; i++) {
        int n = tn + ty + 8 * i, k = tk + tx;
        float w = ts[tx][ty + 8 * i];
        __half hh = __float2half(w);
        bt.s[si].hi[(size_t)n * 512 + k] = hh;
        bt.s[si].lo[(size_t)n * 512 + k] = __float2half(w - __half2float(hh));
    }
}

// ===================== HMMA GEMM v6: fp16 2-product =========================
// epi 0: fp32   1: sigmoid fp32   2: split hi/lo   3: hi-only *0.125
// epi 4: qkv fused (cols<512 *0.125, hi+lo)
struct MSeg {
    const __half *Ah, *Bh, *Bl;
    const float* bias;
    float* C; __half *Ch, *Cl;
    int tx, ty, epi, Mout;
};
struct MBatch { MSeg s[9]; int n; };

#define SSTR 40
#define ARR  (128 * SSTR)

__global__ __launch_bounds__(256, 2) void mma_gemm(MBatch bt)
{
    extern __shared__ __half gsm[];   // [2 buf][3 arr][ARR]

    int t = blockIdx.x, si = 0;
    while (si < bt.n - 1 && t >= bt.s[si].tx * bt.s[si].ty) {
        t -= bt.s[si].tx * bt.s[si].ty; si++;
    }
    const MSeg sg = bt.s[si];
    const int col0 = (t % sg.tx) * 128, row0 = (t / sg.tx) * 128;
    const __half* __restrict__ srcs[3] = { sg.Ah, sg.Bh, sg.Bl };
    const int rbase[3] = { row0, col0, col0 };

    const int tid = threadIdx.x, wid = tid >> 5, lane = tid & 31;
    const int wr = wid & 3, wc = wid >> 2;
    const int lr = lane >> 2, lc = (lane & 3) * 2;

    float acc[2][8][4];
#pragma unroll
    for (int mt = 0; mt < 2; mt++)
#pragma unroll
        for (int nt = 0; nt < 8; nt++)
#pragma unroll
            for (int j = 0; j < 4; j++) acc[mt][nt][j] = 0.f;

    auto load_chunk = [&](int d, int kc) {
#pragma unroll
        for (int i = 0; i < 6; i++) {
            int idx = i * 256 + tid;
            int a = idx >> 9, u = idx & 511;
            int r = u >> 2, cg = u & 3;
            uint32_t dst = smem_u32(gsm + (d * 3 + a) * ARR + r * SSTR + cg * 8);
            cp16(dst, srcs[a] + (size_t)(rbase[a] + r) * 512 + kc + cg * 8);
        }
        CP_COMMIT();
    };

    const int a_row = (lane & 7) + ((lane >> 3) & 1) * 8;
    const int a_col = (lane >> 4) * 8;
    const int b_row = (lane & 7) + ((lane >> 4) & 1) * 8;
    const int b_col = ((lane >> 3) & 1) * 8;

    load_chunk(0, 0);

    for (int c = 0; c < 16; c++) {
        CP_WAIT0();
        __syncthreads();
        if (c + 1 < 16) load_chunk((c + 1) & 1, (c + 1) * 32);

        const int d = c & 1;
        __half* bufAh = gsm + (d * 3 + 0) * ARR;
        __half* bufBh = gsm + (d * 3 + 1) * ARR;
        __half* bufBl = gsm + (d * 3 + 2) * ARR;

#pragma unroll
        for (int ks = 0; ks < 2; ks++) {
            const int k0 = ks * 16;
            uint32_t af[2][4];
#pragma unroll
            for (int mt = 0; mt < 2; mt++)
                ldsm_x4(af[mt], smem_u32(bufAh + (wr * 32 + mt * 16 + a_row) * SSTR + k0 + a_col));
            // p0: Ah x Bh
#pragma unroll
            for (int pr = 0; pr < 4; pr++) {
                uint32_t bh[4];
                ldsm_x4(bh, smem_u32(bufBh + (wc * 64 + pr * 16 + b_row) * SSTR + k0 + b_col));
#pragma unroll
                for (int half = 0; half < 2; half++) {
                    int nt = pr * 2 + half;
                    mma16816(acc[0][nt], af[0], bh[half * 2], bh[half * 2 + 1]);
                    mma16816(acc[1][nt], af[1], bh[half * 2], bh[half * 2 + 1]);
                }
            }
            // p1: Ah x Bl
#pragma unroll
            for (int pr = 0; pr < 4; pr++) {
                uint32_t bl[4];
                ldsm_x4(bl, smem_u32(bufBl + (wc * 64 + pr * 16 + b_row) * SSTR + k0 + b_col));
#pragma unroll
                for (int half = 0; half < 2; half++) {
                    int nt = pr * 2 + half;
                    mma16816(acc[0][nt], af[0], bl[half * 2], bl[half * 2 + 1]);
                    mma16816(acc[1][nt], af[1], bl[half * 2], bl[half * 2 + 1]);
                }
            }
        }
    }

    const float* __restrict__ bias = sg.bias;
    const int Mout = sg.Mout, epi = sg.epi;
#pragma unroll
    for (int mt = 0; mt < 2; mt++) {
        int r = row0 + wr * 32 + mt * 16 + lr;
#pragma unroll
        for (int nt = 0; nt < 8; nt++) {
            int c = col0 + wc * 64 + nt * 8 + lc;
            float b0 = __ldg(bias + c), b1 = __ldg(bias + c + 1);
            float v0 = acc[mt][nt][0] + b0, v1 = acc[mt][nt][1] + b1;
            float v2 = acc[mt][nt][2] + b0, v3 = acc[mt][nt][3] + b1;
            size_t o0 = (size_t)r * Mout + c;
            size_t o1 = (size_t)(r + 8) * Mout + c;
            if (epi == 0) {
                *(float2*)(sg.C + o0) = make_float2(v0, v1);
                *(float2*)(sg.C + o1) = make_float2(v2, v3);
            } else if (epi == 1) {
                *(float2*)(sg.C + o0) = make_float2(
                    1.f / (1.f + expf(-v0)), 1.f / (1.f + expf(-v1)));
                *(float2*)(sg.C + o1) = make_float2(
                    1.f / (1.f + expf(-v2)), 1.f / (1.f + expf(-v3)));
            } else if (epi == 3) {
                v0 *= 0.125f; v1 *= 0.125f; v2 *= 0.125f; v3 *= 0.125f;
                *(__half2*)(sg.Ch + o0) = __halves2half2(__float2half(v0), __float2half(v1));
                *(__half2*)(sg.Ch + o1) = __halves2half2(__float2half(v2), __float2half(v3));
            } else {
                if (epi == 4 && c < 512) {
                    v0 *= 0.125f; v1 *= 0.125f; v2 *= 0.125f; v3 *= 0.125f;
                }
                __half h0 = __float2half(v0), h1 = __float2half(v1);
                __half h2 = __float2half(v2), h3 = __float2half(v3);
                *(__half2*)(sg.Ch + o0) = __halves2half2(h0, h1);
                *(__half2*)(sg.Ch + o1) = __halves2half2(h2, h3);
                *(__half2*)(sg.Cl + o0) = __halves2half2(
                    __float2half(v0 - __half2float(h0)),
                    __float2half(v1 - __half2float(h1)));
                *(__half2*)(sg.Cl + o1) = __halves2half2(
                    __float2half(v2 - __half2float(h2)),
                    __float2half(v3 - __half2float(h3)));
            }
        }
    }
}

// ===================== HMMA flash attention (fp16 2-product) ================
#define ASTR 72
#define SST  68

struct AttnParams {
    const __half *Qh[3], *Kh[3], *Kl[3], *Vh[3], *Vl[3];
    __half *Oh[3];
    int qs[3], ks[3], nk[3];
    const int* tidx;
};

__global__ __launch_bounds__(256) void attn_mma(AttnParams P)
{
    extern __shared__ char dynsm[];
    __half* sQh = (__half*)dynsm;
    __half* sKh = sQh + 64 * ASTR;
    __half* sKl = sKh + 64 * ASTR;
    __half* sVh = sKl + 64 * ASTR;
    __half* sVl = sVh + 64 * ASTR;
    __half* sPh = sVl + 64 * ASTR;
    float* sS  = (float*)(sPh + 64 * ASTR);
    float* sAl = sS + 64 * SST;
    float* sIL = sAl + 64;
    int*   pos = (int*)(sIL + 64);

    const int mode = blockIdx.z >> 1, b = blockIdx.z & 1;
    const int h = blockIdx.y, q0 = blockIdx.x * 64;
    const int tid = threadIdx.x, wid = tid >> 5, lane = tid & 31;
    const int wr = wid & 3, wc = wid >> 2;
    const int lr = lane >> 2, lc = (lane & 3) * 2;

    const int a_row = (lane & 7) + ((lane >> 3) & 1) * 8;
    const int a_col = (lane >> 4) * 8;
    const int b_row = (lane & 7) + ((lane >> 4) & 1) * 8;
    const int b_col = ((lane >> 3) & 1) * 8;
    const int v_row = (lane & 7) + ((lane >> 3) & 1) * 8;
    const int v_col = ((lane >> 4) & 1) * 8;

    const __half* Qh = P.Qh[mode];
    const __half* Kh = P.Kh[mode]; const __half* Kl = P.Kl[mode];
    const __half* Vh = P.Vh[mode]; const __half* Vl = P.Vl[mode];
    const int qs = P.qs[mode], ks = P.ks[mode], nk = P.nk[mode];

    for (int idx = tid; idx < 64 * 8; idx += 256) {
        int r = idx >> 3, d0 = (idx & 7) * 8;
        size_t g = (size_t)(b * S_LEN + q0 + r) * qs + h * HDIM + d0;
        *(uint4*)(sQh + r * ASTR + d0) = *(const uint4*)(Qh + g);
    }

    float oacc[4][4];
#pragma unroll
    for (int nt = 0; nt < 4; nt++)
#pragma unroll
        for (int j = 0; j < 4; j++) oacc[nt][j] = 0.f;

    const int row = tid >> 2, jseg = tid & 3;
    const int q = q0 + row;
    float m = -INFINITY, l = 0.f;

    int kt0 = 0, ktend = nk;
    if (mode == 0) { kt0 = (q0 > 511) ? ((q0 - 511) & ~63) : 0; ktend = q0 + 64; }

    for (int kt = kt0; kt < ktend; kt += 64) {
        __syncthreads();
        for (int idx = tid; idx < 64 * 8; idx += 256) {
            int r = idx >> 3, d0 = (idx & 7) * 8;
            size_t g = (size_t)(b * nk + kt + r) * ks + h * HDIM + d0;
            *(uint4*)(sKh + r * ASTR + d0) = *(const uint4*)(Kh + g);
            *(uint4*)(sKl + r * ASTR + d0) = *(const uint4*)(Kl + g);
            *(uint4*)(sVh + r * ASTR + d0) = *(const uint4*)(Vh + g);
            *(uint4*)(sVl + r * ASTR + d0) = *(const uint4*)(Vl + g);
        }
        if (tid < 64) {
            int j = kt + tid;
            pos[tid] = (mode == 0) ? j : (mode == 1 ? (j + 1) * 8 : P.tidx[b * 64 + j]);
        }
        __syncthreads();

        // ---- S = Q K^T ----
        float sacc[4][4];
#pragma unroll
        for (int nt = 0; nt < 4; nt++)
#pragma unroll
            for (int j = 0; j < 4; j++) sacc[nt][j] = 0.f;
#pragma unroll
        for (int kss = 0; kss < 4; kss++) {
            const int k0 = kss * 16;
            uint32_t qf[4];
            ldsm_x4(qf, smem_u32(sQh + (wr * 16 + a_row) * ASTR + k0 + a_col));
#pragma unroll
            for (int pr = 0; pr < 2; pr++) {
                uint32_t kh[4];
                ldsm_x4(kh, smem_u32(sKh + (wc * 32 + pr * 16 + b_row) * ASTR + k0 + b_col));
#pragma unroll
                for (int half = 0; half < 2; half++)
                    mma16816(sacc[pr * 2 + half], qf, kh[half * 2], kh[half * 2 + 1]);
            }
#pragma unroll
            for (int pr = 0; pr < 2; pr++) {
                uint32_t kl[4];
                ldsm_x4(kl, smem_u32(sKl + (wc * 32 + pr * 16 + b_row) * ASTR + k0 + b_col));
#pragma unroll
                for (int half = 0; half < 2; half++)
                    mma16816(sacc[pr * 2 + half], qf, kl[half * 2], kl[half * 2 + 1]);
            }
        }
#pragma unroll
        for (int nt = 0; nt < 4; nt++) {
            int r0 = wr * 16 + lr, c0 = wc * 32 + nt * 8 + lc;
            *(float2*)(sS + r0 * SST + c0)       = make_float2(sacc[nt][0], sacc[nt][1]);
            *(float2*)(sS + (r0 + 8) * SST + c0) = make_float2(sacc[nt][2], sacc[nt][3]);
        }
        __syncthreads();

        float s[16], mt = -INFINITY;
#pragma unroll
        for (int jj = 0; jj < 16; jj++) {
            int j = 4 * jj + jseg;
            float sv = sS[row * SST + j];
            int p = pos[j];
            bool vis = (mode == 0) ? ((unsigned)(q - p) < 512u) : (q >= p);
            if (!vis) sv = NEGBIG;
            s[jj] = sv;
            mt = fmaxf(mt, sv);
        }
        mt = fmaxf(mt, __shfl_xor_sync(0xffffffffu, mt, 1));
        mt = fmaxf(mt, __shfl_xor_sync(0xffffffffu, mt, 2));
        float m_new = fmaxf(m, mt);

        float lt = 0.f;
#pragma unroll
        for (int jj = 0; jj < 16; jj++) {
            int j = 4 * jj + jseg;
            float p = expf(s[jj] - m_new);
            lt += p;
            sPh[row * ASTR + j] = __float2half(p);
        }
        lt += __shfl_xor_sync(0xffffffffu, lt, 1);
        lt += __shfl_xor_sync(0xffffffffu, lt, 2);
        float alpha = expf(m - m_new);
        l = l * alpha + lt;
        m = m_new;
        if (jseg == 0) sAl[row] = alpha;
        __syncthreads();

        float a0 = sAl[wr * 16 + lr], a1 = sAl[wr * 16 + lr + 8];
#pragma unroll
        for (int nt = 0; nt < 4; nt++) {
            oacc[nt][0] *= a0; oacc[nt][1] *= a0;
            oacc[nt][2] *= a1; oacc[nt][3] *= a1;
        }
        // ---- O += P V ----
#pragma unroll
        for (int kss = 0; kss < 4; kss++) {
            const int k0 = kss * 16;
            uint32_t pf[4];
            ldsm_x4(pf, smem_u32(sPh + (wr * 16 + a_row) * ASTR + k0 + a_col));
#pragma unroll
            for (int pr = 0; pr < 2; pr++) {
                uint32_t vh[4];
                ldsm_x4_t(vh, smem_u32(sVh + (k0 + v_row) * ASTR + wc * 32 + pr * 16 + v_col));
#pragma unroll
                for (int half = 0; half < 2; half++)
                    mma16816(oacc[pr * 2 + half], pf, vh[half * 2], vh[half * 2 + 1]);
            }
#pragma unroll
            for (int pr = 0; pr < 2; pr++) {
                uint32_t vl[4];
                ldsm_x4_t(vl, smem_u32(sVl + (k0 + v_row) * ASTR + wc * 32 + pr * 16 + v_col));
#pragma unroll
                for (int half = 0; half < 2; half++)
                    mma16816(oacc[pr * 2 + half], pf, vl[half * 2], vl[half * 2 + 1]);
            }
        }
    }

    if (jseg == 0) sIL[row] = 1.f / l;
    __syncthreads();
    float i0 = sIL[wr * 16 + lr], i1 = sIL[wr * 16 + lr + 8];
    __half* Oh = P.Oh[mode];
#pragma unroll
    for (int nt = 0; nt < 4; nt++) {
        int c = h * HDIM + wc * 32 + nt * 8 + lc;
        size_t o0 = (size_t)(b * S_LEN + q0 + wr * 16 + lr) * 512 + c;
        size_t o1 = (size_t)(b * S_LEN + q0 + wr * 16 + lr + 8) * 512 + c;
        *(__half2*)(Oh + o0) = __halves2half2(
            __float2half(oacc[nt][0] * i0), __float2half(oacc[nt][1] * i0));
        *(__half2*)(Oh + o1) = __halves2half2(
            __float2half(oacc[nt][2] * i1), __float2half(oacc[nt][3] * i1));
    }
}

// ===================== small kernels ========================================
__global__ void topk_kernel(const float* __restrict__ imp, int* __restrict__ tidx)
{
    int b = blockIdx.x;
    __shared__ float v[2048];
    __shared__ float bestv[256];
    __shared__ int   besti[256];
    int tid = threadIdx.x;
    for (int i = tid; i < 2048; i += 256) v[i] = imp[b * 2048 + i];
    __syncthreads();
    for (int r = 0; r < 64; r++) {
        float bv = -INFINITY; int bi = 0x7fffffff;
        for (int i = tid; i < 2048; i += 256) {
            float xv = v[i];
            if (xv > bv) { bv = xv; bi = i; }
        }
        bestv[tid] = bv; besti[tid] = bi;
        __syncthreads();
        for (int s2 = 128; s2 > 0; s2 >>= 1) {
            if (tid < s2) {
                float xo = bestv[tid + s2]; int io = besti[tid + s2];
                if (xo > bestv[tid] || (xo == bestv[tid] && io < besti[tid])) {
                    bestv[tid] = xo; besti[tid] = io;
                }
            }
            __syncthreads();
        }
        if (tid == 0) { tidx[b * 64 + r] = besti[0]; v[besti[0]] = -INFINITY; }
        __syncthreads();
    }
}

__global__ void gather_kernel(const float* __restrict__ x, const int* __restrict__ tidx,
                              __half* __restrict__ sh)
{
    int rowb = blockIdx.x;
    int b = rowb >> 6;
    int src = tidx[rowb];
    for (int d = threadIdx.x; d < 512; d += 256)
        sh[(size_t)rowb * 512 + d] = __float2half(x[(size_t)(b * S_LEN + src) * 512 + d]);
}

__global__ void combine_kernel(const float* __restrict__ b0, const float* __restrict__ bC,
                               const float* __restrict__ bT, const float* __restrict__ gc,
                               const float* __restrict__ gt, float* __restrict__ out)
{
    int i = (blockIdx.x * 256 + threadIdx.x) * 4;
    float4 v0 = *(const float4*)(b0 + i);
    float4 vC = *(const float4*)(bC + i);
    float4 vT = *(const float4*)(bT + i);
    float4 c = *(const float4*)(gc + i);
    float4 t = *(const float4*)(gt + i);
    v0.x += c.x * vC.x + t.x * vT.x;
    v0.y += c.y * vC.y + t.y * vT.y;
    v0.z += c.z * vC.z + t.z * vT.z;
    v0.w += c.w * vC.w + t.w * vT.w;
    *(float4*)(out + i) = v0;
}

// ===================== launch ===============================================
extern "C" void kernel_launch(void* const* d_in, const int* in_sizes, int n_in,
                              void* d_out, int out_size)
{
    const float* x    = (const float*)d_in[0];
    const float* Wqkv = (const float*)d_in[1];  const float* bqkv = (const float*)d_in[2];
    const float* Wlo  = (const float*)d_in[3];  const float* blo  = (const float*)d_in[4];
    const float* Wcq  = (const float*)d_in[5];  const float* bcq  = (const float*)d_in[6];
    const float* Wck  = (const float*)d_in[7];  const float* bck  = (const float*)d_in[8];
    const float* Wcv  = (const float*)d_in[9];  const float* bcv  = (const float*)d_in[10];
    const float* Wco  = (const float*)d_in[11]; const float* bco  = (const float*)d_in[12];
    const float* Wgc  = (const float*)d_in[13]; const float* bgc  = (const float*)d_in[14];
    const float* Wimp = (const float*)d_in[15]; const float* bimp = (const float*)d_in[16];
    const float* Wtq  = (const float*)d_in[17]; const float* btq  = (const float*)d_in[18];
    const float* Wtk  = (const float*)d_in[19]; const float* btk  = (const float*)d_in[20];
    const float* Wtv  = (const float*)d_in[21]; const float* btv  = (const float*)d_in[22];
    const float* Wto  = (const float*)d_in[23]; const float* bto  = (const float*)d_in[24];
    const float* Wgt  = (const float*)d_in[25]; const float* bgt  = (const float*)d_in[26];
    float* out = (float*)d_out;

    float *obuf, *gatec, *gatet, *imp;
    int* tidx;
    __half *xh, *qkvh, *qkvl, *qch, *qth, *aLh, *aCh, *aTh;
    __half *ch, *sh, *kch, *kcl, *vch, *vcl, *kth, *ktl, *vth, *vtl, *wh, *wl;
    cudaGetSymbolAddress((void**)&obuf,  g_obuf);
    cudaGetSymbolAddress((void**)&gatec, g_gatec);
    cudaGetSymbolAddress((void**)&gatet, g_gatet);
    cudaGetSymbolAddress((void**)&imp,   g_imp);
    cudaGetSymbolAddress((void**)&tidx,  g_tidx);
    cudaGetSymbolAddress((void**)&xh,   g_xh);
    cudaGetSymbolAddress((void**)&qkvh, g_qkvh); cudaGetSymbolAddress((void**)&qkvl, g_qkvl);
    cudaGetSymbolAddress((void**)&qch,  g_qch);
    cudaGetSymbolAddress((void**)&qth,  g_qth);
    cudaGetSymbolAddress((void**)&aLh,  g_aLh);
    cudaGetSymbolAddress((void**)&aCh,  g_aCh);
    cudaGetSymbolAddress((void**)&aTh,  g_aTh);
    cudaGetSymbolAddress((void**)&ch,   g_ch);
    cudaGetSymbolAddress((void**)&sh,   g_sh);
    cudaGetSymbolAddress((void**)&kch,  g_kch);  cudaGetSymbolAddress((void**)&kcl,  g_kcl);
    cudaGetSymbolAddress((void**)&vch,  g_vch);  cudaGetSymbolAddress((void**)&vcl,  g_vcl);
    cudaGetSymbolAddress((void**)&kth,  g_kth);  cudaGetSymbolAddress((void**)&ktl,  g_ktl);
    cudaGetSymbolAddress((void**)&vth,  g_vth);  cudaGetSymbolAddress((void**)&vtl,  g_vtl);
    cudaGetSymbolAddress((void**)&wh,   g_wh);   cudaGetSymbolAddress((void**)&wl,   g_wl);

    const int ATTN_SMEM = 6 * 64 * ASTR * 2 + 64 * SST * 4 + 3 * 64 * 4;
    cudaFuncSetAttribute(attn_mma, cudaFuncAttributeMaxDynamicSharedMemorySize, ATTN_SMEM);
    const int GEMM_SMEM = 2 * 3 * ARR * 2;   // 61440
    cudaFuncSetAttribute(mma_gemm, cudaFuncAttributeMaxDynamicSharedMemorySize, GEMM_SMEM);

    const int O_QKV = 0,    O_LO = 1536, O_CQ = 2048, O_CK = 2560, O_CV = 3072,
              O_CO = 3584,  O_GC = 4096, O_TQ = 4608, O_TK = 5120, O_TV = 5632,
              O_TO = 6144,  O_GT = 6656;
    #define WH(o) (wh + (size_t)(o) * 512)
    #define WL(o) (wl + (size_t)(o) * 512)

    {
        WBatch wb;
        wb.s[0]  = {Wqkv, WH(O_QKV), WL(O_QKV), 1536, 768};
        wb.s[1]  = {Wlo,  WH(O_LO),  WL(O_LO),  512, 256};
        wb.s[2]  = {Wcq,  WH(O_CQ),  WL(O_CQ),  512, 256};
        wb.s[3]  = {Wck,  WH(O_CK),  WL(O_CK),  512, 256};
        wb.s[4]  = {Wcv,  WH(O_CV),  WL(O_CV),  512, 256};
        wb.s[5]  = {Wco,  WH(O_CO),  WL(O_CO),  512, 256};
        wb.s[6]  = {Wgc,  WH(O_GC),  WL(O_GC),  512, 256};
        wb.s[7]  = {Wtq,  WH(O_TQ),  WL(O_TQ),  512, 256};
        wb.s[8]  = {Wtk,  WH(O_TK),  WL(O_TK),  512, 256};
        wb.s[9]  = {Wtv,  WH(O_TV),  WL(O_TV),  512, 256};
        wb.s[10] = {Wto,  WH(O_TO),  WL(O_TO),  512, 256};
        wb.s[11] = {Wgt,  WH(O_GT),  WL(O_GT),  512, 256};
        wb.n = 12;
        conv_w<<<768 + 11 * 256, 256>>>(wb);
    }
    xprep_kernel<<<512, 512>>>(x, Wimp, bimp, xh, ch, imp);
    topk_kernel<<<2, 256>>>(imp, tidx);
    gather_kernel<<<128, 256>>>(x, tidx, sh);

    {
        MBatch mb;
        mb.s[0] = {xh, WH(O_QKV), WL(O_QKV), bqkv, nullptr, qkvh, qkvl, 12, 32, 4, 1536};
        mb.s[1] = {xh, WH(O_CQ),  WL(O_CQ),  bcq,  nullptr, qch,  nullptr, 4, 32, 3, 512};
        mb.s[2] = {xh, WH(O_GC),  WL(O_GC),  bgc,  gatec,  nullptr, nullptr, 4, 32, 1, 512};
        mb.s[3] = {xh, WH(O_TQ),  WL(O_TQ),  btq,  nullptr, qth,  nullptr, 4, 32, 3, 512};
        mb.s[4] = {xh, WH(O_GT),  WL(O_GT),  bgt,  gatet,  nullptr, nullptr, 4, 32, 1, 512};
        mb.s[5] = {ch, WH(O_CK),  WL(O_CK),  bck,  nullptr, kch,  kcl,  4,  3,  2, 512};
        mb.s[6] = {ch, WH(O_CV),  WL(O_CV),  bcv,  nullptr, vch,  vcl,  4,  3,  2, 512};
        mb.s[7] = {sh, WH(O_TK),  WL(O_TK),  btk,  nullptr, kth,  ktl,  4,  1,  2, 512};
        mb.s[8] = {sh, WH(O_TV),  WL(O_TV),  btv,  nullptr, vth,  vtl,  4,  1,  2, 512};
        mb.n = 9;
        mma_gemm<<<928, 256, GEMM_SMEM>>>(mb);
    }

    {
        AttnParams P;
        P.Qh[0] = qkvh;
        P.Kh[0] = qkvh + 512;  P.Kl[0] = qkvl + 512;
        P.Vh[0] = qkvh + 1024; P.Vl[0] = qkvl + 1024;
        P.Oh[0] = aLh; P.qs[0] = 1536; P.ks[0] = 1536; P.nk[0] = 2048;
        P.Qh[1] = qch; P.Kh[1] = kch; P.Kl[1] = kcl;
        P.Vh[1] = vch; P.Vl[1] = vcl;
        P.Oh[1] = aCh; P.qs[1] = 512; P.ks[1] = 512; P.nk[1] = 192;
        P.Qh[2] = qth; P.Kh[2] = kth; P.Kl[2] = ktl;
        P.Vh[2] = vth; P.Vl[2] = vtl;
        P.Oh[2] = aTh; P.qs[2] = 512; P.ks[2] = 512; P.nk[2] = 64;
        P.tidx = tidx;
        attn_mma<<<dim3(32, 8, 6), 256, ATTN_SMEM>>>(P);
    }

    float* buf0 = obuf;
    float* bufC = obuf + (size_t)NTOK * 512;
    float* bufT = obuf + (size_t)NTOK * 1024;
    {
        MBatch mb;
        mb.s[0] = {aLh, WH(O_LO), WL(O_LO), blo, buf0, nullptr, nullptr, 4, 32, 0, 512};
        mb.s[1] = {aCh, WH(O_CO), WL(O_CO), bco, bufC, nullptr, nullptr, 4, 32, 0, 512};
        mb.s[2] = {aTh, WH(O_TO), WL(O_TO), bto, bufT, nullptr, nullptr, 4, 32, 0, 512};
        mb.n = 3;
        mma_gemm<<<384, 256, GEMM_SMEM>>>(mb);
    }
    combine_kernel<<<NTOK * 512 / 1024, 256>>>(buf0, bufC, bufT, gatec, gatet, out);
}

// round 11
// speedup vs baseline: 8.6933x; 1.2338x over previous
#include <cuda_runtime.h>
#include <cuda_fp16.h>
#include <math.h>
#include <stdint.h>

#define S_LEN 2048
#define NTOK  4096
#define HDIM  64
#define NEGBIG -1e9f

// ===================== PTX helpers ==========================================
__device__ __forceinline__ void mma16816(float* c, const uint32_t* a,
                                         uint32_t b0, uint32_t b1) {
    asm volatile(
        "mma.sync.aligned.m16n8k16.row.col.f32.f16.f16.f32 "
        "{%0,%1,%2,%3}, {%4,%5,%6,%7}, {%8,%9}, {%0,%1,%2,%3};"
        : "+f"(c[0]), "+f"(c[1]), "+f"(c[2]), "+f"(c[3])
        : "r"(a[0]), "r"(a[1]), "r"(a[2]), "r"(a[3]), "r"(b0), "r"(b1));
}
__device__ __forceinline__ void ldsm_x4(uint32_t* r, uint32_t addr) {
    asm volatile("ldmatrix.sync.aligned.m8n8.x4.shared.b16 {%0,%1,%2,%3}, [%4];"
                 : "=r"(r[0]), "=r"(r[1]), "=r"(r[2]), "=r"(r[3]) : "r"(addr));
}
__device__ __forceinline__ void ldsm_x4_t(uint32_t* r, uint32_t addr) {
    asm volatile("ldmatrix.sync.aligned.m8n8.x4.trans.shared.b16 {%0,%1,%2,%3}, [%4];"
                 : "=r"(r[0]), "=r"(r[1]), "=r"(r[2]), "=r"(r[3]) : "r"(addr));
}
__device__ __forceinline__ uint32_t smem_u32(const void* p) {
    uint32_t a;
    asm("{ .reg .u64 t; cvta.to.shared.u64 t, %1; cvt.u32.u64 %0, t; }"
        : "=r"(a) : "l"(p));
    return a;
}
__device__ __forceinline__ void cp16(uint32_t dst, const void* src) {
    asm volatile("cp.async.cg.shared.global [%0], [%1], 16;" :: "r"(dst), "l"(src));
}
#define CP_COMMIT() asm volatile("cp.async.commit_group;" ::: "memory")
#define CP_WAIT0()  asm volatile("cp.async.wait_group 0;" ::: "memory")

// ===================== scratch ==============================================
__device__ __align__(16) float g_obuf [NTOK*1536];
__device__ __align__(16) float g_gatec[NTOK*512];
__device__ __align__(16) float g_gatet[NTOK*512];
__device__ __align__(16) float g_imp  [NTOK];
__device__ int   g_tidx [128];

// fp16 arenas: only K operands keep a lo limb
__device__ __align__(16) __half g_xh[NTOK*512];
__device__ __align__(16) __half g_qkvh[NTOK*1536], g_qkvl[NTOK*1536]; // lo used for K band
__device__ __align__(16) __half g_qch[NTOK*512];
__device__ __align__(16) __half g_qth[NTOK*512];
__device__ __align__(16) __half g_aLh[NTOK*512];
__device__ __align__(16) __half g_aCh[NTOK*512];
__device__ __align__(16) __half g_aTh[NTOK*512];
__device__ __align__(16) __half g_ch[384*512];
__device__ __align__(16) __half g_sh[128*512];
__device__ __align__(16) __half g_kch[384*512], g_kcl[384*512];
__device__ __align__(16) __half g_vch[384*512];
__device__ __align__(16) __half g_kth[128*512], g_ktl[128*512];
__device__ __align__(16) __half g_vth[128*512];
__device__ __align__(16) __half g_wh[7168*512];

// ===================== fused x-prep: convert + pool + imp ===================
__global__ __launch_bounds__(512) void xprep_kernel(
    const float* __restrict__ x, const float* __restrict__ Wimp,
    const float* __restrict__ bimp,
    __half* __restrict__ xh, __half* __restrict__ ch, float* __restrict__ imp)
{
    __shared__ float wred[16][8];
    const int g = blockIdx.x;
    const int b = g >> 8, p = g & 255;
    const int d = threadIdx.x;
    const int lane = d & 31, wid = d >> 5;
    const float w = Wimp[d];

    float psum = 0.f, part[8];
#pragma unroll
    for (int r = 0; r < 8; r++) {
        size_t row = (size_t)(b * S_LEN + p * 8 + r);
        float v = x[row * 512 + d];
        xh[row * 512 + d] = __float2half(v);
        psum += v;
        part[r] = v * w;
    }
    if (p < 192) {
        size_t off = (size_t)(b * 192 + p) * 512 + d;
        ch[off] = __float2half(psum * 0.125f);
    }
#pragma unroll
    for (int r = 0; r < 8; r++) {
        float t = part[r];
#pragma unroll
        for (int off = 16; off; off >>= 1)
            t += __shfl_xor_sync(0xffffffffu, t, off);
        if (!lane) wred[wid][r] = t;
    }
    __syncthreads();
    if (d < 8) {
        float s = 0.f;
#pragma unroll
        for (int ww = 0; ww < 16; ww++) s += wred[ww][d];
        imp[b * S_LEN + p * 8 + d] = s + bimp[0];
    }
}

// ===================== weight converter (fp16 hi only, transposed) ==========
struct WSeg { const float* W; __half* hi; int M; int blk; };
struct WBatch { WSeg s[12]; int n; };

__global__ __launch_bounds__(256) void conv_w(WBatch bt)
{
    __shared__ float ts[32][33];
    int b = blockIdx.x, si = 0;
    while (si < bt.n - 1 && b >= bt.s[si].blk) { b -= bt.s[si].blk; si++; }
    const float* __restrict__ W = bt.s[si].W;
    const int M = bt.s[si].M;
    const int ntn = M >> 5;
    const int tk = (b / ntn) * 32, tn = (b % ntn) * 32;
    const int tx = threadIdx.x & 31, ty = threadIdx.x >> 5;
#pragma unroll
    for (int i = 0; i < 4; i++)
        ts[ty + 8 * i][tx] = W[(size_t)(tk + ty + 8 * i) * M + tn + tx];
    __syncthreads();
#pragma unroll
    for (int i = 0; i < 4; i++) {
        int n = tn + ty + 8 * i, k = tk + tx;
        bt.s[si].hi[(size_t)n * 512 + k] = __float2half(ts[tx][ty + 8 * i]);
    }
}

// ===================== HMMA GEMM v7: fp16 single-product ====================
// epi 0: fp32  1: sigmoid fp32  2: hi+lo  3: hi *0.125  4: qkv fused  5: hi
struct MSeg {
    const __half *Ah, *Bh;
    const float* bias;
    float* C; __half *Ch, *Cl;
    int tx, ty, epi, Mout;
};
struct MBatch { MSeg s[9]; int n; };

#define SSTR 40
#define ARR  (128 * SSTR)

__global__ __launch_bounds__(256, 2) void mma_gemm(MBatch bt)
{
    extern __shared__ __half gsm[];   // [2 buf][2 arr][ARR]

    int t = blockIdx.x, si = 0;
    while (si < bt.n - 1 && t >= bt.s[si].tx * bt.s[si].ty) {
        t -= bt.s[si].tx * bt.s[si].ty; si++;
    }
    const MSeg sg = bt.s[si];
    const int col0 = (t % sg.tx) * 128, row0 = (t / sg.tx) * 128;
    const __half* __restrict__ srcs[2] = { sg.Ah, sg.Bh };
    const int rbase[2] = { row0, col0 };

    const int tid = threadIdx.x, wid = tid >> 5, lane = tid & 31;
    const int wr = wid & 3, wc = wid >> 2;
    const int lr = lane >> 2, lc = (lane & 3) * 2;

    float acc[2][8][4];
#pragma unroll
    for (int mt = 0; mt < 2; mt++)
#pragma unroll
        for (int nt = 0; nt < 8; nt++)
#pragma unroll
            for (int j = 0; j < 4; j++) acc[mt][nt][j] = 0.f;

    auto load_chunk = [&](int d, int kc) {
#pragma unroll
        for (int i = 0; i < 4; i++) {
            int idx = i * 256 + tid;
            int a = idx >> 9, u = idx & 511;
            int r = u >> 2, cg = u & 3;
            uint32_t dst = smem_u32(gsm + (d * 2 + a) * ARR + r * SSTR + cg * 8);
            cp16(dst, srcs[a] + (size_t)(rbase[a] + r) * 512 + kc + cg * 8);
        }
        CP_COMMIT();
    };

    const int a_row = (lane & 7) + ((lane >> 3) & 1) * 8;
    const int a_col = (lane >> 4) * 8;
    const int b_row = (lane & 7) + ((lane >> 4) & 1) * 8;
    const int b_col = ((lane >> 3) & 1) * 8;

    load_chunk(0, 0);

    for (int c = 0; c < 16; c++) {
        CP_WAIT0();
        __syncthreads();
        if (c + 1 < 16) load_chunk((c + 1) & 1, (c + 1) * 32);

        const int d = c & 1;
        __half* bufAh = gsm + (d * 2 + 0) * ARR;
        __half* bufBh = gsm + (d * 2 + 1) * ARR;

#pragma unroll
        for (int ks = 0; ks < 2; ks++) {
            const int k0 = ks * 16;
            uint32_t af[2][4];
#pragma unroll
            for (int mt = 0; mt < 2; mt++)
                ldsm_x4(af[mt], smem_u32(bufAh + (wr * 32 + mt * 16 + a_row) * SSTR + k0 + a_col));
#pragma unroll
            for (int pr = 0; pr < 4; pr++) {
                uint32_t bh[4];
                ldsm_x4(bh, smem_u32(bufBh + (wc * 64 + pr * 16 + b_row) * SSTR + k0 + b_col));
#pragma unroll
                for (int half = 0; half < 2; half++) {
                    int nt = pr * 2 + half;
                    mma16816(acc[0][nt], af[0], bh[half * 2], bh[half * 2 + 1]);
                    mma16816(acc[1][nt], af[1], bh[half * 2], bh[half * 2 + 1]);
                }
            }
        }
    }

    const float* __restrict__ bias = sg.bias;
    const int Mout = sg.Mout, epi = sg.epi;
#pragma unroll
    for (int mt = 0; mt < 2; mt++) {
        int r = row0 + wr * 32 + mt * 16 + lr;
#pragma unroll
        for (int nt = 0; nt < 8; nt++) {
            int c = col0 + wc * 64 + nt * 8 + lc;
            float b0 = __ldg(bias + c), b1 = __ldg(bias + c + 1);
            float v0 = acc[mt][nt][0] + b0, v1 = acc[mt][nt][1] + b1;
            float v2 = acc[mt][nt][2] + b0, v3 = acc[mt][nt][3] + b1;
            size_t o0 = (size_t)r * Mout + c;
            size_t o1 = (size_t)(r + 8) * Mout + c;
            if (epi == 0) {
                *(float2*)(sg.C + o0) = make_float2(v0, v1);
                *(float2*)(sg.C + o1) = make_float2(v2, v3);
            } else if (epi == 1) {
                *(float2*)(sg.C + o0) = make_float2(
                    1.f / (1.f + expf(-v0)), 1.f / (1.f + expf(-v1)));
                *(float2*)(sg.C + o1) = make_float2(
                    1.f / (1.f + expf(-v2)), 1.f / (1.f + expf(-v3)));
            } else if (epi == 3 || epi == 5) {
                if (epi == 3) { v0 *= 0.125f; v1 *= 0.125f; v2 *= 0.125f; v3 *= 0.125f; }
                *(__half2*)(sg.Ch + o0) = __halves2half2(__float2half(v0), __float2half(v1));
                *(__half2*)(sg.Ch + o1) = __halves2half2(__float2half(v2), __float2half(v3));
            } else {   // epi 2 (hi+lo) or epi 4 (qkv fused)
                bool wlo = (epi == 2) || (c >= 512 && c < 1024);
                if (epi == 4 && c < 512) {
                    v0 *= 0.125f; v1 *= 0.125f; v2 *= 0.125f; v3 *= 0.125f;
                }
                __half h0 = __float2half(v0), h1 = __float2half(v1);
                __half h2 = __float2half(v2), h3 = __float2half(v3);
                *(__half2*)(sg.Ch + o0) = __halves2half2(h0, h1);
                *(__half2*)(sg.Ch + o1) = __halves2half2(h2, h3);
                if (wlo) {
                    *(__half2*)(sg.Cl + o0) = __halves2half2(
                        __float2half(v0 - __half2float(h0)),
                        __float2half(v1 - __half2float(h1)));
                    *(__half2*)(sg.Cl + o1) = __halves2half2(
                        __float2half(v2 - __half2float(h2)),
                        __float2half(v3 - __half2float(h3)));
                }
            }
        }
    }
}

// ===================== HMMA flash attention (K 2-prod, V 1-prod) ============
#define ASTR 72
#define SST  68

struct AttnParams {
    const __half *Qh[3], *Kh[3], *Kl[3], *Vh[3];
    __half *Oh[3];
    int qs[3], ks[3], nk[3];
    const int* tidx;
};

__global__ __launch_bounds__(256) void attn_mma(AttnParams P)
{
    extern __shared__ char dynsm[];
    __half* sQh = (__half*)dynsm;
    __half* sKh = sQh + 64 * ASTR;
    __half* sKl = sKh + 64 * ASTR;
    __half* sVh = sKl + 64 * ASTR;
    __half* sPh = sVh + 64 * ASTR;
    float* sS  = (float*)(sPh + 64 * ASTR);
    float* sAl = sS + 64 * SST;
    float* sIL = sAl + 64;
    int*   pos = (int*)(sIL + 64);

    const int mode = blockIdx.z >> 1, b = blockIdx.z & 1;
    const int h = blockIdx.y, q0 = blockIdx.x * 64;
    const int tid = threadIdx.x, wid = tid >> 5, lane = tid & 31;
    const int wr = wid & 3, wc = wid >> 2;
    const int lr = lane >> 2, lc = (lane & 3) * 2;

    const int a_row = (lane & 7) + ((lane >> 3) & 1) * 8;
    const int a_col = (lane >> 4) * 8;
    const int b_row = (lane & 7) + ((lane >> 4) & 1) * 8;
    const int b_col = ((lane >> 3) & 1) * 8;
    const int v_row = (lane & 7) + ((lane >> 3) & 1) * 8;
    const int v_col = ((lane >> 4) & 1) * 8;

    const __half* Qh = P.Qh[mode];
    const __half* Kh = P.Kh[mode]; const __half* Kl = P.Kl[mode];
    const __half* Vh = P.Vh[mode];
    const int qs = P.qs[mode], ks = P.ks[mode], nk = P.nk[mode];

    for (int idx = tid; idx < 64 * 8; idx += 256) {
        int r = idx >> 3, d0 = (idx & 7) * 8;
        size_t g = (size_t)(b * S_LEN + q0 + r) * qs + h * HDIM + d0;
        *(uint4*)(sQh + r * ASTR + d0) = *(const uint4*)(Qh + g);
    }

    float oacc[4][4];
#pragma unroll
    for (int nt = 0; nt < 4; nt++)
#pragma unroll
        for (int j = 0; j < 4; j++) oacc[nt][j] = 0.f;

    const int row = tid >> 2, jseg = tid & 3;
    const int q = q0 + row;
    float m = -INFINITY, l = 0.f;

    int kt0 = 0, ktend = nk;
    if (mode == 0) { kt0 = (q0 > 511) ? ((q0 - 511) & ~63) : 0; ktend = q0 + 64; }

    for (int kt = kt0; kt < ktend; kt += 64) {
        __syncthreads();
        for (int idx = tid; idx < 64 * 8; idx += 256) {
            int r = idx >> 3, d0 = (idx & 7) * 8;
            size_t g = (size_t)(b * nk + kt + r) * ks + h * HDIM + d0;
            *(uint4*)(sKh + r * ASTR + d0) = *(const uint4*)(Kh + g);
            *(uint4*)(sKl + r * ASTR + d0) = *(const uint4*)(Kl + g);
            *(uint4*)(sVh + r * ASTR + d0) = *(const uint4*)(Vh + g);
        }
        if (tid < 64) {
            int j = kt + tid;
            pos[tid] = (mode == 0) ? j : (mode == 1 ? (j + 1) * 8 : P.tidx[b * 64 + j]);
        }
        __syncthreads();

        // ---- S = Q K^T (K hi+lo) ----
        float sacc[4][4];
#pragma unroll
        for (int nt = 0; nt < 4; nt++)
#pragma unroll
            for (int j = 0; j < 4; j++) sacc[nt][j] = 0.f;
#pragma unroll
        for (int kss = 0; kss < 4; kss++) {
            const int k0 = kss * 16;
            uint32_t qf[4];
            ldsm_x4(qf, smem_u32(sQh + (wr * 16 + a_row) * ASTR + k0 + a_col));
#pragma unroll
            for (int pr = 0; pr < 2; pr++) {
                uint32_t kh[4];
                ldsm_x4(kh, smem_u32(sKh + (wc * 32 + pr * 16 + b_row) * ASTR + k0 + b_col));
#pragma unroll
                for (int half = 0; half < 2; half++)
                    mma16816(sacc[pr * 2 + half], qf, kh[half * 2], kh[half * 2 + 1]);
            }
#pragma unroll
            for (int pr = 0; pr < 2; pr++) {
                uint32_t kl[4];
                ldsm_x4(kl, smem_u32(sKl + (wc * 32 + pr * 16 + b_row) * ASTR + k0 + b_col));
#pragma unroll
                for (int half = 0; half < 2; half++)
                    mma16816(sacc[pr * 2 + half], qf, kl[half * 2], kl[half * 2 + 1]);
            }
        }
#pragma unroll
        for (int nt = 0; nt < 4; nt++) {
            int r0 = wr * 16 + lr, c0 = wc * 32 + nt * 8 + lc;
            *(float2*)(sS + r0 * SST + c0)       = make_float2(sacc[nt][0], sacc[nt][1]);
            *(float2*)(sS + (r0 + 8) * SST + c0) = make_float2(sacc[nt][2], sacc[nt][3]);
        }
        __syncthreads();

        float s[16], mt = -INFINITY;
#pragma unroll
        for (int jj = 0; jj < 16; jj++) {
            int j = 4 * jj + jseg;
            float sv = sS[row * SST + j];
            int p = pos[j];
            bool vis = (mode == 0) ? ((unsigned)(q - p) < 512u) : (q >= p);
            if (!vis) sv = NEGBIG;
            s[jj] = sv;
            mt = fmaxf(mt, sv);
        }
        mt = fmaxf(mt, __shfl_xor_sync(0xffffffffu, mt, 1));
        mt = fmaxf(mt, __shfl_xor_sync(0xffffffffu, mt, 2));
        float m_new = fmaxf(m, mt);

        float lt = 0.f;
#pragma unroll
        for (int jj = 0; jj < 16; jj++) {
            int j = 4 * jj + jseg;
            float p = expf(s[jj] - m_new);
            lt += p;
            sPh[row * ASTR + j] = __float2half(p);
        }
        lt += __shfl_xor_sync(0xffffffffu, lt, 1);
        lt += __shfl_xor_sync(0xffffffffu, lt, 2);
        float alpha = expf(m - m_new);
        l = l * alpha + lt;
        m = m_new;
        if (jseg == 0) sAl[row] = alpha;
        __syncthreads();

        float a0 = sAl[wr * 16 + lr], a1 = sAl[wr * 16 + lr + 8];
#pragma unroll
        for (int nt = 0; nt < 4; nt++) {
            oacc[nt][0] *= a0; oacc[nt][1] *= a0;
            oacc[nt][2] *= a1; oacc[nt][3] *= a1;
        }
        // ---- O += P V (single product) ----
#pragma unroll
        for (int kss = 0; kss < 4; kss++) {
            const int k0 = kss * 16;
            uint32_t pf[4];
            ldsm_x4(pf, smem_u32(sPh + (wr * 16 + a_row) * ASTR + k0 + a_col));
#pragma unroll
            for (int pr = 0; pr < 2; pr++) {
                uint32_t vh[4];
                ldsm_x4_t(vh, smem_u32(sVh + (k0 + v_row) * ASTR + wc * 32 + pr * 16 + v_col));
#pragma unroll
                for (int half = 0; half < 2; half++)
                    mma16816(oacc[pr * 2 + half], pf, vh[half * 2], vh[half * 2 + 1]);
            }
        }
    }

    if (jseg == 0) sIL[row] = 1.f / l;
    __syncthreads();
    float i0 = sIL[wr * 16 + lr], i1 = sIL[wr * 16 + lr + 8];
    __half* Oh = P.Oh[mode];
#pragma unroll
    for (int nt = 0; nt < 4; nt++) {
        int c = h * HDIM + wc * 32 + nt * 8 + lc;
        size_t o0 = (size_t)(b * S_LEN + q0 + wr * 16 + lr) * 512 + c;
        size_t o1 = (size_t)(b * S_LEN + q0 + wr * 16 + lr + 8) * 512 + c;
        *(__half2*)(Oh + o0) = __halves2half2(
            __float2half(oacc[nt][0] * i0), __float2half(oacc[nt][1] * i0));
        *(__half2*)(Oh + o1) = __halves2half2(
            __float2half(oacc[nt][2] * i1), __float2half(oacc[nt][3] * i1));
    }
}

// ===================== small kernels ========================================
__global__ void topk_kernel(const float* __restrict__ imp, int* __restrict__ tidx)
{
    int b = blockIdx.x;
    __shared__ float v[2048];
    __shared__ float bestv[256];
    __shared__ int   besti[256];
    int tid = threadIdx.x;
    for (int i = tid; i < 2048; i += 256) v[i] = imp[b * 2048 + i];
    __syncthreads();
    for (int r = 0; r < 64; r++) {
        float bv = -INFINITY; int bi = 0x7fffffff;
        for (int i = tid; i < 2048; i += 256) {
            float xv = v[i];
            if (xv > bv) { bv = xv; bi = i; }
        }
        bestv[tid] = bv; besti[tid] = bi;
        __syncthreads();
        for (int s2 = 128; s2 > 0; s2 >>= 1) {
            if (tid < s2) {
                float xo = bestv[tid + s2]; int io = besti[tid + s2];
                if (xo > bestv[tid] || (xo == bestv[tid] && io < besti[tid])) {
                    bestv[tid] = xo; besti[tid] = io;
                }
            }
            __syncthreads();
        }
        if (tid == 0) { tidx[b * 64 + r] = besti[0]; v[besti[0]] = -INFINITY; }
        __syncthreads();
    }
}

__global__ void gather_kernel(const float* __restrict__ x, const int* __restrict__ tidx,
                              __half* __restrict__ sh)
{
    int rowb = blockIdx.x;
    int b = rowb >> 6;
    int src = tidx[rowb];
    for (int d = threadIdx.x; d < 512; d += 256)
        sh[(size_t)rowb * 512 + d] = __float2half(x[(size_t)(b * S_LEN + src) * 512 + d]);
}

__global__ void combine_kernel(const float* __restrict__ b0, const float* __restrict__ bC,
                               const float* __restrict__ bT, const float* __restrict__ gc,
                               const float* __restrict__ gt, float* __restrict__ out)
{
    int i = (blockIdx.x * 256 + threadIdx.x) * 4;
    float4 v0 = *(const float4*)(b0 + i);
    float4 vC = *(const float4*)(bC + i);
    float4 vT = *(const float4*)(bT + i);
    float4 c = *(const float4*)(gc + i);
    float4 t = *(const float4*)(gt + i);
    v0.x += c.x * vC.x + t.x * vT.x;
    v0.y += c.y * vC.y + t.y * vT.y;
    v0.z += c.z * vC.z + t.z * vT.z;
    v0.w += c.w * vC.w + t.w * vT.w;
    *(float4*)(out + i) = v0;
}

// ===================== launch ===============================================
extern "C" void kernel_launch(void* const* d_in, const int* in_sizes, int n_in,
                              void* d_out, int out_size)
{
    const float* x    = (const float*)d_in[0];
    const float* Wqkv = (const float*)d_in[1];  const float* bqkv = (const float*)d_in[2];
    const float* Wlo  = (const float*)d_in[3];  const float* blo  = (const float*)d_in[4];
    const float* Wcq  = (const float*)d_in[5];  const float* bcq  = (const float*)d_in[6];
    const float* Wck  = (const float*)d_in[7];  const float* bck  = (const float*)d_in[8];
    const float* Wcv  = (const float*)d_in[9];  const float* bcv  = (const float*)d_in[10];
    const float* Wco  = (const float*)d_in[11]; const float* bco  = (const float*)d_in[12];
    const float* Wgc  = (const float*)d_in[13]; const float* bgc  = (const float*)d_in[14];
    const float* Wimp = (const float*)d_in[15]; const float* bimp = (const float*)d_in[16];
    const float* Wtq  = (const float*)d_in[17]; const float* btq  = (const float*)d_in[18];
    const float* Wtk  = (const float*)d_in[19]; const float* btk  = (const float*)d_in[20];
    const float* Wtv  = (const float*)d_in[21]; const float* btv  = (const float*)d_in[22];
    const float* Wto  = (const float*)d_in[23]; const float* bto  = (const float*)d_in[24];
    const float* Wgt  = (const float*)d_in[25]; const float* bgt  = (const float*)d_in[26];
    float* out = (float*)d_out;

    float *obuf, *gatec, *gatet, *imp;
    int* tidx;
    __half *xh, *qkvh, *qkvl, *qch, *qth, *aLh, *aCh, *aTh;
    __half *ch, *sh, *kch, *kcl, *vch, *kth, *ktl, *vth, *wh;
    cudaGetSymbolAddress((void**)&obuf,  g_obuf);
    cudaGetSymbolAddress((void**)&gatec, g_gatec);
    cudaGetSymbolAddress((void**)&gatet, g_gatet);
    cudaGetSymbolAddress((void**)&imp,   g_imp);
    cudaGetSymbolAddress((void**)&tidx,  g_tidx);
    cudaGetSymbolAddress((void**)&xh,   g_xh);
    cudaGetSymbolAddress((void**)&qkvh, g_qkvh); cudaGetSymbolAddress((void**)&qkvl, g_qkvl);
    cudaGetSymbolAddress((void**)&qch,  g_qch);
    cudaGetSymbolAddress((void**)&qth,  g_qth);
    cudaGetSymbolAddress((void**)&aLh,  g_aLh);
    cudaGetSymbolAddress((void**)&aCh,  g_aCh);
    cudaGetSymbolAddress((void**)&aTh,  g_aTh);
    cudaGetSymbolAddress((void**)&ch,   g_ch);
    cudaGetSymbolAddress((void**)&sh,   g_sh);
    cudaGetSymbolAddress((void**)&kch,  g_kch);  cudaGetSymbolAddress((void**)&kcl,  g_kcl);
    cudaGetSymbolAddress((void**)&vch,  g_vch);
    cudaGetSymbolAddress((void**)&kth,  g_kth);  cudaGetSymbolAddress((void**)&ktl,  g_ktl);
    cudaGetSymbolAddress((void**)&vth,  g_vth);
    cudaGetSymbolAddress((void**)&wh,   g_wh);

    const int ATTN_SMEM = 5 * 64 * ASTR * 2 + 64 * SST * 4 + 3 * 64 * 4;
    cudaFuncSetAttribute(attn_mma, cudaFuncAttributeMaxDynamicSharedMemorySize, ATTN_SMEM);
    const int GEMM_SMEM = 2 * 2 * ARR * 2;   // 40960
    cudaFuncSetAttribute(mma_gemm, cudaFuncAttributeMaxDynamicSharedMemorySize, GEMM_SMEM);

    const int O_QKV = 0,    O_LO = 1536, O_CQ = 2048, O_CK = 2560, O_CV = 3072,
              O_CO = 3584,  O_GC = 4096, O_TQ = 4608, O_TK = 5120, O_TV = 5632,
              O_TO = 6144,  O_GT = 6656;
    #define WH(o) (wh + (size_t)(o) * 512)

    {
        WBatch wb;
        wb.s[0]  = {Wqkv, WH(O_QKV), 1536, 768};
        wb.s[1]  = {Wlo,  WH(O_LO),  512, 256};
        wb.s[2]  = {Wcq,  WH(O_CQ),  512, 256};
        wb.s[3]  = {Wck,  WH(O_CK),  512, 256};
        wb.s[4]  = {Wcv,  WH(O_CV),  512, 256};
        wb.s[5]  = {Wco,  WH(O_CO),  512, 256};
        wb.s[6]  = {Wgc,  WH(O_GC),  512, 256};
        wb.s[7]  = {Wtq,  WH(O_TQ),  512, 256};
        wb.s[8]  = {Wtk,  WH(O_TK),  512, 256};
        wb.s[9]  = {Wtv,  WH(O_TV),  512, 256};
        wb.s[10] = {Wto,  WH(O_TO),  512, 256};
        wb.s[11] = {Wgt,  WH(O_GT),  512, 256};
        wb.n = 12;
        conv_w<<<768 + 11 * 256, 256>>>(wb);
    }
    xprep_kernel<<<512, 512>>>(x, Wimp, bimp, xh, ch, imp);
    topk_kernel<<<2, 256>>>(imp, tidx);
    gather_kernel<<<128, 256>>>(x, tidx, sh);

    {
        MBatch mb;
        mb.s[0] = {xh, WH(O_QKV), bqkv, nullptr, qkvh, qkvl, 12, 32, 4, 1536};
        mb.s[1] = {xh, WH(O_CQ),  bcq,  nullptr, qch,  nullptr, 4, 32, 3, 512};
        mb.s[2] = {xh, WH(O_GC),  bgc,  gatec,  nullptr, nullptr, 4, 32, 1, 512};
        mb.s[3] = {xh, WH(O_TQ),  btq,  nullptr, qth,  nullptr, 4, 32, 3, 512};
        mb.s[4] = {xh, WH(O_GT),  bgt,  gatet,  nullptr, nullptr, 4, 32, 1, 512};
        mb.s[5] = {ch, WH(O_CK),  bck,  nullptr, kch,  kcl, 4, 3, 2, 512};
        mb.s[6] = {ch, WH(O_CV),  bcv,  nullptr, vch,  nullptr, 4, 3, 5, 512};
        mb.s[7] = {sh, WH(O_TK),  btk,  nullptr, kth,  ktl, 4, 1, 2, 512};
        mb.s[8] = {sh, WH(O_TV),  btv,  nullptr, vth,  nullptr, 4, 1, 5, 512};
        mb.n = 9;
        mma_gemm<<<928, 256, GEMM_SMEM>>>(mb);
    }

    {
        AttnParams P;
        P.Qh[0] = qkvh;
        P.Kh[0] = qkvh + 512;  P.Kl[0] = qkvl + 512;
        P.Vh[0] = qkvh + 1024;
        P.Oh[0] = aLh; P.qs[0] = 1536; P.ks[0] = 1536; P.nk[0] = 2048;
        P.Qh[1] = qch; P.Kh[1] = kch; P.Kl[1] = kcl; P.Vh[1] = vch;
        P.Oh[1] = aCh; P.qs[1] = 512; P.ks[1] = 512; P.nk[1] = 192;
        P.Qh[2] = qth; P.Kh[2] = kth; P.Kl[2] = ktl; P.Vh[2] = vth;
        P.Oh[2] = aTh; P.qs[2] = 512; P.ks[2] = 512; P.nk[2] = 64;
        P.tidx = tidx;
        attn_mma<<<dim3(32, 8, 6), 256, ATTN_SMEM>>>(P);
    }

    float* buf0 = obuf;
    float* bufC = obuf + (size_t)NTOK * 512;
    float* bufT = obuf + (size_t)NTOK * 1024;
    {
        MBatch mb;
        mb.s[0] = {aLh, WH(O_LO), blo, buf0, nullptr, nullptr, 4, 32, 0, 512};
        mb.s[1] = {aCh, WH(O_CO), bco, bufC, nullptr, nullptr, 4, 32, 0, 512};
        mb.s[2] = {aTh, WH(O_TO), bto, bufT, nullptr, nullptr, 4, 32, 0, 512};
        mb.n = 3;
        mma_gemm<<<384, 256, GEMM_SMEM>>>(mb);
    }
    combine_kernel<<<NTOK * 512 / 1024, 256>>>(buf0, bufC, bufT, gatec, gatet, out);
}

// round 12
// speedup vs baseline: 9.2991x; 1.0697x over previous
#include <cuda_runtime.h>
#include <cuda_fp16.h>
#include <math.h>
#include <stdint.h>

#define S_LEN 2048
#define NTOK  4096
#define HDIM  64
#define NEGBIG -1e9f

// ===================== PTX helpers ==========================================
__device__ __forceinline__ void mma16816(float* c, const uint32_t* a,
                                         uint32_t b0, uint32_t b1) {
    asm volatile(
        "mma.sync.aligned.m16n8k16.row.col.f32.f16.f16.f32 "
        "{%0,%1,%2,%3}, {%4,%5,%6,%7}, {%8,%9}, {%0,%1,%2,%3};"
        : "+f"(c[0]), "+f"(c[1]), "+f"(c[2]), "+f"(c[3])
        : "r"(a[0]), "r"(a[1]), "r"(a[2]), "r"(a[3]), "r"(b0), "r"(b1));
}
__device__ __forceinline__ void ldsm_x4(uint32_t* r, uint32_t addr) {
    asm volatile("ldmatrix.sync.aligned.m8n8.x4.shared.b16 {%0,%1,%2,%3}, [%4];"
                 : "=r"(r[0]), "=r"(r[1]), "=r"(r[2]), "=r"(r[3]) : "r"(addr));
}
__device__ __forceinline__ void ldsm_x4_t(uint32_t* r, uint32_t addr) {
    asm volatile("ldmatrix.sync.aligned.m8n8.x4.trans.shared.b16 {%0,%1,%2,%3}, [%4];"
                 : "=r"(r[0]), "=r"(r[1]), "=r"(r[2]), "=r"(r[3]) : "r"(addr));
}
__device__ __forceinline__ uint32_t smem_u32(const void* p) {
    uint32_t a;
    asm("{ .reg .u64 t; cvta.to.shared.u64 t, %1; cvt.u32.u64 %0, t; }"
        : "=r"(a) : "l"(p));
    return a;
}
__device__ __forceinline__ void cp16(uint32_t dst, const void* src) {
    asm volatile("cp.async.cg.shared.global [%0], [%1], 16;" :: "r"(dst), "l"(src));
}
#define CP_COMMIT() asm volatile("cp.async.commit_group;" ::: "memory")
#define CP_WAIT0()  asm volatile("cp.async.wait_group 0;" ::: "memory")

// ===================== scratch ==============================================
__device__ __align__(16) float g_obuf [NTOK*1536];
__device__ __align__(16) float g_gatec[NTOK*512];
__device__ __align__(16) float g_gatet[NTOK*512];
__device__ __align__(16) float g_imp  [NTOK];
__device__ int   g_tidx [128];

__device__ __align__(16) __half g_xh[NTOK*512];
__device__ __align__(16) __half g_qkvh[NTOK*1536], g_qkvl[NTOK*1536];
__device__ __align__(16) __half g_qch[NTOK*512];
__device__ __align__(16) __half g_qth[NTOK*512];
__device__ __align__(16) __half g_aLh[NTOK*512];
__device__ __align__(16) __half g_aCh[NTOK*512];
__device__ __align__(16) __half g_aTh[NTOK*512];
__device__ __align__(16) __half g_ch[384*512];
__device__ __align__(16) __half g_sh[128*512];
__device__ __align__(16) __half g_kch[384*512], g_kcl[384*512];
__device__ __align__(16) __half g_vch[384*512];
__device__ __align__(16) __half g_kth[128*512], g_ktl[128*512];
__device__ __align__(16) __half g_vth[128*512];
__device__ __align__(16) __half g_wh[7168*512];

// ===================== fused x-prep: convert + pool + imp ===================
__global__ __launch_bounds__(512) void xprep_kernel(
    const float* __restrict__ x, const float* __restrict__ Wimp,
    const float* __restrict__ bimp,
    __half* __restrict__ xh, __half* __restrict__ ch, float* __restrict__ imp)
{
    __shared__ float wred[16][8];
    const int g = blockIdx.x;
    const int b = g >> 8, p = g & 255;
    const int d = threadIdx.x;
    const int lane = d & 31, wid = d >> 5;
    const float w = Wimp[d];

    float psum = 0.f, part[8];
#pragma unroll
    for (int r = 0; r < 8; r++) {
        size_t row = (size_t)(b * S_LEN + p * 8 + r);
        float v = x[row * 512 + d];
        xh[row * 512 + d] = __float2half(v);
        psum += v;
        part[r] = v * w;
    }
    if (p < 192) {
        size_t off = (size_t)(b * 192 + p) * 512 + d;
        ch[off] = __float2half(psum * 0.125f);
    }
#pragma unroll
    for (int r = 0; r < 8; r++) {
        float t = part[r];
#pragma unroll
        for (int off = 16; off; off >>= 1)
            t += __shfl_xor_sync(0xffffffffu, t, off);
        if (!lane) wred[wid][r] = t;
    }
    __syncthreads();
    if (d < 8) {
        float s = 0.f;
#pragma unroll
        for (int ww = 0; ww < 16; ww++) s += wred[ww][d];
        imp[b * S_LEN + p * 8 + d] = s + bimp[0];
    }
}

// ===================== weight converter (fp16 hi only, transposed) ==========
struct WSeg { const float* W; __half* hi; int M; int blk; };
struct WBatch { WSeg s[12]; int n; };

__global__ __launch_bounds__(256) void conv_w(WBatch bt)
{
    __shared__ float ts[32][33];
    int b = blockIdx.x, si = 0;
    while (si < bt.n - 1 && b >= bt.s[si].blk) { b -= bt.s[si].blk; si++; }
    const float* __restrict__ W = bt.s[si].W;
    const int M = bt.s[si].M;
    const int ntn = M >> 5;
    const int tk = (b / ntn) * 32, tn = (b % ntn) * 32;
    const int tx = threadIdx.x & 31, ty = threadIdx.x >> 5;
#pragma unroll
    for (int i = 0; i < 4; i++)
        ts[ty + 8 * i][tx] = W[(size_t)(tk + ty + 8 * i) * M + tn + tx];
    __syncthreads();
#pragma unroll
    for (int i = 0; i < 4; i++) {
        int n = tn + ty + 8 * i, k = tk + tx;
        bt.s[si].hi[(size_t)n * 512 + k] = __float2half(ts[tx][ty + 8 * i]);
    }
}

// ===================== HMMA GEMM (fp16 single-product, unchanged) ===========
struct MSeg {
    const __half *Ah, *Bh;
    const float* bias;
    float* C; __half *Ch, *Cl;
    int tx, ty, epi, Mout;
};
struct MBatch { MSeg s[9]; int n; };

#define SSTR 40
#define ARR  (128 * SSTR)

__global__ __launch_bounds__(256, 2) void mma_gemm(MBatch bt)
{
    extern __shared__ __half gsm[];

    int t = blockIdx.x, si = 0;
    while (si < bt.n - 1 && t >= bt.s[si].tx * bt.s[si].ty) {
        t -= bt.s[si].tx * bt.s[si].ty; si++;
    }
    const MSeg sg = bt.s[si];
    const int col0 = (t % sg.tx) * 128, row0 = (t / sg.tx) * 128;
    const __half* __restrict__ srcs[2] = { sg.Ah, sg.Bh };
    const int rbase[2] = { row0, col0 };

    const int tid = threadIdx.x, wid = tid >> 5, lane = tid & 31;
    const int wr = wid & 3, wc = wid >> 2;
    const int lr = lane >> 2, lc = (lane & 3) * 2;

    float acc[2][8][4];
#pragma unroll
    for (int mt = 0; mt < 2; mt++)
#pragma unroll
        for (int nt = 0; nt < 8; nt++)
#pragma unroll
            for (int j = 0; j < 4; j++) acc[mt][nt][j] = 0.f;

    auto load_chunk = [&](int d, int kc) {
#pragma unroll
        for (int i = 0; i < 4; i++) {
            int idx = i * 256 + tid;
            int a = idx >> 9, u = idx & 511;
            int r = u >> 2, cg = u & 3;
            uint32_t dst = smem_u32(gsm + (d * 2 + a) * ARR + r * SSTR + cg * 8);
            cp16(dst, srcs[a] + (size_t)(rbase[a] + r) * 512 + kc + cg * 8);
        }
        CP_COMMIT();
    };

    const int a_row = (lane & 7) + ((lane >> 3) & 1) * 8;
    const int a_col = (lane >> 4) * 8;
    const int b_row = (lane & 7) + ((lane >> 4) & 1) * 8;
    const int b_col = ((lane >> 3) & 1) * 8;

    load_chunk(0, 0);

    for (int c = 0; c < 16; c++) {
        CP_WAIT0();
        __syncthreads();
        if (c + 1 < 16) load_chunk((c + 1) & 1, (c + 1) * 32);

        const int d = c & 1;
        __half* bufAh = gsm + (d * 2 + 0) * ARR;
        __half* bufBh = gsm + (d * 2 + 1) * ARR;

#pragma unroll
        for (int ks = 0; ks < 2; ks++) {
            const int k0 = ks * 16;
            uint32_t af[2][4];
#pragma unroll
            for (int mt = 0; mt < 2; mt++)
                ldsm_x4(af[mt], smem_u32(bufAh + (wr * 32 + mt * 16 + a_row) * SSTR + k0 + a_col));
#pragma unroll
            for (int pr = 0; pr < 4; pr++) {
                uint32_t bh[4];
                ldsm_x4(bh, smem_u32(bufBh + (wc * 64 + pr * 16 + b_row) * SSTR + k0 + b_col));
#pragma unroll
                for (int half = 0; half < 2; half++) {
                    int nt = pr * 2 + half;
                    mma16816(acc[0][nt], af[0], bh[half * 2], bh[half * 2 + 1]);
                    mma16816(acc[1][nt], af[1], bh[half * 2], bh[half * 2 + 1]);
                }
            }
        }
    }

    const float* __restrict__ bias = sg.bias;
    const int Mout = sg.Mout, epi = sg.epi;
#pragma unroll
    for (int mt = 0; mt < 2; mt++) {
        int r = row0 + wr * 32 + mt * 16 + lr;
#pragma unroll
        for (int nt = 0; nt < 8; nt++) {
            int c = col0 + wc * 64 + nt * 8 + lc;
            float b0 = __ldg(bias + c), b1 = __ldg(bias + c + 1);
            float v0 = acc[mt][nt][0] + b0, v1 = acc[mt][nt][1] + b1;
            float v2 = acc[mt][nt][2] + b0, v3 = acc[mt][nt][3] + b1;
            size_t o0 = (size_t)r * Mout + c;
            size_t o1 = (size_t)(r + 8) * Mout + c;
            if (epi == 0) {
                *(float2*)(sg.C + o0) = make_float2(v0, v1);
                *(float2*)(sg.C + o1) = make_float2(v2, v3);
            } else if (epi == 1) {
                *(float2*)(sg.C + o0) = make_float2(
                    1.f / (1.f + expf(-v0)), 1.f / (1.f + expf(-v1)));
                *(float2*)(sg.C + o1) = make_float2(
                    1.f / (1.f + expf(-v2)), 1.f / (1.f + expf(-v3)));
            } else if (epi == 3 || epi == 5) {
                if (epi == 3) { v0 *= 0.125f; v1 *= 0.125f; v2 *= 0.125f; v3 *= 0.125f; }
                *(__half2*)(sg.Ch + o0) = __halves2half2(__float2half(v0), __float2half(v1));
                *(__half2*)(sg.Ch + o1) = __halves2half2(__float2half(v2), __float2half(v3));
            } else {
                bool wlo = (epi == 2) || (c >= 512 && c < 1024);
                if (epi == 4 && c < 512) {
                    v0 *= 0.125f; v1 *= 0.125f; v2 *= 0.125f; v3 *= 0.125f;
                }
                __half h0 = __float2half(v0), h1 = __float2half(v1);
                __half h2 = __float2half(v2), h3 = __float2half(v3);
                *(__half2*)(sg.Ch + o0) = __halves2half2(h0, h1);
                *(__half2*)(sg.Ch + o1) = __halves2half2(h2, h3);
                if (wlo) {
                    *(__half2*)(sg.Cl + o0) = __halves2half2(
                        __float2half(v0 - __half2float(h0)),
                        __float2half(v1 - __half2float(h1)));
                    *(__half2*)(sg.Cl + o1) = __halves2half2(
                        __float2half(v2 - __half2float(h2)),
                        __float2half(v3 - __half2float(h3)));
                }
            }
        }
    }
}

// ===================== attention v2: register-resident softmax & P ==========
#define ASTR 72

struct AttnParams {
    const __half *Qh[3], *Kh[3], *Kl[3], *Vh[3];
    __half *Oh[3];
    int qs[3], ks[3], nk[3];
    const int* tidx;
};

__global__ __launch_bounds__(256) void attn_mma(AttnParams P)
{
    extern __shared__ char dynsm[];
    __half* sQh = (__half*)dynsm;
    __half* sKh = sQh + 64 * ASTR;
    __half* sKl = sKh + 64 * ASTR;
    __half* sVh = sKl + 64 * ASTR;
    int*   pos = (int*)(sVh + 64 * ASTR);
    float* bm  = (float*)(pos + 64);       // [64][2]
    float* bs  = bm + 128;                 // [64][2]
    float* obuf = (float*)sKh;             // [64][66] epilogue overlay

    const int mode = blockIdx.z >> 1, b = blockIdx.z & 1;
    const int h = blockIdx.y, q0 = blockIdx.x * 64;
    const int tid = threadIdx.x, wid = tid >> 5, lane = tid & 31;
    const int wr = wid & 3, wc = wid >> 2;
    const int lr = lane >> 2, lc = (lane & 3) * 2;
    const int r0 = wr * 16 + lr, r1 = r0 + 8;
    const int qq0 = q0 + r0, qq1 = q0 + r1;

    const int a_row = (lane & 7) + ((lane >> 3) & 1) * 8;
    const int a_col = (lane >> 4) * 8;
    const int b_row = (lane & 7) + ((lane >> 4) & 1) * 8;
    const int b_col = ((lane >> 3) & 1) * 8;
    const int v_row = (lane & 7) + ((lane >> 3) & 1) * 8;
    const int v_col = ((lane >> 4) & 1) * 8;

    const __half* Qh = P.Qh[mode];
    const __half* Kh = P.Kh[mode]; const __half* Kl = P.Kl[mode];
    const __half* Vh = P.Vh[mode];
    const int qs = P.qs[mode], ks = P.ks[mode], nk = P.nk[mode];

    for (int idx = tid; idx < 64 * 8; idx += 256) {
        int r = idx >> 3, d0 = (idx & 7) * 8;
        size_t g = (size_t)(b * S_LEN + q0 + r) * qs + h * HDIM + d0;
        *(uint4*)(sQh + r * ASTR + d0) = *(const uint4*)(Qh + g);
    }

    float oacc[8][4];   // partial O: keys of this wc-half, all 64 d-cols
#pragma unroll
    for (int nb = 0; nb < 8; nb++)
#pragma unroll
        for (int j = 0; j < 4; j++) oacc[nb][j] = 0.f;

    float m0 = -INFINITY, m1 = -INFINITY, l0 = 0.f, l1 = 0.f;

    int kt0 = 0, ktend = nk;
    if (mode == 0) { kt0 = (q0 > 511) ? ((q0 - 511) & ~63) : 0; ktend = q0 + 64; }

    for (int kt = kt0; kt < ktend; kt += 64) {
        __syncthreads();
        for (int idx = tid; idx < 64 * 8; idx += 256) {
            int r = idx >> 3, d0 = (idx & 7) * 8;
            size_t g = (size_t)(b * nk + kt + r) * ks + h * HDIM + d0;
            *(uint4*)(sKh + r * ASTR + d0) = *(const uint4*)(Kh + g);
            *(uint4*)(sKl + r * ASTR + d0) = *(const uint4*)(Kl + g);
            *(uint4*)(sVh + r * ASTR + d0) = *(const uint4*)(Vh + g);
        }
        if (tid < 64) {
            int j = kt + tid;
            pos[tid] = (mode == 0) ? j : (mode == 1 ? (j + 1) * 8 : P.tidx[b * 64 + j]);
        }
        __syncthreads();

        // ---- S = Q K^T (K hi+lo) ----
        float sacc[4][4];
#pragma unroll
        for (int nt = 0; nt < 4; nt++)
#pragma unroll
            for (int j = 0; j < 4; j++) sacc[nt][j] = 0.f;
#pragma unroll
        for (int kss = 0; kss < 4; kss++) {
            const int k0 = kss * 16;
            uint32_t qf[4];
            ldsm_x4(qf, smem_u32(sQh + (wr * 16 + a_row) * ASTR + k0 + a_col));
#pragma unroll
            for (int pr = 0; pr < 2; pr++) {
                uint32_t kh[4];
                ldsm_x4(kh, smem_u32(sKh + (wc * 32 + pr * 16 + b_row) * ASTR + k0 + b_col));
#pragma unroll
                for (int half = 0; half < 2; half++)
                    mma16816(sacc[pr * 2 + half], qf, kh[half * 2], kh[half * 2 + 1]);
            }
#pragma unroll
            for (int pr = 0; pr < 2; pr++) {
                uint32_t kl[4];
                ldsm_x4(kl, smem_u32(sKl + (wc * 32 + pr * 16 + b_row) * ASTR + k0 + b_col));
#pragma unroll
                for (int half = 0; half < 2; half++)
                    mma16816(sacc[pr * 2 + half], qf, kl[half * 2], kl[half * 2 + 1]);
            }
        }

        // ---- mask + band max (registers) ----
        float bx0 = -INFINITY, bx1 = -INFINITY;
#pragma unroll
        for (int nt = 0; nt < 4; nt++) {
#pragma unroll
            for (int ci = 0; ci < 2; ci++) {
                int p = pos[wc * 32 + nt * 8 + lc + ci];
                bool v0 = (mode == 0) ? ((unsigned)(qq0 - p) < 512u) : (qq0 >= p);
                bool v1 = (mode == 0) ? ((unsigned)(qq1 - p) < 512u) : (qq1 >= p);
                if (!v0) sacc[nt][ci] = NEGBIG;
                if (!v1) sacc[nt][2 + ci] = NEGBIG;
                bx0 = fmaxf(bx0, sacc[nt][ci]);
                bx1 = fmaxf(bx1, sacc[nt][2 + ci]);
            }
        }
        bx0 = fmaxf(bx0, __shfl_xor_sync(0xffffffffu, bx0, 1));
        bx0 = fmaxf(bx0, __shfl_xor_sync(0xffffffffu, bx0, 2));
        bx1 = fmaxf(bx1, __shfl_xor_sync(0xffffffffu, bx1, 1));
        bx1 = fmaxf(bx1, __shfl_xor_sync(0xffffffffu, bx1, 2));
        if ((lane & 3) == 0) { bm[r0 * 2 + wc] = bx0; bm[r1 * 2 + wc] = bx1; }
        __syncthreads();

        float mn0 = fmaxf(m0, fmaxf(bm[r0 * 2], bm[r0 * 2 + 1]));
        float mn1 = fmaxf(m1, fmaxf(bm[r1 * 2], bm[r1 * 2 + 1]));

        // ---- exp + pack P into A-operand registers ----
        uint32_t pr0[4], pr1[4];
        float lt0 = 0.f, lt1 = 0.f;
#pragma unroll
        for (int nt = 0; nt < 4; nt++) {
            float e0 = expf(sacc[nt][0] - mn0), e1 = expf(sacc[nt][1] - mn0);
            float e2 = expf(sacc[nt][2] - mn1), e3 = expf(sacc[nt][3] - mn1);
            lt0 += e0 + e1; lt1 += e2 + e3;
            __half2 hp0 = __halves2half2(__float2half(e0), __float2half(e1));
            __half2 hp1 = __halves2half2(__float2half(e2), __float2half(e3));
            pr0[nt] = *(uint32_t*)&hp0;
            pr1[nt] = *(uint32_t*)&hp1;
        }
        lt0 += __shfl_xor_sync(0xffffffffu, lt0, 1);
        lt0 += __shfl_xor_sync(0xffffffffu, lt0, 2);
        lt1 += __shfl_xor_sync(0xffffffffu, lt1, 1);
        lt1 += __shfl_xor_sync(0xffffffffu, lt1, 2);
        if ((lane & 3) == 0) { bs[r0 * 2 + wc] = lt0; bs[r1 * 2 + wc] = lt1; }

        float al0 = expf(m0 - mn0), al1 = expf(m1 - mn1);
        m0 = mn0; m1 = mn1;
#pragma unroll
        for (int nb = 0; nb < 8; nb++) {
            oacc[nb][0] *= al0; oacc[nb][1] *= al0;
            oacc[nb][2] *= al1; oacc[nb][3] *= al1;
        }
        __syncthreads();
        l0 = l0 * al0 + bs[r0 * 2] + bs[r0 * 2 + 1];
        l1 = l1 * al1 + bs[r1 * 2] + bs[r1 * 2 + 1];

        // ---- O_partial += P_band V_band (P straight from registers) ----
#pragma unroll
        for (int kb = 0; kb < 2; kb++) {
            uint32_t af[4] = { pr0[2 * kb], pr1[2 * kb], pr0[2 * kb + 1], pr1[2 * kb + 1] };
            const int krow = wc * 32 + kb * 16;
#pragma unroll
            for (int vt = 0; vt < 4; vt++) {
                uint32_t vh[4];
                ldsm_x4_t(vh, smem_u32(sVh + (krow + v_row) * ASTR + vt * 16 + v_col));
                mma16816(oacc[vt * 2],     af, vh[0], vh[1]);
                mma16816(oacc[vt * 2 + 1], af, vh[2], vh[3]);
            }
        }
    }

    // ---- cross-warp O combine + write ----
    __syncthreads();
    if (wc == 0) {
#pragma unroll
        for (int nb = 0; nb < 8; nb++) {
            *(float2*)(obuf + r0 * 66 + nb * 8 + lc) = make_float2(oacc[nb][0], oacc[nb][1]);
            *(float2*)(obuf + r1 * 66 + nb * 8 + lc) = make_float2(oacc[nb][2], oacc[nb][3]);
        }
    }
    __syncthreads();
    if (wc == 1) {
        float i0 = 1.f / l0, i1 = 1.f / l1;
        __half* Oh = P.Oh[mode];
#pragma unroll
        for (int nb = 0; nb < 8; nb++) {
            float2 p0 = *(const float2*)(obuf + r0 * 66 + nb * 8 + lc);
            float2 p1 = *(const float2*)(obuf + r1 * 66 + nb * 8 + lc);
            int c = h * HDIM + nb * 8 + lc;
            size_t o0 = (size_t)(b * S_LEN + qq0) * 512 + c;
            size_t o1 = (size_t)(b * S_LEN + qq1) * 512 + c;
            *(__half2*)(Oh + o0) = __halves2half2(
                __float2half((p0.x + oacc[nb][0]) * i0),
                __float2half((p0.y + oacc[nb][1]) * i0));
            *(__half2*)(Oh + o1) = __halves2half2(
                __float2half((p1.x + oacc[nb][2]) * i1),
                __float2half((p1.y + oacc[nb][3]) * i1));
        }
    }
}

// ===================== fused topk + gather ==================================
__global__ __launch_bounds__(256) void topk_gather(
    const float* __restrict__ imp, const float* __restrict__ x,
    int* __restrict__ tidx, __half* __restrict__ sh)
{
    int b = blockIdx.x;
    __shared__ float v[2048];
    __shared__ float wv[8];
    __shared__ int   wi[8];
    __shared__ int   sel[64];
    const int tid = threadIdx.x, lane = tid & 31, wid = tid >> 5;

    for (int i = tid; i < 2048; i += 256) v[i] = imp[b * 2048 + i];
    __syncthreads();

    for (int r = 0; r < 64; r++) {
        float bv = -INFINITY; int bi = 0x7fffffff;
        for (int i = tid; i < 2048; i += 256) {
            float xv = v[i];
            if (xv > bv) { bv = xv; bi = i; }   // ascending i: ties keep lower
        }
#pragma unroll
        for (int off = 16; off; off >>= 1) {
            float ov = __shfl_xor_sync(0xffffffffu, bv, off);
            int   oi = __shfl_xor_sync(0xffffffffu, bi, off);
            if (ov > bv || (ov == bv && oi < bi)) { bv = ov; bi = oi; }
        }
        if (!lane) { wv[wid] = bv; wi[wid] = bi; }
        __syncthreads();
        if (wid == 0) {
            float cv = (lane < 8) ? wv[lane] : -INFINITY;
            int   ci = (lane < 8) ? wi[lane] : 0x7fffffff;
#pragma unroll
            for (int off = 4; off; off >>= 1) {
                float ov = __shfl_xor_sync(0xffffffffu, cv, off);
                int   oi = __shfl_xor_sync(0xffffffffu, ci, off);
                if (ov > cv || (ov == cv && oi < ci)) { cv = ov; ci = oi; }
            }
            if (!lane) { sel[r] = ci; tidx[b * 64 + r] = ci; v[ci] = -INFINITY; }
        }
        __syncthreads();
    }

    // gather selected rows -> fp16 arena
    for (int r = 0; r < 64; r++) {
        int src = sel[r];
        for (int d = tid; d < 512; d += 256)
            sh[(size_t)(b * 64 + r) * 512 + d] =
                __float2half(x[(size_t)(b * S_LEN + src) * 512 + d]);
    }
}

__global__ void combine_kernel(const float* __restrict__ b0, const float* __restrict__ bC,
                               const float* __restrict__ bT, const float* __restrict__ gc,
                               const float* __restrict__ gt, float* __restrict__ out)
{
    int i = (blockIdx.x * 256 + threadIdx.x) * 4;
    float4 v0 = *(const float4*)(b0 + i);
    float4 vC = *(const float4*)(bC + i);
    float4 vT = *(const float4*)(bT + i);
    float4 c = *(const float4*)(gc + i);
    float4 t = *(const float4*)(gt + i);
    v0.x += c.x * vC.x + t.x * vT.x;
    v0.y += c.y * vC.y + t.y * vT.y;
    v0.z += c.z * vC.z + t.z * vT.z;
    v0.w += c.w * vC.w + t.w * vT.w;
    *(float4*)(out + i) = v0;
}

// ===================== launch ===============================================
extern "C" void kernel_launch(void* const* d_in, const int* in_sizes, int n_in,
                              void* d_out, int out_size)
{
    const float* x    = (const float*)d_in[0];
    const float* Wqkv = (const float*)d_in[1];  const float* bqkv = (const float*)d_in[2];
    const float* Wlo  = (const float*)d_in[3];  const float* blo  = (const float*)d_in[4];
    const float* Wcq  = (const float*)d_in[5];  const float* bcq  = (const float*)d_in[6];
    const float* Wck  = (const float*)d_in[7];  const float* bck  = (const float*)d_in[8];
    const float* Wcv  = (const float*)d_in[9];  const float* bcv  = (const float*)d_in[10];
    const float* Wco  = (const float*)d_in[11]; const float* bco  = (const float*)d_in[12];
    const float* Wgc  = (const float*)d_in[13]; const float* bgc  = (const float*)d_in[14];
    const float* Wimp = (const float*)d_in[15]; const float* bimp = (const float*)d_in[16];
    const float* Wtq  = (const float*)d_in[17]; const float* btq  = (const float*)d_in[18];
    const float* Wtk  = (const float*)d_in[19]; const float* btk  = (const float*)d_in[20];
    const float* Wtv  = (const float*)d_in[21]; const float* btv  = (const float*)d_in[22];
    const float* Wto  = (const float*)d_in[23]; const float* bto  = (const float*)d_in[24];
    const float* Wgt  = (const float*)d_in[25]; const float* bgt  = (const float*)d_in[26];
    float* out = (float*)d_out;

    float *obuf, *gatec, *gatet, *imp;
    int* tidx;
    __half *xh, *qkvh, *qkvl, *qch, *qth, *aLh, *aCh, *aTh;
    __half *ch, *sh, *kch, *kcl, *vch, *kth, *ktl, *vth, *wh;
    cudaGetSymbolAddress((void**)&obuf,  g_obuf);
    cudaGetSymbolAddress((void**)&gatec, g_gatec);
    cudaGetSymbolAddress((void**)&gatet, g_gatet);
    cudaGetSymbolAddress((void**)&imp,   g_imp);
    cudaGetSymbolAddress((void**)&tidx,  g_tidx);
    cudaGetSymbolAddress((void**)&xh,   g_xh);
    cudaGetSymbolAddress((void**)&qkvh, g_qkvh); cudaGetSymbolAddress((void**)&qkvl, g_qkvl);
    cudaGetSymbolAddress((void**)&qch,  g_qch);
    cudaGetSymbolAddress((void**)&qth,  g_qth);
    cudaGetSymbolAddress((void**)&aLh,  g_aLh);
    cudaGetSymbolAddress((void**)&aCh,  g_aCh);
    cudaGetSymbolAddress((void**)&aTh,  g_aTh);
    cudaGetSymbolAddress((void**)&ch,   g_ch);
    cudaGetSymbolAddress((void**)&sh,   g_sh);
    cudaGetSymbolAddress((void**)&kch,  g_kch);  cudaGetSymbolAddress((void**)&kcl,  g_kcl);
    cudaGetSymbolAddress((void**)&vch,  g_vch);
    cudaGetSymbolAddress((void**)&kth,  g_kth);  cudaGetSymbolAddress((void**)&ktl,  g_ktl);
    cudaGetSymbolAddress((void**)&vth,  g_vth);
    cudaGetSymbolAddress((void**)&wh,   g_wh);

    const int ATTN_SMEM = 4 * 64 * ASTR * 2 + 64 * 4 + 2 * 128 * 4; // 38144
    cudaFuncSetAttribute(attn_mma, cudaFuncAttributeMaxDynamicSharedMemorySize, ATTN_SMEM);
    const int GEMM_SMEM = 2 * 2 * ARR * 2;   // 40960
    cudaFuncSetAttribute(mma_gemm, cudaFuncAttributeMaxDynamicSharedMemorySize, GEMM_SMEM);

    const int O_QKV = 0,    O_LO = 1536, O_CQ = 2048, O_CK = 2560, O_CV = 3072,
              O_CO = 3584,  O_GC = 4096, O_TQ = 4608, O_TK = 5120, O_TV = 5632,
              O_TO = 6144,  O_GT = 6656;
    #define WH(o) (wh + (size_t)(o) * 512)

    {
        WBatch wb;
        wb.s[0]  = {Wqkv, WH(O_QKV), 1536, 768};
        wb.s[1]  = {Wlo,  WH(O_LO),  512, 256};
        wb.s[2]  = {Wcq,  WH(O_CQ),  512, 256};
        wb.s[3]  = {Wck,  WH(O_CK),  512, 256};
        wb.s[4]  = {Wcv,  WH(O_CV),  512, 256};
        wb.s[5]  = {Wco,  WH(O_CO),  512, 256};
        wb.s[6]  = {Wgc,  WH(O_GC),  512, 256};
        wb.s[7]  = {Wtq,  WH(O_TQ),  512, 256};
        wb.s[8]  = {Wtk,  WH(O_TK),  512, 256};
        wb.s[9]  = {Wtv,  WH(O_TV),  512, 256};
        wb.s[10] = {Wto,  WH(O_TO),  512, 256};
        wb.s[11] = {Wgt,  WH(O_GT),  512, 256};
        wb.n = 12;
        conv_w<<<768 + 11 * 256, 256>>>(wb);
    }
    xprep_kernel<<<512, 512>>>(x, Wimp, bimp, xh, ch, imp);
    topk_gather<<<2, 256>>>(imp, x, tidx, sh);

    {
        MBatch mb;
        mb.s[0] = {xh, WH(O_QKV), bqkv, nullptr, qkvh, qkvl, 12, 32, 4, 1536};
        mb.s[1] = {xh, WH(O_CQ),  bcq,  nullptr, qch,  nullptr, 4, 32, 3, 512};
        mb.s[2] = {xh, WH(O_GC),  bgc,  gatec,  nullptr, nullptr, 4, 32, 1, 512};
        mb.s[3] = {xh, WH(O_TQ),  btq,  nullptr, qth,  nullptr, 4, 32, 3, 512};
        mb.s[4] = {xh, WH(O_GT),  bgt,  gatet,  nullptr, nullptr, 4, 32, 1, 512};
        mb.s[5] = {ch, WH(O_CK),  bck,  nullptr, kch,  kcl, 4, 3, 2, 512};
        mb.s[6] = {ch, WH(O_CV),  bcv,  nullptr, vch,  nullptr, 4, 3, 5, 512};
        mb.s[7] = {sh, WH(O_TK),  btk,  nullptr, kth,  ktl, 4, 1, 2, 512};
        mb.s[8] = {sh, WH(O_TV),  btv,  nullptr, vth,  nullptr, 4, 1, 5, 512};
        mb.n = 9;
        mma_gemm<<<928, 256, GEMM_SMEM>>>(mb);
    }

    {
        AttnParams P;
        P.Qh[0] = qkvh;
        P.Kh[0] = qkvh + 512;  P.Kl[0] = qkvl + 512;
        P.Vh[0] = qkvh + 1024;
        P.Oh[0] = aLh; P.qs[0] = 1536; P.ks[0] = 1536; P.nk[0] = 2048;
        P.Qh[1] = qch; P.Kh[1] = kch; P.Kl[1] = kcl; P.Vh[1] = vch;
        P.Oh[1] = aCh; P.qs[1] = 512; P.ks[1] = 512; P.nk[1] = 192;
        P.Qh[2] = qth; P.Kh[2] = kth; P.Kl[2] = ktl; P.Vh[2] = vth;
        P.Oh[2] = aTh; P.qs[2] = 512; P.ks[2] = 512; P.nk[2] = 64;
        P.tidx = tidx;
        attn_mma<<<dim3(32, 8, 6), 256, ATTN_SMEM>>>(P);
    }

    float* buf0 = obuf;
    float* bufC = obuf + (size_t)NTOK * 512;
    float* bufT = obuf + (size_t)NTOK * 1024;
    {
        MBatch mb;
        mb.s[0] = {aLh, WH(O_LO), blo, buf0, nullptr, nullptr, 4, 32, 0, 512};
        mb.s[1] = {aCh, WH(O_CO), bco, bufC, nullptr, nullptr, 4, 32, 0, 512};
        mb.s[2] = {aTh, WH(O_TO), bto, bufT, nullptr, nullptr, 4, 32, 0, 512};
        mb.n = 3;
        mma_gemm<<<384, 256, GEMM_SMEM>>>(mb);
    }
    combine_kernel<<<NTOK * 512 / 1024, 256>>>(buf0, bufC, bufT, gatec, gatet, out);
}